// round 1
// baseline (speedup 1.0000x reference)
#include <cuda_runtime.h>

// ---------------------------------------------------------------------------
// SelfAttention_2826088481408 — GB300 sm_103a
// B=16, H=W=64 (hw=4096), C=256, d=32, dv=128
// out = x + softmax(g f^T) h Wo + bo   with f=xWf+bf, g=xWg+bg, h=xWh+bh
//
// 3 kernels:
//   1) proj_kernel : fused [f|g|h] projection GEMM  (M=65536,K=256,N=192)
//   2) attn_kernel : flash-attention, 1 CTA per (batch, 64-query tile)
//   3) out_kernel  : x + o@Wo + bo                  (M=65536,K=128,N=256)
// All math in fp32 using packed fma.rn.f32x2 (2x FFMA throughput on sm_103a).
// ---------------------------------------------------------------------------

#define BATCH 16
#define HW    4096
#define CH    256
#define DK    32
#define DV    128
#define MTOT  (BATCH * HW)   // 65536
#define NPROJ 192            // 32 f + 32 g + 128 h

// scratch (allocation-free: device globals)
__device__ float g_fgh[(size_t)MTOT * NPROJ];  // [m, 0:32)=f, [32:64)=g, [64:192)=h
__device__ float g_o[(size_t)MTOT * DV];

// ---- packed f32x2 helpers --------------------------------------------------
__device__ __forceinline__ unsigned long long pk2(float lo, float hi) {
    unsigned long long r;
    asm("mov.b64 %0, {%1, %2};" : "=l"(r) : "f"(lo), "f"(hi));
    return r;
}
__device__ __forceinline__ void upk2(unsigned long long v, float& lo, float& hi) {
    asm("mov.b64 {%0, %1}, %2;" : "=f"(lo), "=f"(hi) : "l"(v));
}
__device__ __forceinline__ unsigned long long fma2(unsigned long long a,
                                                   unsigned long long b,
                                                   unsigned long long c) {
    unsigned long long d;
    asm("fma.rn.f32x2 %0, %1, %2, %3;" : "=l"(d) : "l"(a), "l"(b), "l"(c));
    return d;
}
__device__ __forceinline__ unsigned long long mul2(unsigned long long a,
                                                   unsigned long long b) {
    unsigned long long d;
    asm("mul.rn.f32x2 %0, %1, %2;" : "=l"(d) : "l"(a), "l"(b));
    return d;
}

// ---------------------------------------------------------------------------
// Kernel 1: fused projection GEMM. Block = 64x64 tile, 256 threads, 4x4 micro.
// Columns 0..31 -> Wf, 32..63 -> Wg, 64..191 -> Wh.
// ---------------------------------------------------------------------------
__global__ __launch_bounds__(256) void proj_kernel(
    const float* __restrict__ x,
    const float* __restrict__ Wf, const float* __restrict__ bf,
    const float* __restrict__ Wg, const float* __restrict__ bg,
    const float* __restrict__ Wh, const float* __restrict__ bh)
{
    __shared__ float As[16][64];   // As[k][row]
    __shared__ float Bs[16][64];   // Bs[k][col]

    const int bm = blockIdx.x * 64;
    const int bn = blockIdx.y * 64;   // 0, 64, 128
    const int tid = threadIdx.x;
    const int tx = tid & 15;          // col group
    const int ty = tid >> 4;          // row group

    unsigned long long acc[4][2];
    #pragma unroll
    for (int i = 0; i < 4; i++) { acc[i][0] = 0ull; acc[i][1] = 0ull; }

    for (int k0 = 0; k0 < CH; k0 += 16) {
        // A tile: 64 rows x 16 k, one float4 per thread
        {
            int r = tid >> 2, c4 = tid & 3;
            float4 v = *(const float4*)&x[(size_t)(bm + r) * CH + k0 + c4 * 4];
            As[c4 * 4 + 0][r] = v.x; As[c4 * 4 + 1][r] = v.y;
            As[c4 * 4 + 2][r] = v.z; As[c4 * 4 + 3][r] = v.w;
        }
        // B tile: select source weight matrix per global column
        #pragma unroll
        for (int i = tid; i < 16 * 64; i += 256) {
            int c = i >> 6, n = i & 63;
            int gn = bn + n, k = k0 + c;
            float w;
            if (gn < 32)      w = Wf[k * 32 + gn];
            else if (gn < 64) w = Wg[k * 32 + gn - 32];
            else              w = Wh[k * 128 + gn - 64];
            Bs[c][n] = w;
        }
        __syncthreads();
        #pragma unroll
        for (int c = 0; c < 16; c++) {
            float4 a4 = *(const float4*)&As[c][ty * 4];
            ulonglong2 b2 = *(const ulonglong2*)&Bs[c][tx * 4];
            unsigned long long a0 = pk2(a4.x, a4.x);
            unsigned long long a1 = pk2(a4.y, a4.y);
            unsigned long long a2 = pk2(a4.z, a4.z);
            unsigned long long a3 = pk2(a4.w, a4.w);
            acc[0][0] = fma2(a0, b2.x, acc[0][0]); acc[0][1] = fma2(a0, b2.y, acc[0][1]);
            acc[1][0] = fma2(a1, b2.x, acc[1][0]); acc[1][1] = fma2(a1, b2.y, acc[1][1]);
            acc[2][0] = fma2(a2, b2.x, acc[2][0]); acc[2][1] = fma2(a2, b2.y, acc[2][1]);
            acc[3][0] = fma2(a3, b2.x, acc[3][0]); acc[3][1] = fma2(a3, b2.y, acc[3][1]);
        }
        __syncthreads();
    }

    // epilogue: + bias, store to g_fgh
    const int n0 = bn + tx * 4;
    float bias[4];
    #pragma unroll
    for (int j = 0; j < 4; j++) {
        int gn = n0 + j;
        if (gn < 32)      bias[j] = bf[gn];
        else if (gn < 64) bias[j] = bg[gn - 32];
        else              bias[j] = bh[gn - 64];
    }
    #pragma unroll
    for (int i = 0; i < 4; i++) {
        float o0, o1, o2, o3;
        upk2(acc[i][0], o0, o1);
        upk2(acc[i][1], o2, o3);
        float4 v = make_float4(o0 + bias[0], o1 + bias[1], o2 + bias[2], o3 + bias[3]);
        *(float4*)&g_fgh[(size_t)(bm + ty * 4 + i) * NPROJ + n0] = v;
    }
}

// ---------------------------------------------------------------------------
// Kernel 2: flash attention. 1 CTA = (batch b, 64 queries). 256 threads.
// Thread t: q = t/4 (fixed), sub = t%4 is key-group (S phase) / dv-group (PV).
// Online softmax state (m, l) replicated across the 4 threads of a quad via
// warp shuffles. f/h/P staged in dynamic smem; g row and O accum in registers.
// ---------------------------------------------------------------------------
__global__ __launch_bounds__(256, 2) void attn_kernel()
{
    extern __shared__ float smem[];
    float* sf = smem;                 // [64][32]   8 KB
    float* sh = smem + 64 * 32;       // [64][128] 32 KB
    float* sP = sh + 64 * 128;        // [64][65]  16.25 KB (pad kills bank conflicts)

    const int tid = threadIdx.x;
    const int b   = blockIdx.y;
    const int q0  = blockIdx.x * 64;
    const int q   = tid >> 2;
    const int sub = tid & 3;
    const size_t mrow = (size_t)b * HW + q0 + q;
    const size_t bbase = (size_t)b * HW;

    // g row (query) packed into 16 f32x2 pairs (replicated x4 per quad)
    unsigned long long g2[16];
    {
        const ulonglong2* gp = (const ulonglong2*)&g_fgh[mrow * NPROJ + 32];
        #pragma unroll
        for (int jj = 0; jj < 8; jj++) {
            ulonglong2 t = gp[jj];
            g2[2 * jj] = t.x; g2[2 * jj + 1] = t.y;
        }
    }

    unsigned long long acc[16];       // O accum: 32 floats for dv[sub*32 .. +31]
    #pragma unroll
    for (int j = 0; j < 16; j++) acc[j] = 0ull;
    float m_i = -1e30f, l_i = 0.0f;

    for (int k0 = 0; k0 < HW; k0 += 64) {
        __syncthreads();  // previous-iter consumers of sf/sh/sP done

        // stage f tile [64][32] and h tile [64][128]
        #pragma unroll
        for (int i = tid; i < 512; i += 256) {
            int r = i >> 3, c = i & 7;
            ((float4*)sf)[i] = *(const float4*)&g_fgh[(bbase + k0 + r) * NPROJ + c * 4];
        }
        #pragma unroll
        for (int i = tid; i < 2048; i += 256) {
            int r = i >> 5, c = i & 31;
            ((float4*)sh)[i] = *(const float4*)&g_fgh[(bbase + k0 + r) * NPROJ + 64 + c * 4];
        }
        __syncthreads();

        // ---- S = g . f^T for this thread's 16 keys ----
        float sreg[16];
        float mtile = -1e30f;
        #pragma unroll
        for (int kk = 0; kk < 16; kk++) {
            int k = sub * 16 + kk;
            const ulonglong2* fr = (const ulonglong2*)&sf[k * 32];
            unsigned long long sa = 0ull, sb = 0ull;
            #pragma unroll
            for (int jj = 0; jj < 8; jj++) {
                ulonglong2 fv = fr[jj];
                sa = fma2(g2[2 * jj],     fv.x, sa);
                sb = fma2(g2[2 * jj + 1], fv.y, sb);
            }
            float a0, a1, c0, c1;
            upk2(sa, a0, a1); upk2(sb, c0, c1);
            float s = (a0 + a1) + (c0 + c1);
            sreg[kk] = s;
            mtile = fmaxf(mtile, s);
        }
        // quad max -> all 4 lanes of the quad agree
        mtile = fmaxf(mtile, __shfl_xor_sync(0xffffffffu, mtile, 1));
        mtile = fmaxf(mtile, __shfl_xor_sync(0xffffffffu, mtile, 2));
        float m_new = fmaxf(m_i, mtile);
        float corr  = __expf(m_i - m_new);

        float psum = 0.0f;
        #pragma unroll
        for (int kk = 0; kk < 16; kk++) {
            float p = __expf(sreg[kk] - m_new);
            psum += p;
            sP[q * 65 + sub * 16 + kk] = p;
        }
        psum += __shfl_xor_sync(0xffffffffu, psum, 1);
        psum += __shfl_xor_sync(0xffffffffu, psum, 2);
        l_i = l_i * corr + psum;
        m_i = m_new;

        unsigned long long cc = pk2(corr, corr);
        #pragma unroll
        for (int j = 0; j < 16; j++) acc[j] = mul2(acc[j], cc);
        __syncthreads();  // sP ready

        // ---- O += P @ h  (this thread: 32 dv channels) ----
        #pragma unroll 4
        for (int k = 0; k < 64; k++) {
            float p = sP[q * 65 + k];
            unsigned long long pp = pk2(p, p);
            const ulonglong2* hr = (const ulonglong2*)(sh + k * 128 + sub * 32);
            #pragma unroll
            for (int jj = 0; jj < 8; jj++) {
                ulonglong2 hv = hr[jj];
                acc[2 * jj]     = fma2(pp, hv.x, acc[2 * jj]);
                acc[2 * jj + 1] = fma2(pp, hv.y, acc[2 * jj + 1]);
            }
        }
    }

    // finalize: O /= l, write o
    float rl = 1.0f / l_i;
    unsigned long long rr = pk2(rl, rl);
    float* orow = &g_o[mrow * DV + sub * 32];
    #pragma unroll
    for (int j = 0; j < 16; j++) {
        unsigned long long v = mul2(acc[j], rr);
        *(unsigned long long*)&orow[2 * j] = v;
    }
}

// ---------------------------------------------------------------------------
// Kernel 3: out = x + o @ Wo + bo.  M=65536, K=128, N=256. Same GEMM scheme.
// ---------------------------------------------------------------------------
__global__ __launch_bounds__(256) void out_kernel(
    const float* __restrict__ x,
    const float* __restrict__ Wo,
    const float* __restrict__ bo,
    float* __restrict__ out)
{
    __shared__ float As[16][64];
    __shared__ float Bs[16][64];

    const int bm = blockIdx.x * 64;
    const int bn = blockIdx.y * 64;
    const int tid = threadIdx.x;
    const int tx = tid & 15;
    const int ty = tid >> 4;

    unsigned long long acc[4][2];
    #pragma unroll
    for (int i = 0; i < 4; i++) { acc[i][0] = 0ull; acc[i][1] = 0ull; }

    for (int k0 = 0; k0 < DV; k0 += 16) {
        {
            int r = tid >> 2, c4 = tid & 3;
            float4 v = *(const float4*)&g_o[(size_t)(bm + r) * DV + k0 + c4 * 4];
            As[c4 * 4 + 0][r] = v.x; As[c4 * 4 + 1][r] = v.y;
            As[c4 * 4 + 2][r] = v.z; As[c4 * 4 + 3][r] = v.w;
        }
        #pragma unroll
        for (int i = tid; i < 16 * 64; i += 256) {
            int c = i >> 6, n = i & 63;
            Bs[c][n] = Wo[(size_t)(k0 + c) * CH + bn + n];
        }
        __syncthreads();
        #pragma unroll
        for (int c = 0; c < 16; c++) {
            float4 a4 = *(const float4*)&As[c][ty * 4];
            ulonglong2 b2 = *(const ulonglong2*)&Bs[c][tx * 4];
            unsigned long long a0 = pk2(a4.x, a4.x);
            unsigned long long a1 = pk2(a4.y, a4.y);
            unsigned long long a2 = pk2(a4.z, a4.z);
            unsigned long long a3 = pk2(a4.w, a4.w);
            acc[0][0] = fma2(a0, b2.x, acc[0][0]); acc[0][1] = fma2(a0, b2.y, acc[0][1]);
            acc[1][0] = fma2(a1, b2.x, acc[1][0]); acc[1][1] = fma2(a1, b2.y, acc[1][1]);
            acc[2][0] = fma2(a2, b2.x, acc[2][0]); acc[2][1] = fma2(a2, b2.y, acc[2][1]);
            acc[3][0] = fma2(a3, b2.x, acc[3][0]); acc[3][1] = fma2(a3, b2.y, acc[3][1]);
        }
        __syncthreads();
    }

    const int n0 = bn + tx * 4;
    float4 bias = *(const float4*)&bo[n0];
    #pragma unroll
    for (int i = 0; i < 4; i++) {
        size_t row = (size_t)(bm + ty * 4 + i);
        float4 xv = *(const float4*)&x[row * CH + n0];
        float o0, o1, o2, o3;
        upk2(acc[i][0], o0, o1);
        upk2(acc[i][1], o2, o3);
        float4 v = make_float4(xv.x + o0 + bias.x, xv.y + o1 + bias.y,
                               xv.z + o2 + bias.z, xv.w + o3 + bias.w);
        *(float4*)&out[row * CH + n0] = v;
    }
}

// ---------------------------------------------------------------------------
extern "C" void kernel_launch(void* const* d_in, const int* in_sizes, int n_in,
                              void* d_out, int out_size)
{
    const float* x  = (const float*)d_in[0];
    const float* Wf = (const float*)d_in[1];
    const float* bf = (const float*)d_in[2];
    const float* Wg = (const float*)d_in[3];
    const float* bg = (const float*)d_in[4];
    const float* Wh = (const float*)d_in[5];
    const float* bh = (const float*)d_in[6];
    const float* Wo = (const float*)d_in[7];
    const float* bo = (const float*)d_in[8];
    float* out = (float*)d_out;

    // 1) projections -> g_fgh
    proj_kernel<<<dim3(MTOT / 64, 3), 256>>>(x, Wf, bf, Wg, bg, Wh, bh);

    // 2) flash attention -> g_o
    const int attn_smem = (64 * 32 + 64 * 128 + 64 * 65) * (int)sizeof(float); // 57600 B
    cudaFuncSetAttribute(attn_kernel, cudaFuncAttributeMaxDynamicSharedMemorySize,
                         attn_smem);
    attn_kernel<<<dim3(HW / 64, BATCH), 256, attn_smem>>>();

    // 3) output projection + residual
    out_kernel<<<dim3(MTOT / 64, 4), 256>>>(x, Wo, bo, out);
}

// round 4
// speedup vs baseline: 16.2789x; 16.2789x over previous
#include <cuda_runtime.h>
#include <cuda_fp16.h>
#include <cstdint>

// ---------------------------------------------------------------------------
// SelfAttention_2826088481408 — GB300 sm_103a (base sm_103 PTX target)
// B=16, hw=4096, C=256, d=32, dv=128
// R4: mma.sync fp16 flash attention with ONLINE softmax (overflow-proof),
//     3-pass hi/lo QK, register-resident P, fp16 PV.
// ---------------------------------------------------------------------------

#define BATCH 16
#define HW    4096
#define CH    256
#define DK    32
#define DV    128
#define MTOT  (BATCH * HW)
#define NPROJ 192

__device__ float  g_fgh[(size_t)MTOT * NPROJ];     // [m: f(32)|g(32)|h(128)]
__device__ __half g_ht_h[(size_t)BATCH * DV * HW]; // h^T fp16 [b][dv][key]
__device__ float  g_o[(size_t)MTOT * DV];

// ---- packed f32x2 helpers (SIMT GEMMs) ------------------------------------
__device__ __forceinline__ unsigned long long pk2(float lo, float hi) {
    unsigned long long r;
    asm("mov.b64 %0, {%1, %2};" : "=l"(r) : "f"(lo), "f"(hi));
    return r;
}
__device__ __forceinline__ void upk2(unsigned long long v, float& lo, float& hi) {
    asm("mov.b64 {%0, %1}, %2;" : "=f"(lo), "=f"(hi) : "l"(v));
}
__device__ __forceinline__ unsigned long long fma2(unsigned long long a,
                                                   unsigned long long b,
                                                   unsigned long long c) {
    unsigned long long d;
    asm("fma.rn.f32x2 %0, %1, %2, %3;" : "=l"(d) : "l"(a), "l"(b), "l"(c));
    return d;
}

// ---- mma.sync m16n8k16 f16 -------------------------------------------------
__device__ __forceinline__ void mma16816(float* c, const uint32_t* a,
                                         uint32_t b0, uint32_t b1) {
    asm volatile(
        "mma.sync.aligned.m16n8k16.row.col.f32.f16.f16.f32 "
        "{%0,%1,%2,%3}, {%4,%5,%6,%7}, {%8,%9}, {%0,%1,%2,%3};"
        : "+f"(c[0]), "+f"(c[1]), "+f"(c[2]), "+f"(c[3])
        : "r"(a[0]), "r"(a[1]), "r"(a[2]), "r"(a[3]), "r"(b0), "r"(b1));
}

// split float2 -> packed fp16 hi pair + fp16 lo (residual) pair
__device__ __forceinline__ void hilo2(float2 v, uint32_t& hi, uint32_t& lo) {
    __half hx = __float2half_rn(v.x), hy = __float2half_rn(v.y);
    float rx = v.x - __half2float(hx);
    float ry = v.y - __half2float(hy);
    __half2 h = __halves2half2(hx, hy);
    __half2 l = __floats2half2_rn(rx, ry);
    hi = *(uint32_t*)&h;
    lo = *(uint32_t*)&l;
}
__device__ __forceinline__ uint32_t packh2(float x, float y) {
    __half2 h = __floats2half2_rn(x, y);
    return *(uint32_t*)&h;
}

// ===========================================================================
// Kernel 1: fused projection GEMM (fp32). Writes f|g|h and h^T (fp16).
// ===========================================================================
__global__ __launch_bounds__(256) void proj_kernel(
    const float* __restrict__ x,
    const float* __restrict__ Wf, const float* __restrict__ bf,
    const float* __restrict__ Wg, const float* __restrict__ bg,
    const float* __restrict__ Wh, const float* __restrict__ bh)
{
    __shared__ float As[16][64];
    __shared__ float Bs[16][64];

    const int bm = blockIdx.x * 64;
    const int bn = blockIdx.y * 64;
    const int tid = threadIdx.x;
    const int tx = tid & 15;
    const int ty = tid >> 4;

    unsigned long long acc[4][2];
    #pragma unroll
    for (int i = 0; i < 4; i++) { acc[i][0] = 0ull; acc[i][1] = 0ull; }

    for (int k0 = 0; k0 < CH; k0 += 16) {
        {
            int r = tid >> 2, c4 = tid & 3;
            float4 v = *(const float4*)&x[(size_t)(bm + r) * CH + k0 + c4 * 4];
            As[c4 * 4 + 0][r] = v.x; As[c4 * 4 + 1][r] = v.y;
            As[c4 * 4 + 2][r] = v.z; As[c4 * 4 + 3][r] = v.w;
        }
        #pragma unroll
        for (int i = tid; i < 16 * 64; i += 256) {
            int c = i >> 6, n = i & 63;
            int gn = bn + n, k = k0 + c;
            float w;
            if (gn < 32)      w = Wf[k * 32 + gn];
            else if (gn < 64) w = Wg[k * 32 + gn - 32];
            else              w = Wh[k * 128 + gn - 64];
            Bs[c][n] = w;
        }
        __syncthreads();
        #pragma unroll
        for (int c = 0; c < 16; c++) {
            float4 a4 = *(const float4*)&As[c][ty * 4];
            ulonglong2 b2 = *(const ulonglong2*)&Bs[c][tx * 4];
            unsigned long long a0 = pk2(a4.x, a4.x);
            unsigned long long a1 = pk2(a4.y, a4.y);
            unsigned long long a2 = pk2(a4.z, a4.z);
            unsigned long long a3 = pk2(a4.w, a4.w);
            acc[0][0] = fma2(a0, b2.x, acc[0][0]); acc[0][1] = fma2(a0, b2.y, acc[0][1]);
            acc[1][0] = fma2(a1, b2.x, acc[1][0]); acc[1][1] = fma2(a1, b2.y, acc[1][1]);
            acc[2][0] = fma2(a2, b2.x, acc[2][0]); acc[2][1] = fma2(a2, b2.y, acc[2][1]);
            acc[3][0] = fma2(a3, b2.x, acc[3][0]); acc[3][1] = fma2(a3, b2.y, acc[3][1]);
        }
        __syncthreads();
    }

    const int n0 = bn + tx * 4;
    float bias[4];
    #pragma unroll
    for (int j = 0; j < 4; j++) {
        int gn = n0 + j;
        if (gn < 32)      bias[j] = bf[gn];
        else if (gn < 64) bias[j] = bg[gn - 32];
        else              bias[j] = bh[gn - 64];
    }
    #pragma unroll
    for (int i = 0; i < 4; i++) {
        int m = bm + ty * 4 + i;
        float o0, o1, o2, o3;
        upk2(acc[i][0], o0, o1);
        upk2(acc[i][1], o2, o3);
        float4 v = make_float4(o0 + bias[0], o1 + bias[1], o2 + bias[2], o3 + bias[3]);
        *(float4*)&g_fgh[(size_t)m * NPROJ + n0] = v;
        if (n0 >= 64) {   // h region: write transposed fp16 [b][dv][pix]
            int b = m >> 12, pix = m & 4095;
            size_t tb = ((size_t)b * DV + (n0 - 64)) * HW + pix;
            g_ht_h[tb]          = __float2half_rn(v.x);
            g_ht_h[tb + HW]     = __float2half_rn(v.y);
            g_ht_h[tb + 2 * HW] = __float2half_rn(v.z);
            g_ht_h[tb + 3 * HW] = __float2half_rn(v.w);
        }
    }
}

// ===========================================================================
// Kernel 2: mma.sync flash attention, ONLINE softmax.
// CTA = (batch b, 64-query tile), 128 threads / 4 warps; warp owns 16 rows.
// Per key tile (64 keys):
//   S(16x64) = 3-pass fp16 hi/lo mma;
//   row max via register+shfl; p = exp(s - m_new) in (0,1];
//   O registers rescaled by corr = exp(m_old - m_new) in [0,1];
//   P packed to fp16 A-fragments IN REGISTERS; O(16x128) += P @ Ht (fp16).
// Nothing can overflow: p<=1, corr<=1, l<=4096.
// ===========================================================================
__global__ __launch_bounds__(128) void attn_kernel()
{
    // F hi/lo: [nb=8][kb=2][lane=32][2reg]; Ht: [nb=16][ks=4][lane=32][2reg]
    __shared__ uint32_t sFhi[8 * 2 * 64];
    __shared__ uint32_t sFlo[8 * 2 * 64];
    __shared__ uint32_t sHt[16 * 4 * 64];

    const int tid = threadIdx.x;
    const int w = tid >> 5, lane = tid & 31;
    const int gq = lane >> 2, t = lane & 3;
    const int b = blockIdx.y, q0 = blockIdx.x * 64;
    const size_t bbase = (size_t)b * HW;
    const int qr = q0 + w * 16;           // warp's first query row

    // ---- load G A-fragments once (rows qr+gq, qr+gq+8; d-blocks kb=0,1) ----
    uint32_t Ahi[2][4], Alo[2][4];
    #pragma unroll
    for (int kb = 0; kb < 2; kb++) {
        const float* r0 = &g_fgh[(bbase + qr + gq) * NPROJ + 32 + kb * 16];
        const float* r1 = &g_fgh[(bbase + qr + gq + 8) * NPROJ + 32 + kb * 16];
        float2 v;
        v = *(const float2*)&r0[2 * t];     hilo2(v, Ahi[kb][0], Alo[kb][0]);
        v = *(const float2*)&r1[2 * t];     hilo2(v, Ahi[kb][1], Alo[kb][1]);
        v = *(const float2*)&r0[2 * t + 8]; hilo2(v, Ahi[kb][2], Alo[kb][2]);
        v = *(const float2*)&r1[2 * t + 8]; hilo2(v, Ahi[kb][3], Alo[kb][3]);
    }

    float O[16][4];
    #pragma unroll
    for (int i = 0; i < 16; i++)
        #pragma unroll
        for (int j = 0; j < 4; j++) O[i][j] = 0.0f;
    float m0 = -1e30f, m1 = -1e30f, l0 = 0.0f, l1 = 0.0f;

    for (int kt = 0; kt < 64; ++kt) {
        const int k0 = kt * 64;
        __syncthreads();   // prior reads of smem done before overwrite

        // ---- stage F (hi/lo fp16, fragment-major) ----
        #pragma unroll
        for (int task = tid; task < 512; task += 128) {
            int tt = task & 3, kb = (task >> 2) & 1, n = task >> 3;
            const float2* frow = (const float2*)&g_fgh[(bbase + k0 + n) * NPROJ];
            float2 v0 = frow[kb * 8 + tt];
            float2 v1 = frow[kb * 8 + tt + 4];
            uint32_t h0, l0_, h1, l1_;
            hilo2(v0, h0, l0_);
            hilo2(v1, h1, l1_);
            int idx = ((n >> 3) * 2 + kb) * 64 + ((n & 7) * 4 + tt) * 2;
            *(uint2*)&sFhi[idx] = make_uint2(h0, h1);
            *(uint2*)&sFlo[idx] = make_uint2(l0_, l1_);
        }
        // ---- stage Ht (fp16 pairs, fragment-major) ----
        #pragma unroll
        for (int task = tid; task < 2048; task += 128) {
            int tt = task & 3, ks = (task >> 2) & 3, n = task >> 4;
            const uint32_t* hrow =
                (const uint32_t*)(g_ht_h + ((size_t)b * DV + n) * HW + k0);
            uint32_t b0 = hrow[ks * 8 + tt];
            uint32_t b1 = hrow[ks * 8 + tt + 4];
            int idx = ((n >> 3) * 4 + ks) * 64 + ((n & 7) * 4 + tt) * 2;
            *(uint2*)&sHt[idx] = make_uint2(b0, b1);
        }
        __syncthreads();

        // ---- S = G F^T (3-pass hi/lo) ----
        float S[8][4];
        float mt0 = -1e30f, mt1 = -1e30f;
        #pragma unroll
        for (int nb = 0; nb < 8; nb++) {
            float* c = S[nb];
            c[0] = c[1] = c[2] = c[3] = 0.0f;
            uint2 bh0 = *(const uint2*)&sFhi[(nb * 2 + 0) * 64 + lane * 2];
            uint2 bh1 = *(const uint2*)&sFhi[(nb * 2 + 1) * 64 + lane * 2];
            uint2 bl0 = *(const uint2*)&sFlo[(nb * 2 + 0) * 64 + lane * 2];
            uint2 bl1 = *(const uint2*)&sFlo[(nb * 2 + 1) * 64 + lane * 2];
            mma16816(c, Ahi[0], bh0.x, bh0.y);
            mma16816(c, Ahi[1], bh1.x, bh1.y);
            mma16816(c, Ahi[0], bl0.x, bl0.y);
            mma16816(c, Ahi[1], bl1.x, bl1.y);
            mma16816(c, Alo[0], bh0.x, bh0.y);
            mma16816(c, Alo[1], bh1.x, bh1.y);
            mt0 = fmaxf(mt0, fmaxf(c[0], c[1]));
            mt1 = fmaxf(mt1, fmaxf(c[2], c[3]));
        }
        // row max across the 4 lanes of each row group
        mt0 = fmaxf(mt0, __shfl_xor_sync(0xffffffffu, mt0, 1));
        mt0 = fmaxf(mt0, __shfl_xor_sync(0xffffffffu, mt0, 2));
        mt1 = fmaxf(mt1, __shfl_xor_sync(0xffffffffu, mt1, 1));
        mt1 = fmaxf(mt1, __shfl_xor_sync(0xffffffffu, mt1, 2));
        float mn0 = fmaxf(m0, mt0), mn1 = fmaxf(m1, mt1);
        float corr0 = __expf(m0 - mn0), corr1 = __expf(m1 - mn1);
        m0 = mn0; m1 = mn1;

        // ---- p = exp(s - m), pack P fragments, accumulate l ----
        uint32_t Pa[4][4];
        float ps0 = 0.0f, ps1 = 0.0f;
        #pragma unroll
        for (int nb = 0; nb < 8; nb++) {
            float p0 = __expf(S[nb][0] - mn0);
            float p1 = __expf(S[nb][1] - mn0);
            float p2 = __expf(S[nb][2] - mn1);
            float p3 = __expf(S[nb][3] - mn1);
            ps0 += p0 + p1;
            ps1 += p2 + p3;
            int j = nb >> 1, hi = (nb & 1) << 1;   // S nb -> PV A kblock/slot
            Pa[j][hi + 0] = packh2(p0, p1);
            Pa[j][hi + 1] = packh2(p2, p3);
        }
        l0 = l0 * corr0 + ps0;
        l1 = l1 * corr1 + ps1;

        // ---- rescale O, then O += P @ Ht ----
        #pragma unroll
        for (int nb = 0; nb < 16; nb++) {
            O[nb][0] *= corr0; O[nb][1] *= corr0;
            O[nb][2] *= corr1; O[nb][3] *= corr1;
        }
        #pragma unroll
        for (int nb = 0; nb < 16; nb++) {
            #pragma unroll
            for (int j = 0; j < 4; j++) {
                uint2 bb = *(const uint2*)&sHt[(nb * 4 + j) * 64 + lane * 2];
                mma16816(O[nb], Pa[j], bb.x, bb.y);
            }
        }
    }

    // ---- l reduce across the 4 lanes of each row group ----
    l0 += __shfl_xor_sync(0xffffffffu, l0, 1);
    l0 += __shfl_xor_sync(0xffffffffu, l0, 2);
    l1 += __shfl_xor_sync(0xffffffffu, l1, 1);
    l1 += __shfl_xor_sync(0xffffffffu, l1, 2);
    float rl0 = 1.0f / l0, rl1 = 1.0f / l1;

    // ---- write O/l ----
    float* out0 = &g_o[(bbase + qr + gq) * DV + 2 * t];
    float* out1 = &g_o[(bbase + qr + gq + 8) * DV + 2 * t];
    #pragma unroll
    for (int nb = 0; nb < 16; nb++) {
        *(float2*)&out0[nb * 8] = make_float2(O[nb][0] * rl0, O[nb][1] * rl0);
        *(float2*)&out1[nb * 8] = make_float2(O[nb][2] * rl1, O[nb][3] * rl1);
    }
}

// ===========================================================================
// Kernel 3: out = x + o @ Wo + bo (fp32 SIMT).
// ===========================================================================
__global__ __launch_bounds__(256) void out_kernel(
    const float* __restrict__ x,
    const float* __restrict__ Wo,
    const float* __restrict__ bo,
    float* __restrict__ out)
{
    __shared__ float As[16][64];
    __shared__ float Bs[16][64];

    const int bm = blockIdx.x * 64;
    const int bn = blockIdx.y * 64;
    const int tid = threadIdx.x;
    const int tx = tid & 15;
    const int ty = tid >> 4;

    unsigned long long acc[4][2];
    #pragma unroll
    for (int i = 0; i < 4; i++) { acc[i][0] = 0ull; acc[i][1] = 0ull; }

    for (int k0 = 0; k0 < DV; k0 += 16) {
        {
            int r = tid >> 2, c4 = tid & 3;
            float4 v = *(const float4*)&g_o[(size_t)(bm + r) * DV + k0 + c4 * 4];
            As[c4 * 4 + 0][r] = v.x; As[c4 * 4 + 1][r] = v.y;
            As[c4 * 4 + 2][r] = v.z; As[c4 * 4 + 3][r] = v.w;
        }
        #pragma unroll
        for (int i = tid; i < 16 * 64; i += 256) {
            int c = i >> 6, n = i & 63;
            Bs[c][n] = Wo[(size_t)(k0 + c) * CH + bn + n];
        }
        __syncthreads();
        #pragma unroll
        for (int c = 0; c < 16; c++) {
            float4 a4 = *(const float4*)&As[c][ty * 4];
            ulonglong2 b2 = *(const ulonglong2*)&Bs[c][tx * 4];
            unsigned long long a0 = pk2(a4.x, a4.x);
            unsigned long long a1 = pk2(a4.y, a4.y);
            unsigned long long a2 = pk2(a4.z, a4.z);
            unsigned long long a3 = pk2(a4.w, a4.w);
            acc[0][0] = fma2(a0, b2.x, acc[0][0]); acc[0][1] = fma2(a0, b2.y, acc[0][1]);
            acc[1][0] = fma2(a1, b2.x, acc[1][0]); acc[1][1] = fma2(a1, b2.y, acc[1][1]);
            acc[2][0] = fma2(a2, b2.x, acc[2][0]); acc[2][1] = fma2(a2, b2.y, acc[2][1]);
            acc[3][0] = fma2(a3, b2.x, acc[3][0]); acc[3][1] = fma2(a3, b2.y, acc[3][1]);
        }
        __syncthreads();
    }

    const int n0 = bn + tx * 4;
    float4 bias = *(const float4*)&bo[n0];
    #pragma unroll
    for (int i = 0; i < 4; i++) {
        size_t row = (size_t)(bm + ty * 4 + i);
        float4 xv = *(const float4*)&x[row * CH + n0];
        float o0, o1, o2, o3;
        upk2(acc[i][0], o0, o1);
        upk2(acc[i][1], o2, o3);
        float4 v = make_float4(xv.x + o0 + bias.x, xv.y + o1 + bias.y,
                               xv.z + o2 + bias.z, xv.w + o3 + bias.w);
        *(float4*)&out[row * CH + n0] = v;
    }
}

// ===========================================================================
extern "C" void kernel_launch(void* const* d_in, const int* in_sizes, int n_in,
                              void* d_out, int out_size)
{
    const float* x  = (const float*)d_in[0];
    const float* Wf = (const float*)d_in[1];
    const float* bf = (const float*)d_in[2];
    const float* Wg = (const float*)d_in[3];
    const float* bg = (const float*)d_in[4];
    const float* Wh = (const float*)d_in[5];
    const float* bh = (const float*)d_in[6];
    const float* Wo = (const float*)d_in[7];
    const float* bo = (const float*)d_in[8];
    float* out = (float*)d_out;

    proj_kernel<<<dim3(MTOT / 64, 3), 256>>>(x, Wf, bf, Wg, bg, Wh, bh);
    attn_kernel<<<dim3(HW / 64, BATCH), 128>>>();
    out_kernel<<<dim3(MTOT / 64, 4), 256>>>(x, Wo, bo, out);
}

// round 5
// speedup vs baseline: 20.8628x; 1.2816x over previous
#include <cuda_runtime.h>
#include <cuda_fp16.h>
#include <cstdint>

// ---------------------------------------------------------------------------
// SelfAttention_2826088481408 — GB300 sm_103a (base sm_103 PTX target)
// B=16, hw=4096, C=256, d=32, dv=128
// R5: all three stages on mma.sync fp16 hi/lo 3-pass tensor path.
//   proj_mma : f|g|h = x@W + b        (M=65536,K=256,N=192) + fp16 h^T write
//   attn     : flash attention (unchanged from passing R4)
//   out_mma  : out = x + o@Wo + bo    (M=65536,K=128,N=256)
// ---------------------------------------------------------------------------

#define BATCH 16
#define HW    4096
#define CH    256
#define DK    32
#define DV    128
#define MTOT  (BATCH * HW)
#define NPROJ 192

__device__ float  g_fgh[(size_t)MTOT * NPROJ];     // [m: f(32)|g(32)|h(128)]
__device__ __half g_ht_h[(size_t)BATCH * DV * HW]; // h^T fp16 [b][dv][key]
__device__ float  g_o[(size_t)MTOT * DV];

// ---- mma.sync m16n8k16 f16 -------------------------------------------------
__device__ __forceinline__ void mma16816(float* c, const uint32_t* a,
                                         uint32_t b0, uint32_t b1) {
    asm volatile(
        "mma.sync.aligned.m16n8k16.row.col.f32.f16.f16.f32 "
        "{%0,%1,%2,%3}, {%4,%5,%6,%7}, {%8,%9}, {%0,%1,%2,%3};"
        : "+f"(c[0]), "+f"(c[1]), "+f"(c[2]), "+f"(c[3])
        : "r"(a[0]), "r"(a[1]), "r"(a[2]), "r"(a[3]), "r"(b0), "r"(b1));
}

// split float2 -> packed fp16 hi pair + fp16 lo (residual) pair
__device__ __forceinline__ void hilo2(float2 v, uint32_t& hi, uint32_t& lo) {
    __half hx = __float2half_rn(v.x), hy = __float2half_rn(v.y);
    float rx = v.x - __half2float(hx);
    float ry = v.y - __half2float(hy);
    __half2 h = __halves2half2(hx, hy);
    __half2 l = __floats2half2_rn(rx, ry);
    hi = *(uint32_t*)&h;
    lo = *(uint32_t*)&l;
}
__device__ __forceinline__ uint32_t packh2(float x, float y) {
    __half2 h = __floats2half2_rn(x, y);
    return *(uint32_t*)&h;
}

// ===========================================================================
// Kernel 1: proj GEMM on tensor path. CTA = 128 rows x 64 cols, 8 warps.
// B (weights) staged fragment-major in smem, two 8-kblock phases (32KB).
// A (x) fragments loaded straight from gmem (coalesced float2), hi/lo split.
// ===========================================================================
__device__ __forceinline__ float wsel(
    const float* __restrict__ Wf, const float* __restrict__ Wg,
    const float* __restrict__ Wh, int k, int gn)
{
    if (gn < 32)  return Wf[k * 32 + gn];
    if (gn < 64)  return Wg[k * 32 + gn - 32];
    return Wh[k * 128 + gn - 64];
}
__device__ __forceinline__ float bsel(
    const float* __restrict__ bf, const float* __restrict__ bg,
    const float* __restrict__ bh, int gn)
{
    if (gn < 32)  return bf[gn];
    if (gn < 64)  return bg[gn - 32];
    return bh[gn - 64];
}

__global__ __launch_bounds__(256) void proj_mma(
    const float* __restrict__ x,
    const float* __restrict__ Wf, const float* __restrict__ bf,
    const float* __restrict__ Wg, const float* __restrict__ bg,
    const float* __restrict__ Wh, const float* __restrict__ bh)
{
    __shared__ uint32_t sBhi[8 * 8 * 64];   // [nb][kb][lane][2]
    __shared__ uint32_t sBlo[8 * 8 * 64];

    const int tid = threadIdx.x;
    const int w = tid >> 5, lane = tid & 31;
    const int gq = lane >> 2, t = lane & 3;
    const int bm = blockIdx.x * 128;
    const int bn = blockIdx.y * 64;

    const int m0 = bm + w * 16 + gq;
    const float* xr0 = &x[(size_t)m0 * CH];
    const float* xr1 = xr0 + 8 * CH;

    float c[8][4];
    #pragma unroll
    for (int nb = 0; nb < 8; nb++)
        #pragma unroll
        for (int j = 0; j < 4; j++) c[nb][j] = 0.0f;

    #pragma unroll
    for (int ph = 0; ph < 2; ph++) {
        __syncthreads();
        // stage W fragments for k-blocks [ph*8, ph*8+8)
        #pragma unroll
        for (int task = tid; task < 8 * 8 * 32; task += 256) {
            int ln = task & 31, kb = (task >> 5) & 7, nb = task >> 8;
            int g = ln >> 2, tt = ln & 3;
            int gn = bn + nb * 8 + g;
            int k = (ph * 8 + kb) * 16 + 2 * tt;
            float w0 = wsel(Wf, Wg, Wh, k,     gn);
            float w1 = wsel(Wf, Wg, Wh, k + 1, gn);
            float w2 = wsel(Wf, Wg, Wh, k + 8, gn);
            float w3 = wsel(Wf, Wg, Wh, k + 9, gn);
            uint32_t h0, l0, h1, l1;
            hilo2(make_float2(w0, w1), h0, l0);
            hilo2(make_float2(w2, w3), h1, l1);
            int idx = ((nb * 8 + kb) * 32 + ln) * 2;
            sBhi[idx] = h0; sBhi[idx + 1] = h1;
            sBlo[idx] = l0; sBlo[idx + 1] = l1;
        }
        __syncthreads();

        #pragma unroll
        for (int kb = 0; kb < 8; kb++) {
            const int kc = (ph * 8 + kb) * 16;
            uint32_t Ahi[4], Alo[4];
            float2 v;
            v = *(const float2*)&xr0[kc + 2 * t];     hilo2(v, Ahi[0], Alo[0]);
            v = *(const float2*)&xr1[kc + 2 * t];     hilo2(v, Ahi[1], Alo[1]);
            v = *(const float2*)&xr0[kc + 2 * t + 8]; hilo2(v, Ahi[2], Alo[2]);
            v = *(const float2*)&xr1[kc + 2 * t + 8]; hilo2(v, Ahi[3], Alo[3]);
            #pragma unroll
            for (int nb = 0; nb < 8; nb++) {
                uint2 bh2 = *(const uint2*)&sBhi[((nb * 8 + kb) * 32 + lane) * 2];
                uint2 bl2 = *(const uint2*)&sBlo[((nb * 8 + kb) * 32 + lane) * 2];
                mma16816(c[nb], Ahi, bh2.x, bh2.y);
                mma16816(c[nb], Ahi, bl2.x, bl2.y);
                mma16816(c[nb], Alo, bh2.x, bh2.y);
            }
        }
    }

    // epilogue: + bias, write g_fgh (fp32) and h^T (fp16)
    #pragma unroll
    for (int nb = 0; nb < 8; nb++) {
        int gn0 = bn + nb * 8 + 2 * t;
        float b0 = bsel(bf, bg, bh, gn0);
        float b1 = bsel(bf, bg, bh, gn0 + 1);
        float v00 = c[nb][0] + b0, v01 = c[nb][1] + b1;
        float v10 = c[nb][2] + b0, v11 = c[nb][3] + b1;
        *(float2*)&g_fgh[(size_t)m0 * NPROJ + gn0]       = make_float2(v00, v01);
        *(float2*)&g_fgh[(size_t)(m0 + 8) * NPROJ + gn0] = make_float2(v10, v11);
        if (gn0 >= 64) {
            int dv = gn0 - 64;
            int bb0 = m0 >> 12, pix0 = m0 & 4095;
            int m1 = m0 + 8, bb1 = m1 >> 12, pix1 = m1 & 4095;
            size_t t0 = ((size_t)bb0 * DV + dv) * HW + pix0;
            size_t t1 = ((size_t)bb1 * DV + dv) * HW + pix1;
            g_ht_h[t0]      = __float2half_rn(v00);
            g_ht_h[t0 + HW] = __float2half_rn(v01);
            g_ht_h[t1]      = __float2half_rn(v10);
            g_ht_h[t1 + HW] = __float2half_rn(v11);
        }
    }
}

// ===========================================================================
// Kernel 2: mma.sync flash attention, ONLINE softmax. (unchanged from R4)
// ===========================================================================
__global__ __launch_bounds__(128) void attn_kernel()
{
    __shared__ uint32_t sFhi[8 * 2 * 64];
    __shared__ uint32_t sFlo[8 * 2 * 64];
    __shared__ uint32_t sHt[16 * 4 * 64];

    const int tid = threadIdx.x;
    const int w = tid >> 5, lane = tid & 31;
    const int gq = lane >> 2, t = lane & 3;
    const int b = blockIdx.y, q0 = blockIdx.x * 64;
    const size_t bbase = (size_t)b * HW;
    const int qr = q0 + w * 16;

    uint32_t Ahi[2][4], Alo[2][4];
    #pragma unroll
    for (int kb = 0; kb < 2; kb++) {
        const float* r0 = &g_fgh[(bbase + qr + gq) * NPROJ + 32 + kb * 16];
        const float* r1 = &g_fgh[(bbase + qr + gq + 8) * NPROJ + 32 + kb * 16];
        float2 v;
        v = *(const float2*)&r0[2 * t];     hilo2(v, Ahi[kb][0], Alo[kb][0]);
        v = *(const float2*)&r1[2 * t];     hilo2(v, Ahi[kb][1], Alo[kb][1]);
        v = *(const float2*)&r0[2 * t + 8]; hilo2(v, Ahi[kb][2], Alo[kb][2]);
        v = *(const float2*)&r1[2 * t + 8]; hilo2(v, Ahi[kb][3], Alo[kb][3]);
    }

    float O[16][4];
    #pragma unroll
    for (int i = 0; i < 16; i++)
        #pragma unroll
        for (int j = 0; j < 4; j++) O[i][j] = 0.0f;
    float m0 = -1e30f, m1 = -1e30f, l0 = 0.0f, l1 = 0.0f;

    for (int kt = 0; kt < 64; ++kt) {
        const int k0 = kt * 64;
        __syncthreads();

        #pragma unroll
        for (int task = tid; task < 512; task += 128) {
            int tt = task & 3, kb = (task >> 2) & 1, n = task >> 3;
            const float2* frow = (const float2*)&g_fgh[(bbase + k0 + n) * NPROJ];
            float2 v0 = frow[kb * 8 + tt];
            float2 v1 = frow[kb * 8 + tt + 4];
            uint32_t h0, l0_, h1, l1_;
            hilo2(v0, h0, l0_);
            hilo2(v1, h1, l1_);
            int idx = ((n >> 3) * 2 + kb) * 64 + ((n & 7) * 4 + tt) * 2;
            *(uint2*)&sFhi[idx] = make_uint2(h0, h1);
            *(uint2*)&sFlo[idx] = make_uint2(l0_, l1_);
        }
        #pragma unroll
        for (int task = tid; task < 2048; task += 128) {
            int tt = task & 3, ks = (task >> 2) & 3, n = task >> 4;
            const uint32_t* hrow =
                (const uint32_t*)(g_ht_h + ((size_t)b * DV + n) * HW + k0);
            uint32_t b0 = hrow[ks * 8 + tt];
            uint32_t b1 = hrow[ks * 8 + tt + 4];
            int idx = ((n >> 3) * 4 + ks) * 64 + ((n & 7) * 4 + tt) * 2;
            *(uint2*)&sHt[idx] = make_uint2(b0, b1);
        }
        __syncthreads();

        float S[8][4];
        float mt0 = -1e30f, mt1 = -1e30f;
        #pragma unroll
        for (int nb = 0; nb < 8; nb++) {
            float* c = S[nb];
            c[0] = c[1] = c[2] = c[3] = 0.0f;
            uint2 bh0 = *(const uint2*)&sFhi[(nb * 2 + 0) * 64 + lane * 2];
            uint2 bh1 = *(const uint2*)&sFhi[(nb * 2 + 1) * 64 + lane * 2];
            uint2 bl0 = *(const uint2*)&sFlo[(nb * 2 + 0) * 64 + lane * 2];
            uint2 bl1 = *(const uint2*)&sFlo[(nb * 2 + 1) * 64 + lane * 2];
            mma16816(c, Ahi[0], bh0.x, bh0.y);
            mma16816(c, Ahi[1], bh1.x, bh1.y);
            mma16816(c, Ahi[0], bl0.x, bl0.y);
            mma16816(c, Ahi[1], bl1.x, bl1.y);
            mma16816(c, Alo[0], bh0.x, bh0.y);
            mma16816(c, Alo[1], bh1.x, bh1.y);
            mt0 = fmaxf(mt0, fmaxf(c[0], c[1]));
            mt1 = fmaxf(mt1, fmaxf(c[2], c[3]));
        }
        mt0 = fmaxf(mt0, __shfl_xor_sync(0xffffffffu, mt0, 1));
        mt0 = fmaxf(mt0, __shfl_xor_sync(0xffffffffu, mt0, 2));
        mt1 = fmaxf(mt1, __shfl_xor_sync(0xffffffffu, mt1, 1));
        mt1 = fmaxf(mt1, __shfl_xor_sync(0xffffffffu, mt1, 2));
        float mn0 = fmaxf(m0, mt0), mn1 = fmaxf(m1, mt1);
        float corr0 = __expf(m0 - mn0), corr1 = __expf(m1 - mn1);
        m0 = mn0; m1 = mn1;

        uint32_t Pa[4][4];
        float ps0 = 0.0f, ps1 = 0.0f;
        #pragma unroll
        for (int nb = 0; nb < 8; nb++) {
            float p0 = __expf(S[nb][0] - mn0);
            float p1 = __expf(S[nb][1] - mn0);
            float p2 = __expf(S[nb][2] - mn1);
            float p3 = __expf(S[nb][3] - mn1);
            ps0 += p0 + p1;
            ps1 += p2 + p3;
            int j = nb >> 1, hi = (nb & 1) << 1;
            Pa[j][hi + 0] = packh2(p0, p1);
            Pa[j][hi + 1] = packh2(p2, p3);
        }
        l0 = l0 * corr0 + ps0;
        l1 = l1 * corr1 + ps1;

        #pragma unroll
        for (int nb = 0; nb < 16; nb++) {
            O[nb][0] *= corr0; O[nb][1] *= corr0;
            O[nb][2] *= corr1; O[nb][3] *= corr1;
        }
        #pragma unroll
        for (int nb = 0; nb < 16; nb++) {
            #pragma unroll
            for (int j = 0; j < 4; j++) {
                uint2 bb = *(const uint2*)&sHt[(nb * 4 + j) * 64 + lane * 2];
                mma16816(O[nb], Pa[j], bb.x, bb.y);
            }
        }
    }

    l0 += __shfl_xor_sync(0xffffffffu, l0, 1);
    l0 += __shfl_xor_sync(0xffffffffu, l0, 2);
    l1 += __shfl_xor_sync(0xffffffffu, l1, 1);
    l1 += __shfl_xor_sync(0xffffffffu, l1, 2);
    float rl0 = 1.0f / l0, rl1 = 1.0f / l1;

    float* out0 = &g_o[(bbase + qr + gq) * DV + 2 * t];
    float* out1 = &g_o[(bbase + qr + gq + 8) * DV + 2 * t];
    #pragma unroll
    for (int nb = 0; nb < 16; nb++) {
        *(float2*)&out0[nb * 8] = make_float2(O[nb][0] * rl0, O[nb][1] * rl0);
        *(float2*)&out1[nb * 8] = make_float2(O[nb][2] * rl1, O[nb][3] * rl1);
    }
}

// ===========================================================================
// Kernel 3: out = x + o@Wo + bo on tensor path. CTA = 128 rows x 64 cols.
// ===========================================================================
__global__ __launch_bounds__(256) void out_mma(
    const float* __restrict__ x,
    const float* __restrict__ Wo,
    const float* __restrict__ bo,
    float* __restrict__ out)
{
    __shared__ uint32_t sBhi[8 * 8 * 64];
    __shared__ uint32_t sBlo[8 * 8 * 64];

    const int tid = threadIdx.x;
    const int w = tid >> 5, lane = tid & 31;
    const int gq = lane >> 2, t = lane & 3;
    const int bm = blockIdx.x * 128;
    const int bn = blockIdx.y * 64;

    // stage Wo fragments (K=128 -> 8 k-blocks, single phase)
    #pragma unroll
    for (int task = tid; task < 8 * 8 * 32; task += 256) {
        int ln = task & 31, kb = (task >> 5) & 7, nb = task >> 8;
        int g = ln >> 2, tt = ln & 3;
        int gn = bn + nb * 8 + g;
        int k = kb * 16 + 2 * tt;
        float w0 = Wo[(size_t)(k)     * CH + gn];
        float w1 = Wo[(size_t)(k + 1) * CH + gn];
        float w2 = Wo[(size_t)(k + 8) * CH + gn];
        float w3 = Wo[(size_t)(k + 9) * CH + gn];
        uint32_t h0, l0, h1, l1;
        hilo2(make_float2(w0, w1), h0, l0);
        hilo2(make_float2(w2, w3), h1, l1);
        int idx = ((nb * 8 + kb) * 32 + ln) * 2;
        sBhi[idx] = h0; sBhi[idx + 1] = h1;
        sBlo[idx] = l0; sBlo[idx + 1] = l1;
    }
    __syncthreads();

    const int m0 = bm + w * 16 + gq;
    const float* ar0 = &g_o[(size_t)m0 * DV];
    const float* ar1 = ar0 + 8 * DV;

    float c[8][4];
    #pragma unroll
    for (int nb = 0; nb < 8; nb++)
        #pragma unroll
        for (int j = 0; j < 4; j++) c[nb][j] = 0.0f;

    #pragma unroll
    for (int kb = 0; kb < 8; kb++) {
        const int kc = kb * 16;
        uint32_t Ahi[4], Alo[4];
        float2 v;
        v = *(const float2*)&ar0[kc + 2 * t];     hilo2(v, Ahi[0], Alo[0]);
        v = *(const float2*)&ar1[kc + 2 * t];     hilo2(v, Ahi[1], Alo[1]);
        v = *(const float2*)&ar0[kc + 2 * t + 8]; hilo2(v, Ahi[2], Alo[2]);
        v = *(const float2*)&ar1[kc + 2 * t + 8]; hilo2(v, Ahi[3], Alo[3]);
        #pragma unroll
        for (int nb = 0; nb < 8; nb++) {
            uint2 bh2 = *(const uint2*)&sBhi[((nb * 8 + kb) * 32 + lane) * 2];
            uint2 bl2 = *(const uint2*)&sBlo[((nb * 8 + kb) * 32 + lane) * 2];
            mma16816(c[nb], Ahi, bh2.x, bh2.y);
            mma16816(c[nb], Ahi, bl2.x, bl2.y);
            mma16816(c[nb], Alo, bh2.x, bh2.y);
        }
    }

    // epilogue: out = x + c + bo
    #pragma unroll
    for (int nb = 0; nb < 8; nb++) {
        int gn0 = bn + nb * 8 + 2 * t;
        float2 bb = *(const float2*)&bo[gn0];
        float2 x0 = *(const float2*)&x[(size_t)m0 * CH + gn0];
        float2 x1 = *(const float2*)&x[(size_t)(m0 + 8) * CH + gn0];
        *(float2*)&out[(size_t)m0 * CH + gn0] =
            make_float2(x0.x + c[nb][0] + bb.x, x0.y + c[nb][1] + bb.y);
        *(float2*)&out[(size_t)(m0 + 8) * CH + gn0] =
            make_float2(x1.x + c[nb][2] + bb.x, x1.y + c[nb][3] + bb.y);
    }
}

// ===========================================================================
extern "C" void kernel_launch(void* const* d_in, const int* in_sizes, int n_in,
                              void* d_out, int out_size)
{
    const float* x  = (const float*)d_in[0];
    const float* Wf = (const float*)d_in[1];
    const float* bf = (const float*)d_in[2];
    const float* Wg = (const float*)d_in[3];
    const float* bg = (const float*)d_in[4];
    const float* Wh = (const float*)d_in[5];
    const float* bh = (const float*)d_in[6];
    const float* Wo = (const float*)d_in[7];
    const float* bo = (const float*)d_in[8];
    float* out = (float*)d_out;

    proj_mma<<<dim3(MTOT / 128, 3), 256>>>(x, Wf, bf, Wg, bg, Wh, bh);
    attn_kernel<<<dim3(HW / 64, BATCH), 128>>>();
    out_mma<<<dim3(MTOT / 128, 4), 256>>>(x, Wo, bo, out);
}

// round 6
// speedup vs baseline: 26.2786x; 1.2596x over previous
#include <cuda_runtime.h>
#include <cuda_fp16.h>
#include <cstdint>

// ---------------------------------------------------------------------------
// SelfAttention_2826088481408 — GB300 sm_103a (base sm_103 PTX target)
// B=16, hw=4096, C=256, d=32, dv=128
// R6: attn -> 128q CTAs, proj-precomputed fp16 fragment streams,
//     cp.async double-buffered staging, conditional O rescale.
// ---------------------------------------------------------------------------

#define BATCH 16
#define HW    4096
#define CH    256
#define DK    32
#define DV    128
#define MTOT  (BATCH * HW)

// f,g as pair-interleaved fp16 hi/lo fragment streams: 16 uint per row.
// pos(ch): j=ch>>1; kb=j>>3; j8=j&7; pos = kb*8 + (j8&3)*2 + (j8>>2)
__device__ __align__(16) uint32_t g_f16hi[(size_t)MTOT * 16];
__device__ __align__(16) uint32_t g_f16lo[(size_t)MTOT * 16];
__device__ __align__(16) uint32_t g_g16hi[(size_t)MTOT * 16];
__device__ __align__(16) uint32_t g_g16lo[(size_t)MTOT * 16];
// h^T fp16 [b][dv][key-permuted]: within each 16-key group, half2 pairs are
// interleaved so B-fragment (b0,b1) is contiguous:
//   perm(pix) = (pix>>4)*16 + (((pix>>1)&3)*2 + ((pix>>1)>>2 & 1))*2 + (pix&1)
__device__ __align__(16) __half g_ht_h[(size_t)BATCH * DV * HW];
__device__ float g_o[(size_t)MTOT * DV];

// ---- mma.sync m16n8k16 f16 -------------------------------------------------
__device__ __forceinline__ void mma16816(float* c, const uint32_t* a,
                                         uint32_t b0, uint32_t b1) {
    asm volatile(
        "mma.sync.aligned.m16n8k16.row.col.f32.f16.f16.f32 "
        "{%0,%1,%2,%3}, {%4,%5,%6,%7}, {%8,%9}, {%0,%1,%2,%3};"
        : "+f"(c[0]), "+f"(c[1]), "+f"(c[2]), "+f"(c[3])
        : "r"(a[0]), "r"(a[1]), "r"(a[2]), "r"(a[3]), "r"(b0), "r"(b1));
}

__device__ __forceinline__ void hilo2(float2 v, uint32_t& hi, uint32_t& lo) {
    __half hx = __float2half_rn(v.x), hy = __float2half_rn(v.y);
    float rx = v.x - __half2float(hx);
    float ry = v.y - __half2float(hy);
    __half2 h = __halves2half2(hx, hy);
    __half2 l = __floats2half2_rn(rx, ry);
    hi = *(uint32_t*)&h;
    lo = *(uint32_t*)&l;
}
__device__ __forceinline__ uint32_t packh2(float x, float y) {
    __half2 h = __floats2half2_rn(x, y);
    return *(uint32_t*)&h;
}

__device__ __forceinline__ uint32_t smem_u32(const void* p) {
    uint32_t a;
    asm("{ .reg .u64 t; cvta.to.shared.u64 t, %1; cvt.u32.u64 %0, t; }"
        : "=r"(a) : "l"(p));
    return a;
}
__device__ __forceinline__ void cpa16(uint32_t s, const void* g) {
    asm volatile(
        "{ .reg .u64 gp; cvta.to.global.u64 gp, %1;"
        "  cp.async.cg.shared.global [%0], [gp], 16; }"
        :: "r"(s), "l"(g) : "memory");
}
#define CP_COMMIT() asm volatile("cp.async.commit_group;" ::: "memory")

// fragment-stream position for channel pair starting at even channel c
__device__ __forceinline__ int fpos(int c) {
    int j = c >> 1, kb = j >> 3, j8 = j & 7;
    return kb * 8 + (j8 & 3) * 2 + (j8 >> 2);
}
// permuted ht index for pixel
__device__ __forceinline__ int htperm(int pix) {
    int j = (pix >> 1) & 7;
    return (pix >> 4) * 16 + ((j & 3) * 2 + (j >> 2)) * 2 + (pix & 1);
}

// ===========================================================================
// Kernel 1: proj GEMM on tensor path. CTA = 128 rows x 64 cols, 8 warps.
// Epilogue writes f/g fragment streams (hi/lo) and permuted fp16 h^T.
// ===========================================================================
__device__ __forceinline__ float wsel(
    const float* __restrict__ Wf, const float* __restrict__ Wg,
    const float* __restrict__ Wh, int k, int gn)
{
    if (gn < 32)  return Wf[k * 32 + gn];
    if (gn < 64)  return Wg[k * 32 + gn - 32];
    return Wh[k * 128 + gn - 64];
}
__device__ __forceinline__ float bsel(
    const float* __restrict__ bf, const float* __restrict__ bg,
    const float* __restrict__ bh, int gn)
{
    if (gn < 32)  return bf[gn];
    if (gn < 64)  return bg[gn - 32];
    return bh[gn - 64];
}

__global__ __launch_bounds__(256) void proj_mma(
    const float* __restrict__ x,
    const float* __restrict__ Wf, const float* __restrict__ bf,
    const float* __restrict__ Wg, const float* __restrict__ bg,
    const float* __restrict__ Wh, const float* __restrict__ bh)
{
    __shared__ uint32_t sBhi[8 * 8 * 64];
    __shared__ uint32_t sBlo[8 * 8 * 64];

    const int tid = threadIdx.x;
    const int w = tid >> 5, lane = tid & 31;
    const int gq = lane >> 2, t = lane & 3;
    const int bm = blockIdx.x * 128;
    const int bn = blockIdx.y * 64;

    const int m0 = bm + w * 16 + gq;
    const float* xr0 = &x[(size_t)m0 * CH];
    const float* xr1 = xr0 + 8 * CH;

    float c[8][4];
    #pragma unroll
    for (int nb = 0; nb < 8; nb++)
        #pragma unroll
        for (int j = 0; j < 4; j++) c[nb][j] = 0.0f;

    #pragma unroll
    for (int ph = 0; ph < 2; ph++) {
        __syncthreads();
        #pragma unroll
        for (int task = tid; task < 8 * 8 * 32; task += 256) {
            int ln = task & 31, kb = (task >> 5) & 7, nb = task >> 8;
            int g = ln >> 2, tt = ln & 3;
            int gn = bn + nb * 8 + g;
            int k = (ph * 8 + kb) * 16 + 2 * tt;
            float w0 = wsel(Wf, Wg, Wh, k,     gn);
            float w1 = wsel(Wf, Wg, Wh, k + 1, gn);
            float w2 = wsel(Wf, Wg, Wh, k + 8, gn);
            float w3 = wsel(Wf, Wg, Wh, k + 9, gn);
            uint32_t h0, l0, h1, l1;
            hilo2(make_float2(w0, w1), h0, l0);
            hilo2(make_float2(w2, w3), h1, l1);
            int idx = ((nb * 8 + kb) * 32 + ln) * 2;
            sBhi[idx] = h0; sBhi[idx + 1] = h1;
            sBlo[idx] = l0; sBlo[idx + 1] = l1;
        }
        __syncthreads();

        #pragma unroll
        for (int kb = 0; kb < 8; kb++) {
            const int kc = (ph * 8 + kb) * 16;
            uint32_t Ahi[4], Alo[4];
            float2 v;
            v = *(const float2*)&xr0[kc + 2 * t];     hilo2(v, Ahi[0], Alo[0]);
            v = *(const float2*)&xr1[kc + 2 * t];     hilo2(v, Ahi[1], Alo[1]);
            v = *(const float2*)&xr0[kc + 2 * t + 8]; hilo2(v, Ahi[2], Alo[2]);
            v = *(const float2*)&xr1[kc + 2 * t + 8]; hilo2(v, Ahi[3], Alo[3]);
            #pragma unroll
            for (int nb = 0; nb < 8; nb++) {
                uint2 bh2 = *(const uint2*)&sBhi[((nb * 8 + kb) * 32 + lane) * 2];
                uint2 bl2 = *(const uint2*)&sBlo[((nb * 8 + kb) * 32 + lane) * 2];
                mma16816(c[nb], Ahi, bh2.x, bh2.y);
                mma16816(c[nb], Ahi, bl2.x, bl2.y);
                mma16816(c[nb], Alo, bh2.x, bh2.y);
            }
        }
    }

    // epilogue
    #pragma unroll
    for (int nb = 0; nb < 8; nb++) {
        int gn0 = bn + nb * 8 + 2 * t;
        float b0 = bsel(bf, bg, bh, gn0);
        float b1 = bsel(bf, bg, bh, gn0 + 1);
        float v00 = c[nb][0] + b0, v01 = c[nb][1] + b1;
        float v10 = c[nb][2] + b0, v11 = c[nb][3] + b1;
        if (gn0 < 32) {            // f stream
            int p = fpos(gn0);
            uint32_t h, l;
            hilo2(make_float2(v00, v01), h, l);
            g_f16hi[(size_t)m0 * 16 + p] = h;
            g_f16lo[(size_t)m0 * 16 + p] = l;
            hilo2(make_float2(v10, v11), h, l);
            g_f16hi[(size_t)(m0 + 8) * 16 + p] = h;
            g_f16lo[(size_t)(m0 + 8) * 16 + p] = l;
        } else if (gn0 < 64) {     // g stream
            int p = fpos(gn0 - 32);
            uint32_t h, l;
            hilo2(make_float2(v00, v01), h, l);
            g_g16hi[(size_t)m0 * 16 + p] = h;
            g_g16lo[(size_t)m0 * 16 + p] = l;
            hilo2(make_float2(v10, v11), h, l);
            g_g16hi[(size_t)(m0 + 8) * 16 + p] = h;
            g_g16lo[(size_t)(m0 + 8) * 16 + p] = l;
        } else {                   // h^T permuted fp16
            int dv0 = gn0 - 64;
            int bb0 = m0 >> 12, pix0 = m0 & 4095;
            int m1r = m0 + 8, bb1 = m1r >> 12, pix1 = m1r & 4095;
            int pi0 = htperm(pix0), pi1 = htperm(pix1);
            size_t r00 = ((size_t)bb0 * DV + dv0) * HW;
            size_t r01 = ((size_t)bb0 * DV + dv0 + 1) * HW;
            size_t r10 = ((size_t)bb1 * DV + dv0) * HW;
            size_t r11 = ((size_t)bb1 * DV + dv0 + 1) * HW;
            g_ht_h[r00 + pi0] = __float2half_rn(v00);
            g_ht_h[r01 + pi0] = __float2half_rn(v01);
            g_ht_h[r10 + pi1] = __float2half_rn(v10);
            g_ht_h[r11 + pi1] = __float2half_rn(v11);
        }
    }
}

// ===========================================================================
// Kernel 2: mma.sync flash attention. 128 queries/CTA, 8 warps (16 rows each),
// cp.async 16B double-buffered staging, conditional O rescale.
// ===========================================================================
__global__ __launch_bounds__(256) void attn_kernel()
{
    // double-buffered fragment stores: F hi/lo 2x4KB each, Ht 2x16KB = 48KB
    __shared__ __align__(16) uint32_t sFhi[2][1024];
    __shared__ __align__(16) uint32_t sFlo[2][1024];
    __shared__ __align__(16) uint32_t sHt[2][4096];

    const int tid = threadIdx.x;
    const int w = tid >> 5, lane = tid & 31;
    const int gq = lane >> 2, t = lane & 3;
    const int b = blockIdx.y, q0 = blockIdx.x * 128;
    const size_t bbase = (size_t)b * HW;
    const int qr = q0 + w * 16;

    const uint32_t aFhi[2] = { smem_u32(&sFhi[0][0]), smem_u32(&sFhi[1][0]) };
    const uint32_t aFlo[2] = { smem_u32(&sFlo[0][0]), smem_u32(&sFlo[1][0]) };
    const uint32_t aHt[2]  = { smem_u32(&sHt[0][0]),  smem_u32(&sHt[1][0]) };

    // ---- G A-fragments (once) from fragment stream ----
    uint32_t Ahi[2][4], Alo[2][4];
    {
        const uint32_t* ghr0 = &g_g16hi[(bbase + qr + gq) * 16];
        const uint32_t* glr0 = &g_g16lo[(bbase + qr + gq) * 16];
        const uint32_t* ghr1 = ghr0 + 8 * 16;
        const uint32_t* glr1 = glr0 + 8 * 16;
        #pragma unroll
        for (int kb = 0; kb < 2; kb++) {
            uint2 u;
            u = *(const uint2*)&ghr0[kb * 8 + 2 * t]; Ahi[kb][0] = u.x; Ahi[kb][2] = u.y;
            u = *(const uint2*)&ghr1[kb * 8 + 2 * t]; Ahi[kb][1] = u.x; Ahi[kb][3] = u.y;
            u = *(const uint2*)&glr0[kb * 8 + 2 * t]; Alo[kb][0] = u.x; Alo[kb][2] = u.y;
            u = *(const uint2*)&glr1[kb * 8 + 2 * t]; Alo[kb][1] = u.x; Alo[kb][3] = u.y;
        }
    }

    // staging: 512 F tasks + 1024 Ht tasks of 16B each
    auto stage = [&](int k0, int buf) {
        #pragma unroll
        for (int i = 0; i < 2; i++) {
            int task = tid + 256 * i;
            int n = task >> 3, rem = task & 7;
            int kb = (rem >> 2) & 1, tp = (rem >> 1) & 1, arr = rem & 1;
            size_t goff = (bbase + k0 + n) * 16 + kb * 8 + tp * 4;
            const uint32_t* gp = arr ? &g_f16lo[goff] : &g_f16hi[goff];
            int sidx = ((n >> 3) * 2 + kb) * 64 + ((n & 7) * 4 + 2 * tp) * 2;
            uint32_t sp = (arr ? aFlo[buf] : aFhi[buf]) + sidx * 4;
            cpa16(sp, gp);
        }
        #pragma unroll
        for (int i = 0; i < 4; i++) {
            int task = tid + 256 * i;
            int n = task >> 3, rem = task & 7;
            int ks = (rem >> 1) & 3, tp = rem & 1;
            const uint32_t* hrow =
                (const uint32_t*)(g_ht_h + ((size_t)b * DV + n) * HW + k0);
            const uint32_t* gp = hrow + ks * 8 + 4 * tp;
            int sidx = ((n >> 3) * 4 + ks) * 64 + ((n & 7) * 4 + 2 * tp) * 2;
            cpa16(aHt[buf] + sidx * 4, gp);
        }
        CP_COMMIT();
    };

    float O[16][4];
    #pragma unroll
    for (int i = 0; i < 16; i++)
        #pragma unroll
        for (int j = 0; j < 4; j++) O[i][j] = 0.0f;
    float m0 = -1e30f, m1 = -1e30f, l0 = 0.0f, l1 = 0.0f;

    stage(0, 0);

    for (int kt = 0; kt < 64; ++kt) {
        const int buf = kt & 1;
        __syncthreads();                       // prior compute done with buf^1
        if (kt < 63) {
            stage((kt + 1) * 64, buf ^ 1);
            asm volatile("cp.async.wait_group 1;" ::: "memory");
        } else {
            asm volatile("cp.async.wait_group 0;" ::: "memory");
        }
        __syncthreads();                       // tile kt visible to all

        const uint32_t* fhi = sFhi[buf];
        const uint32_t* flo = sFlo[buf];
        const uint32_t* ht  = sHt[buf];

        // ---- S = G F^T (3-pass hi/lo) ----
        float S[8][4];
        float mt0 = -1e30f, mt1 = -1e30f;
        #pragma unroll
        for (int nb = 0; nb < 8; nb++) {
            float* c = S[nb];
            c[0] = c[1] = c[2] = c[3] = 0.0f;
            uint2 bh0 = *(const uint2*)&fhi[(nb * 2 + 0) * 64 + lane * 2];
            uint2 bh1 = *(const uint2*)&fhi[(nb * 2 + 1) * 64 + lane * 2];
            uint2 bl0 = *(const uint2*)&flo[(nb * 2 + 0) * 64 + lane * 2];
            uint2 bl1 = *(const uint2*)&flo[(nb * 2 + 1) * 64 + lane * 2];
            mma16816(c, Ahi[0], bh0.x, bh0.y);
            mma16816(c, Ahi[1], bh1.x, bh1.y);
            mma16816(c, Ahi[0], bl0.x, bl0.y);
            mma16816(c, Ahi[1], bl1.x, bl1.y);
            mma16816(c, Alo[0], bh0.x, bh0.y);
            mma16816(c, Alo[1], bh1.x, bh1.y);
            mt0 = fmaxf(mt0, fmaxf(c[0], c[1]));
            mt1 = fmaxf(mt1, fmaxf(c[2], c[3]));
        }
        mt0 = fmaxf(mt0, __shfl_xor_sync(0xffffffffu, mt0, 1));
        mt0 = fmaxf(mt0, __shfl_xor_sync(0xffffffffu, mt0, 2));
        mt1 = fmaxf(mt1, __shfl_xor_sync(0xffffffffu, mt1, 1));
        mt1 = fmaxf(mt1, __shfl_xor_sync(0xffffffffu, mt1, 2));
        const bool newmax = (mt0 > m0) | (mt1 > m1);
        float mn0 = fmaxf(m0, mt0), mn1 = fmaxf(m1, mt1);
        float corr0 = __expf(m0 - mn0), corr1 = __expf(m1 - mn1);
        m0 = mn0; m1 = mn1;

        uint32_t Pa[4][4];
        float ps0 = 0.0f, ps1 = 0.0f;
        #pragma unroll
        for (int nb = 0; nb < 8; nb++) {
            float p0 = __expf(S[nb][0] - mn0);
            float p1 = __expf(S[nb][1] - mn0);
            float p2 = __expf(S[nb][2] - mn1);
            float p3 = __expf(S[nb][3] - mn1);
            ps0 += p0 + p1;
            ps1 += p2 + p3;
            int j = nb >> 1, hi = (nb & 1) << 1;
            Pa[j][hi + 0] = packh2(p0, p1);
            Pa[j][hi + 1] = packh2(p2, p3);
        }
        l0 = l0 * corr0 + ps0;
        l1 = l1 * corr1 + ps1;

        if (newmax) {
            #pragma unroll
            for (int nb = 0; nb < 16; nb++) {
                O[nb][0] *= corr0; O[nb][1] *= corr0;
                O[nb][2] *= corr1; O[nb][3] *= corr1;
            }
        }
        #pragma unroll
        for (int nb = 0; nb < 16; nb++) {
            #pragma unroll
            for (int j = 0; j < 4; j++) {
                uint2 bb = *(const uint2*)&ht[(nb * 4 + j) * 64 + lane * 2];
                mma16816(O[nb], Pa[j], bb.x, bb.y);
            }
        }
    }

    l0 += __shfl_xor_sync(0xffffffffu, l0, 1);
    l0 += __shfl_xor_sync(0xffffffffu, l0, 2);
    l1 += __shfl_xor_sync(0xffffffffu, l1, 1);
    l1 += __shfl_xor_sync(0xffffffffu, l1, 2);
    float rl0 = 1.0f / l0, rl1 = 1.0f / l1;

    float* out0 = &g_o[(bbase + qr + gq) * DV + 2 * t];
    float* out1 = &g_o[(bbase + qr + gq + 8) * DV + 2 * t];
    #pragma unroll
    for (int nb = 0; nb < 16; nb++) {
        *(float2*)&out0[nb * 8] = make_float2(O[nb][0] * rl0, O[nb][1] * rl0);
        *(float2*)&out1[nb * 8] = make_float2(O[nb][2] * rl1, O[nb][3] * rl1);
    }
}

// ===========================================================================
// Kernel 3: out = x + o@Wo + bo on tensor path. CTA = 128 rows x 64 cols.
// ===========================================================================
__global__ __launch_bounds__(256) void out_mma(
    const float* __restrict__ x,
    const float* __restrict__ Wo,
    const float* __restrict__ bo,
    float* __restrict__ out)
{
    __shared__ uint32_t sBhi[8 * 8 * 64];
    __shared__ uint32_t sBlo[8 * 8 * 64];

    const int tid = threadIdx.x;
    const int w = tid >> 5, lane = tid & 31;
    const int gq = lane >> 2, t = lane & 3;
    const int bm = blockIdx.x * 128;
    const int bn = blockIdx.y * 64;

    #pragma unroll
    for (int task = tid; task < 8 * 8 * 32; task += 256) {
        int ln = task & 31, kb = (task >> 5) & 7, nb = task >> 8;
        int g = ln >> 2, tt = ln & 3;
        int gn = bn + nb * 8 + g;
        int k = kb * 16 + 2 * tt;
        float w0 = Wo[(size_t)(k)     * CH + gn];
        float w1 = Wo[(size_t)(k + 1) * CH + gn];
        float w2 = Wo[(size_t)(k + 8) * CH + gn];
        float w3 = Wo[(size_t)(k + 9) * CH + gn];
        uint32_t h0, l0, h1, l1;
        hilo2(make_float2(w0, w1), h0, l0);
        hilo2(make_float2(w2, w3), h1, l1);
        int idx = ((nb * 8 + kb) * 32 + ln) * 2;
        sBhi[idx] = h0; sBhi[idx + 1] = h1;
        sBlo[idx] = l0; sBlo[idx + 1] = l1;
    }
    __syncthreads();

    const int m0 = bm + w * 16 + gq;
    const float* ar0 = &g_o[(size_t)m0 * DV];
    const float* ar1 = ar0 + 8 * DV;

    float c[8][4];
    #pragma unroll
    for (int nb = 0; nb < 8; nb++)
        #pragma unroll
        for (int j = 0; j < 4; j++) c[nb][j] = 0.0f;

    #pragma unroll
    for (int kb = 0; kb < 8; kb++) {
        const int kc = kb * 16;
        uint32_t Ahi[4], Alo[4];
        float2 v;
        v = *(const float2*)&ar0[kc + 2 * t];     hilo2(v, Ahi[0], Alo[0]);
        v = *(const float2*)&ar1[kc + 2 * t];     hilo2(v, Ahi[1], Alo[1]);
        v = *(const float2*)&ar0[kc + 2 * t + 8]; hilo2(v, Ahi[2], Alo[2]);
        v = *(const float2*)&ar1[kc + 2 * t + 8]; hilo2(v, Ahi[3], Alo[3]);
        #pragma unroll
        for (int nb = 0; nb < 8; nb++) {
            uint2 bh2 = *(const uint2*)&sBhi[((nb * 8 + kb) * 32 + lane) * 2];
            uint2 bl2 = *(const uint2*)&sBlo[((nb * 8 + kb) * 32 + lane) * 2];
            mma16816(c[nb], Ahi, bh2.x, bh2.y);
            mma16816(c[nb], Ahi, bl2.x, bl2.y);
            mma16816(c[nb], Alo, bh2.x, bh2.y);
        }
    }

    #pragma unroll
    for (int nb = 0; nb < 8; nb++) {
        int gn0 = bn + nb * 8 + 2 * t;
        float2 bb = *(const float2*)&bo[gn0];
        float2 x0 = *(const float2*)&x[(size_t)m0 * CH + gn0];
        float2 x1 = *(const float2*)&x[(size_t)(m0 + 8) * CH + gn0];
        *(float2*)&out[(size_t)m0 * CH + gn0] =
            make_float2(x0.x + c[nb][0] + bb.x, x0.y + c[nb][1] + bb.y);
        *(float2*)&out[(size_t)(m0 + 8) * CH + gn0] =
            make_float2(x1.x + c[nb][2] + bb.x, x1.y + c[nb][3] + bb.y);
    }
}

// ===========================================================================
extern "C" void kernel_launch(void* const* d_in, const int* in_sizes, int n_in,
                              void* d_out, int out_size)
{
    const float* x  = (const float*)d_in[0];
    const float* Wf = (const float*)d_in[1];
    const float* bf = (const float*)d_in[2];
    const float* Wg = (const float*)d_in[3];
    const float* bg = (const float*)d_in[4];
    const float* Wh = (const float*)d_in[5];
    const float* bh = (const float*)d_in[6];
    const float* Wo = (const float*)d_in[7];
    const float* bo = (const float*)d_in[8];
    float* out = (float*)d_out;

    proj_mma<<<dim3(MTOT / 128, 3), 256>>>(x, Wf, bf, Wg, bg, Wh, bh);
    attn_kernel<<<dim3(HW / 128, BATCH), 256>>>();
    out_mma<<<dim3(MTOT / 128, 4), 256>>>(x, Wo, bo, out);
}

// round 7
// speedup vs baseline: 30.6860x; 1.1677x over previous
#include <cuda_runtime.h>
#include <cuda_fp16.h>
#include <cstdint>

// ---------------------------------------------------------------------------
// SelfAttention_2826088481408 — GB300 sm_103a (base sm_103 PTX target)
// B=16, hw=4096, C=256, d=32, dv=128
// R7: attn at 2 CTAs/SM (__launch_bounds__(256,2) + register hygiene).
// ---------------------------------------------------------------------------

#define BATCH 16
#define HW    4096
#define CH    256
#define DK    32
#define DV    128
#define MTOT  (BATCH * HW)

__device__ __align__(16) uint32_t g_f16hi[(size_t)MTOT * 16];
__device__ __align__(16) uint32_t g_f16lo[(size_t)MTOT * 16];
__device__ __align__(16) uint32_t g_g16hi[(size_t)MTOT * 16];
__device__ __align__(16) uint32_t g_g16lo[(size_t)MTOT * 16];
__device__ __align__(16) __half g_ht_h[(size_t)BATCH * DV * HW];
__device__ float g_o[(size_t)MTOT * DV];

// ---- mma.sync m16n8k16 f16 -------------------------------------------------
__device__ __forceinline__ void mma16816(float* c, const uint32_t* a,
                                         uint32_t b0, uint32_t b1) {
    asm volatile(
        "mma.sync.aligned.m16n8k16.row.col.f32.f16.f16.f32 "
        "{%0,%1,%2,%3}, {%4,%5,%6,%7}, {%8,%9}, {%0,%1,%2,%3};"
        : "+f"(c[0]), "+f"(c[1]), "+f"(c[2]), "+f"(c[3])
        : "r"(a[0]), "r"(a[1]), "r"(a[2]), "r"(a[3]), "r"(b0), "r"(b1));
}

__device__ __forceinline__ void hilo2(float2 v, uint32_t& hi, uint32_t& lo) {
    __half hx = __float2half_rn(v.x), hy = __float2half_rn(v.y);
    float rx = v.x - __half2float(hx);
    float ry = v.y - __half2float(hy);
    __half2 h = __halves2half2(hx, hy);
    __half2 l = __floats2half2_rn(rx, ry);
    hi = *(uint32_t*)&h;
    lo = *(uint32_t*)&l;
}
__device__ __forceinline__ uint32_t packh2(float x, float y) {
    __half2 h = __floats2half2_rn(x, y);
    return *(uint32_t*)&h;
}

__device__ __forceinline__ uint32_t smem_u32(const void* p) {
    uint32_t a;
    asm("{ .reg .u64 t; cvta.to.shared.u64 t, %1; cvt.u32.u64 %0, t; }"
        : "=r"(a) : "l"(p));
    return a;
}
__device__ __forceinline__ void cpa16(uint32_t s, const void* g) {
    asm volatile(
        "{ .reg .u64 gp; cvta.to.global.u64 gp, %1;"
        "  cp.async.cg.shared.global [%0], [gp], 16; }"
        :: "r"(s), "l"(g) : "memory");
}
#define CP_COMMIT() asm volatile("cp.async.commit_group;" ::: "memory")

__device__ __forceinline__ int fpos(int c) {
    int j = c >> 1, kb = j >> 3, j8 = j & 7;
    return kb * 8 + (j8 & 3) * 2 + (j8 >> 2);
}
__device__ __forceinline__ int htperm(int pix) {
    int j = (pix >> 1) & 7;
    return (pix >> 4) * 16 + ((j & 3) * 2 + (j >> 2)) * 2 + (pix & 1);
}

// ===========================================================================
// Kernel 1: proj GEMM (unchanged from R6).
// ===========================================================================
__device__ __forceinline__ float wsel(
    const float* __restrict__ Wf, const float* __restrict__ Wg,
    const float* __restrict__ Wh, int k, int gn)
{
    if (gn < 32)  return Wf[k * 32 + gn];
    if (gn < 64)  return Wg[k * 32 + gn - 32];
    return Wh[k * 128 + gn - 64];
}
__device__ __forceinline__ float bsel(
    const float* __restrict__ bf, const float* __restrict__ bg,
    const float* __restrict__ bh, int gn)
{
    if (gn < 32)  return bf[gn];
    if (gn < 64)  return bg[gn - 32];
    return bh[gn - 64];
}

__global__ __launch_bounds__(256) void proj_mma(
    const float* __restrict__ x,
    const float* __restrict__ Wf, const float* __restrict__ bf,
    const float* __restrict__ Wg, const float* __restrict__ bg,
    const float* __restrict__ Wh, const float* __restrict__ bh)
{
    __shared__ uint32_t sBhi[8 * 8 * 64];
    __shared__ uint32_t sBlo[8 * 8 * 64];

    const int tid = threadIdx.x;
    const int w = tid >> 5, lane = tid & 31;
    const int gq = lane >> 2, t = lane & 3;
    const int bm = blockIdx.x * 128;
    const int bn = blockIdx.y * 64;

    const int m0 = bm + w * 16 + gq;
    const float* xr0 = &x[(size_t)m0 * CH];
    const float* xr1 = xr0 + 8 * CH;

    float c[8][4];
    #pragma unroll
    for (int nb = 0; nb < 8; nb++)
        #pragma unroll
        for (int j = 0; j < 4; j++) c[nb][j] = 0.0f;

    #pragma unroll
    for (int ph = 0; ph < 2; ph++) {
        __syncthreads();
        #pragma unroll
        for (int task = tid; task < 8 * 8 * 32; task += 256) {
            int ln = task & 31, kb = (task >> 5) & 7, nb = task >> 8;
            int g = ln >> 2, tt = ln & 3;
            int gn = bn + nb * 8 + g;
            int k = (ph * 8 + kb) * 16 + 2 * tt;
            float w0 = wsel(Wf, Wg, Wh, k,     gn);
            float w1 = wsel(Wf, Wg, Wh, k + 1, gn);
            float w2 = wsel(Wf, Wg, Wh, k + 8, gn);
            float w3 = wsel(Wf, Wg, Wh, k + 9, gn);
            uint32_t h0, l0, h1, l1;
            hilo2(make_float2(w0, w1), h0, l0);
            hilo2(make_float2(w2, w3), h1, l1);
            int idx = ((nb * 8 + kb) * 32 + ln) * 2;
            sBhi[idx] = h0; sBhi[idx + 1] = h1;
            sBlo[idx] = l0; sBlo[idx + 1] = l1;
        }
        __syncthreads();

        #pragma unroll
        for (int kb = 0; kb < 8; kb++) {
            const int kc = (ph * 8 + kb) * 16;
            uint32_t Ahi[4], Alo[4];
            float2 v;
            v = *(const float2*)&xr0[kc + 2 * t];     hilo2(v, Ahi[0], Alo[0]);
            v = *(const float2*)&xr1[kc + 2 * t];     hilo2(v, Ahi[1], Alo[1]);
            v = *(const float2*)&xr0[kc + 2 * t + 8]; hilo2(v, Ahi[2], Alo[2]);
            v = *(const float2*)&xr1[kc + 2 * t + 8]; hilo2(v, Ahi[3], Alo[3]);
            #pragma unroll
            for (int nb = 0; nb < 8; nb++) {
                uint2 bh2 = *(const uint2*)&sBhi[((nb * 8 + kb) * 32 + lane) * 2];
                uint2 bl2 = *(const uint2*)&sBlo[((nb * 8 + kb) * 32 + lane) * 2];
                mma16816(c[nb], Ahi, bh2.x, bh2.y);
                mma16816(c[nb], Ahi, bl2.x, bl2.y);
                mma16816(c[nb], Alo, bh2.x, bh2.y);
            }
        }
    }

    #pragma unroll
    for (int nb = 0; nb < 8; nb++) {
        int gn0 = bn + nb * 8 + 2 * t;
        float b0 = bsel(bf, bg, bh, gn0);
        float b1 = bsel(bf, bg, bh, gn0 + 1);
        float v00 = c[nb][0] + b0, v01 = c[nb][1] + b1;
        float v10 = c[nb][2] + b0, v11 = c[nb][3] + b1;
        if (gn0 < 32) {
            int p = fpos(gn0);
            uint32_t h, l;
            hilo2(make_float2(v00, v01), h, l);
            g_f16hi[(size_t)m0 * 16 + p] = h;
            g_f16lo[(size_t)m0 * 16 + p] = l;
            hilo2(make_float2(v10, v11), h, l);
            g_f16hi[(size_t)(m0 + 8) * 16 + p] = h;
            g_f16lo[(size_t)(m0 + 8) * 16 + p] = l;
        } else if (gn0 < 64) {
            int p = fpos(gn0 - 32);
            uint32_t h, l;
            hilo2(make_float2(v00, v01), h, l);
            g_g16hi[(size_t)m0 * 16 + p] = h;
            g_g16lo[(size_t)m0 * 16 + p] = l;
            hilo2(make_float2(v10, v11), h, l);
            g_g16hi[(size_t)(m0 + 8) * 16 + p] = h;
            g_g16lo[(size_t)(m0 + 8) * 16 + p] = l;
        } else {
            int dv0 = gn0 - 64;
            int bb0 = m0 >> 12, pix0 = m0 & 4095;
            int m1r = m0 + 8, bb1 = m1r >> 12, pix1 = m1r & 4095;
            int pi0 = htperm(pix0), pi1 = htperm(pix1);
            size_t r00 = ((size_t)bb0 * DV + dv0) * HW;
            size_t r01 = ((size_t)bb0 * DV + dv0 + 1) * HW;
            size_t r10 = ((size_t)bb1 * DV + dv0) * HW;
            size_t r11 = ((size_t)bb1 * DV + dv0 + 1) * HW;
            g_ht_h[r00 + pi0] = __float2half_rn(v00);
            g_ht_h[r01 + pi0] = __float2half_rn(v01);
            g_ht_h[r10 + pi1] = __float2half_rn(v10);
            g_ht_h[r11 + pi1] = __float2half_rn(v11);
        }
    }
}

// ===========================================================================
// Kernel 2: mma.sync flash attention, 2 CTAs/SM target.
// ===========================================================================
__global__ void __launch_bounds__(256, 2) attn_kernel()
{
    __shared__ __align__(16) uint32_t sFhi[2][1024];
    __shared__ __align__(16) uint32_t sFlo[2][1024];
    __shared__ __align__(16) uint32_t sHt[2][4096];

    const int tid = threadIdx.x;
    const int w = tid >> 5, lane = tid & 31;
    const int gq = lane >> 2, t = lane & 3;
    const int b = blockIdx.y, q0 = blockIdx.x * 128;
    const size_t bbase = (size_t)b * HW;
    const int qr = q0 + w * 16;

    // ---- G A-fragments (once) ----
    uint32_t Ahi[2][4], Alo[2][4];
    {
        const uint32_t* ghr0 = &g_g16hi[(bbase + qr + gq) * 16];
        const uint32_t* glr0 = &g_g16lo[(bbase + qr + gq) * 16];
        const uint32_t* ghr1 = ghr0 + 8 * 16;
        const uint32_t* glr1 = glr0 + 8 * 16;
        #pragma unroll
        for (int kb = 0; kb < 2; kb++) {
            uint2 u;
            u = *(const uint2*)&ghr0[kb * 8 + 2 * t]; Ahi[kb][0] = u.x; Ahi[kb][2] = u.y;
            u = *(const uint2*)&ghr1[kb * 8 + 2 * t]; Ahi[kb][1] = u.x; Ahi[kb][3] = u.y;
            u = *(const uint2*)&glr0[kb * 8 + 2 * t]; Alo[kb][0] = u.x; Alo[kb][2] = u.y;
            u = *(const uint2*)&glr1[kb * 8 + 2 * t]; Alo[kb][1] = u.x; Alo[kb][3] = u.y;
        }
    }

    auto stage = [&](int k0, int buf) {
        const uint32_t fhiB = smem_u32(&sFhi[buf][0]);
        const uint32_t floB = smem_u32(&sFlo[buf][0]);
        const uint32_t htB  = smem_u32(&sHt[buf][0]);
        #pragma unroll
        for (int i = 0; i < 2; i++) {
            int task = tid + 256 * i;
            int n = task >> 3, rem = task & 7;
            int kb = (rem >> 2) & 1, tp = (rem >> 1) & 1, arr = rem & 1;
            size_t goff = (bbase + k0 + n) * 16 + kb * 8 + tp * 4;
            const uint32_t* gp = arr ? &g_f16lo[goff] : &g_f16hi[goff];
            int sidx = ((n >> 3) * 2 + kb) * 64 + ((n & 7) * 4 + 2 * tp) * 2;
            uint32_t sp = (arr ? floB : fhiB) + sidx * 4;
            cpa16(sp, gp);
        }
        #pragma unroll
        for (int i = 0; i < 4; i++) {
            int task = tid + 256 * i;
            int n = task >> 3, rem = task & 7;
            int ks = (rem >> 1) & 3, tp = rem & 1;
            const uint32_t* hrow =
                (const uint32_t*)(g_ht_h + ((size_t)b * DV + n) * HW + k0);
            const uint32_t* gp = hrow + ks * 8 + 4 * tp;
            int sidx = ((n >> 3) * 4 + ks) * 64 + ((n & 7) * 4 + 2 * tp) * 2;
            cpa16(htB + sidx * 4, gp);
        }
        CP_COMMIT();
    };

    float O[16][4];
    #pragma unroll
    for (int i = 0; i < 16; i++)
        #pragma unroll
        for (int j = 0; j < 4; j++) O[i][j] = 0.0f;
    float m0 = -1e30f, m1 = -1e30f, l0 = 0.0f, l1 = 0.0f;

    stage(0, 0);

    for (int kt = 0; kt < 64; ++kt) {
        const int buf = kt & 1;
        __syncthreads();
        if (kt < 63) {
            stage((kt + 1) * 64, buf ^ 1);
            asm volatile("cp.async.wait_group 1;" ::: "memory");
        } else {
            asm volatile("cp.async.wait_group 0;" ::: "memory");
        }
        __syncthreads();

        const uint32_t* fhi = sFhi[buf];
        const uint32_t* flo = sFlo[buf];
        const uint32_t* ht  = sHt[buf];

        // ---- S = G F^T (3-pass hi/lo) ----
        float S[8][4];
        float mt0 = -1e30f, mt1 = -1e30f;
        #pragma unroll
        for (int nb = 0; nb < 8; nb++) {
            float* c = S[nb];
            c[0] = c[1] = c[2] = c[3] = 0.0f;
            uint2 bh0 = *(const uint2*)&fhi[(nb * 2 + 0) * 64 + lane * 2];
            uint2 bh1 = *(const uint2*)&fhi[(nb * 2 + 1) * 64 + lane * 2];
            uint2 bl0 = *(const uint2*)&flo[(nb * 2 + 0) * 64 + lane * 2];
            uint2 bl1 = *(const uint2*)&flo[(nb * 2 + 1) * 64 + lane * 2];
            mma16816(c, Ahi[0], bh0.x, bh0.y);
            mma16816(c, Ahi[1], bh1.x, bh1.y);
            mma16816(c, Ahi[0], bl0.x, bl0.y);
            mma16816(c, Ahi[1], bl1.x, bl1.y);
            mma16816(c, Alo[0], bh0.x, bh0.y);
            mma16816(c, Alo[1], bh1.x, bh1.y);
            mt0 = fmaxf(mt0, fmaxf(c[0], c[1]));
            mt1 = fmaxf(mt1, fmaxf(c[2], c[3]));
        }
        mt0 = fmaxf(mt0, __shfl_xor_sync(0xffffffffu, mt0, 1));
        mt0 = fmaxf(mt0, __shfl_xor_sync(0xffffffffu, mt0, 2));
        mt1 = fmaxf(mt1, __shfl_xor_sync(0xffffffffu, mt1, 1));
        mt1 = fmaxf(mt1, __shfl_xor_sync(0xffffffffu, mt1, 2));
        const bool newmax = (mt0 > m0) | (mt1 > m1);
        float mn0 = fmaxf(m0, mt0), mn1 = fmaxf(m1, mt1);
        float corr0 = __expf(m0 - mn0), corr1 = __expf(m1 - mn1);
        m0 = mn0; m1 = mn1;

        // exp consumes S; Pa overlays its registers
        uint32_t Pa[4][4];
        float ps0 = 0.0f, ps1 = 0.0f;
        #pragma unroll
        for (int nb = 0; nb < 8; nb++) {
            float p0 = __expf(S[nb][0] - mn0);
            float p1 = __expf(S[nb][1] - mn0);
            float p2 = __expf(S[nb][2] - mn1);
            float p3 = __expf(S[nb][3] - mn1);
            ps0 += p0 + p1;
            ps1 += p2 + p3;
            int j = nb >> 1, hi = (nb & 1) << 1;
            Pa[j][hi + 0] = packh2(p0, p1);
            Pa[j][hi + 1] = packh2(p2, p3);
        }
        l0 = l0 * corr0 + ps0;
        l1 = l1 * corr1 + ps1;

        if (newmax) {
            #pragma unroll
            for (int nb = 0; nb < 16; nb++) {
                O[nb][0] *= corr0; O[nb][1] *= corr0;
                O[nb][2] *= corr1; O[nb][3] *= corr1;
            }
        }
        #pragma unroll
        for (int nb = 0; nb < 16; nb++) {
            #pragma unroll
            for (int j = 0; j < 4; j++) {
                uint2 bb = *(const uint2*)&ht[(nb * 4 + j) * 64 + lane * 2];
                mma16816(O[nb], Pa[j], bb.x, bb.y);
            }
        }
    }

    l0 += __shfl_xor_sync(0xffffffffu, l0, 1);
    l0 += __shfl_xor_sync(0xffffffffu, l0, 2);
    l1 += __shfl_xor_sync(0xffffffffu, l1, 1);
    l1 += __shfl_xor_sync(0xffffffffu, l1, 2);
    float rl0 = 1.0f / l0, rl1 = 1.0f / l1;

    float* out0 = &g_o[(bbase + qr + gq) * DV + 2 * t];
    float* out1 = &g_o[(bbase + qr + gq + 8) * DV + 2 * t];
    #pragma unroll
    for (int nb = 0; nb < 16; nb++) {
        *(float2*)&out0[nb * 8] = make_float2(O[nb][0] * rl0, O[nb][1] * rl0);
        *(float2*)&out1[nb * 8] = make_float2(O[nb][2] * rl1, O[nb][3] * rl1);
    }
}

// ===========================================================================
// Kernel 3: out = x + o@Wo + bo (unchanged from R6).
// ===========================================================================
__global__ __launch_bounds__(256) void out_mma(
    const float* __restrict__ x,
    const float* __restrict__ Wo,
    const float* __restrict__ bo,
    float* __restrict__ out)
{
    __shared__ uint32_t sBhi[8 * 8 * 64];
    __shared__ uint32_t sBlo[8 * 8 * 64];

    const int tid = threadIdx.x;
    const int w = tid >> 5, lane = tid & 31;
    const int gq = lane >> 2, t = lane & 3;
    const int bm = blockIdx.x * 128;
    const int bn = blockIdx.y * 64;

    #pragma unroll
    for (int task = tid; task < 8 * 8 * 32; task += 256) {
        int ln = task & 31, kb = (task >> 5) & 7, nb = task >> 8;
        int g = ln >> 2, tt = ln & 3;
        int gn = bn + nb * 8 + g;
        int k = kb * 16 + 2 * tt;
        float w0 = Wo[(size_t)(k)     * CH + gn];
        float w1 = Wo[(size_t)(k + 1) * CH + gn];
        float w2 = Wo[(size_t)(k + 8) * CH + gn];
        float w3 = Wo[(size_t)(k + 9) * CH + gn];
        uint32_t h0, l0, h1, l1;
        hilo2(make_float2(w0, w1), h0, l0);
        hilo2(make_float2(w2, w3), h1, l1);
        int idx = ((nb * 8 + kb) * 32 + ln) * 2;
        sBhi[idx] = h0; sBhi[idx + 1] = h1;
        sBlo[idx] = l0; sBlo[idx + 1] = l1;
    }
    __syncthreads();

    const int m0 = bm + w * 16 + gq;
    const float* ar0 = &g_o[(size_t)m0 * DV];
    const float* ar1 = ar0 + 8 * DV;

    float c[8][4];
    #pragma unroll
    for (int nb = 0; nb < 8; nb++)
        #pragma unroll
        for (int j = 0; j < 4; j++) c[nb][j] = 0.0f;

    #pragma unroll
    for (int kb = 0; kb < 8; kb++) {
        const int kc = kb * 16;
        uint32_t Ahi[4], Alo[4];
        float2 v;
        v = *(const float2*)&ar0[kc + 2 * t];     hilo2(v, Ahi[0], Alo[0]);
        v = *(const float2*)&ar1[kc + 2 * t];     hilo2(v, Ahi[1], Alo[1]);
        v = *(const float2*)&ar0[kc + 2 * t + 8]; hilo2(v, Ahi[2], Alo[2]);
        v = *(const float2*)&ar1[kc + 2 * t + 8]; hilo2(v, Ahi[3], Alo[3]);
        #pragma unroll
        for (int nb = 0; nb < 8; nb++) {
            uint2 bh2 = *(const uint2*)&sBhi[((nb * 8 + kb) * 32 + lane) * 2];
            uint2 bl2 = *(const uint2*)&sBlo[((nb * 8 + kb) * 32 + lane) * 2];
            mma16816(c[nb], Ahi, bh2.x, bh2.y);
            mma16816(c[nb], Ahi, bl2.x, bl2.y);
            mma16816(c[nb], Alo, bh2.x, bh2.y);
        }
    }

    #pragma unroll
    for (int nb = 0; nb < 8; nb++) {
        int gn0 = bn + nb * 8 + 2 * t;
        float2 bb = *(const float2*)&bo[gn0];
        float2 x0 = *(const float2*)&x[(size_t)m0 * CH + gn0];
        float2 x1 = *(const float2*)&x[(size_t)(m0 + 8) * CH + gn0];
        *(float2*)&out[(size_t)m0 * CH + gn0] =
            make_float2(x0.x + c[nb][0] + bb.x, x0.y + c[nb][1] + bb.y);
        *(float2*)&out[(size_t)(m0 + 8) * CH + gn0] =
            make_float2(x1.x + c[nb][2] + bb.x, x1.y + c[nb][3] + bb.y);
    }
}

// ===========================================================================
extern "C" void kernel_launch(void* const* d_in, const int* in_sizes, int n_in,
                              void* d_out, int out_size)
{
    const float* x  = (const float*)d_in[0];
    const float* Wf = (const float*)d_in[1];
    const float* bf = (const float*)d_in[2];
    const float* Wg = (const float*)d_in[3];
    const float* bg = (const float*)d_in[4];
    const float* Wh = (const float*)d_in[5];
    const float* bh = (const float*)d_in[6];
    const float* Wo = (const float*)d_in[7];
    const float* bo = (const float*)d_in[8];
    float* out = (float*)d_out;

    proj_mma<<<dim3(MTOT / 128, 3), 256>>>(x, Wf, bf, Wg, bg, Wh, bh);
    attn_kernel<<<dim3(HW / 128, BATCH), 256>>>();
    out_mma<<<dim3(MTOT / 128, 4), 256>>>(x, Wo, bo, out);
}

// round 8
// speedup vs baseline: 35.5989x; 1.1601x over previous
#include <cuda_runtime.h>
#include <cuda_fp16.h>
#include <cstdint>

// ---------------------------------------------------------------------------
// SelfAttention_2826088481408 — GB300 sm_103a (base sm_103 PTX target)
// B=16, hw=4096, C=256, d=32, dv=128
// R8: attn QK = (Ghi+Glo)*Fhi (2-pass, no F-lo buffer), fp16x2 ex2 softmax.
// ---------------------------------------------------------------------------

#define BATCH 16
#define HW    4096
#define CH    256
#define DK    32
#define DV    128
#define MTOT  (BATCH * HW)

__device__ __align__(16) uint32_t g_f16hi[(size_t)MTOT * 16];
__device__ __align__(16) uint32_t g_g16hi[(size_t)MTOT * 16];
__device__ __align__(16) uint32_t g_g16lo[(size_t)MTOT * 16];
__device__ __align__(16) __half g_ht_h[(size_t)BATCH * DV * HW];
__device__ float g_o[(size_t)MTOT * DV];

// ---- mma.sync m16n8k16 f16 -------------------------------------------------
__device__ __forceinline__ void mma16816(float* c, const uint32_t* a,
                                         uint32_t b0, uint32_t b1) {
    asm volatile(
        "mma.sync.aligned.m16n8k16.row.col.f32.f16.f16.f32 "
        "{%0,%1,%2,%3}, {%4,%5,%6,%7}, {%8,%9}, {%0,%1,%2,%3};"
        : "+f"(c[0]), "+f"(c[1]), "+f"(c[2]), "+f"(c[3])
        : "r"(a[0]), "r"(a[1]), "r"(a[2]), "r"(a[3]), "r"(b0), "r"(b1));
}

__device__ __forceinline__ void hilo2(float2 v, uint32_t& hi, uint32_t& lo) {
    __half hx = __float2half_rn(v.x), hy = __float2half_rn(v.y);
    float rx = v.x - __half2float(hx);
    float ry = v.y - __half2float(hy);
    __half2 h = __halves2half2(hx, hy);
    __half2 l = __floats2half2_rn(rx, ry);
    hi = *(uint32_t*)&h;
    lo = *(uint32_t*)&l;
}

// pack two floats to f16x2 (x -> low, y -> high)
__device__ __forceinline__ uint32_t cvt_f16x2(float x, float y) {
    uint32_t r;
    asm("cvt.rn.f16x2.f32 %0, %1, %2;" : "=r"(r) : "f"(y), "f"(x));
    return r;
}
__device__ __forceinline__ uint32_t ex2_f16x2(uint32_t a) {
    uint32_t r;
    asm("ex2.approx.f16x2 %0, %1;" : "=r"(r) : "r"(a));
    return r;
}
__device__ __forceinline__ float2 h2f2(uint32_t p) {
    __half2 h = *(__half2*)&p;
    return __half22float2(h);
}

__device__ __forceinline__ uint32_t smem_u32(const void* p) {
    uint32_t a;
    asm("{ .reg .u64 t; cvta.to.shared.u64 t, %1; cvt.u32.u64 %0, t; }"
        : "=r"(a) : "l"(p));
    return a;
}
__device__ __forceinline__ void cpa16(uint32_t s, const void* g) {
    asm volatile(
        "{ .reg .u64 gp; cvta.to.global.u64 gp, %1;"
        "  cp.async.cg.shared.global [%0], [gp], 16; }"
        :: "r"(s), "l"(g) : "memory");
}
#define CP_COMMIT() asm volatile("cp.async.commit_group;" ::: "memory")

__device__ __forceinline__ int fpos(int c) {
    int j = c >> 1, kb = j >> 3, j8 = j & 7;
    return kb * 8 + (j8 & 3) * 2 + (j8 >> 2);
}
__device__ __forceinline__ int htperm(int pix) {
    int j = (pix >> 1) & 7;
    return (pix >> 4) * 16 + ((j & 3) * 2 + (j >> 2)) * 2 + (pix & 1);
}

// ===========================================================================
// Kernel 1: proj GEMM. (f-lo stream removed; otherwise unchanged.)
// ===========================================================================
__device__ __forceinline__ float wsel(
    const float* __restrict__ Wf, const float* __restrict__ Wg,
    const float* __restrict__ Wh, int k, int gn)
{
    if (gn < 32)  return Wf[k * 32 + gn];
    if (gn < 64)  return Wg[k * 32 + gn - 32];
    return Wh[k * 128 + gn - 64];
}
__device__ __forceinline__ float bsel(
    const float* __restrict__ bf, const float* __restrict__ bg,
    const float* __restrict__ bh, int gn)
{
    if (gn < 32)  return bf[gn];
    if (gn < 64)  return bg[gn - 32];
    return bh[gn - 64];
}

__global__ __launch_bounds__(256) void proj_mma(
    const float* __restrict__ x,
    const float* __restrict__ Wf, const float* __restrict__ bf,
    const float* __restrict__ Wg, const float* __restrict__ bg,
    const float* __restrict__ Wh, const float* __restrict__ bh)
{
    __shared__ uint32_t sBhi[8 * 8 * 64];
    __shared__ uint32_t sBlo[8 * 8 * 64];

    const int tid = threadIdx.x;
    const int w = tid >> 5, lane = tid & 31;
    const int gq = lane >> 2, t = lane & 3;
    const int bm = blockIdx.x * 128;
    const int bn = blockIdx.y * 64;

    const int m0 = bm + w * 16 + gq;
    const float* xr0 = &x[(size_t)m0 * CH];
    const float* xr1 = xr0 + 8 * CH;

    float c[8][4];
    #pragma unroll
    for (int nb = 0; nb < 8; nb++)
        #pragma unroll
        for (int j = 0; j < 4; j++) c[nb][j] = 0.0f;

    #pragma unroll
    for (int ph = 0; ph < 2; ph++) {
        __syncthreads();
        #pragma unroll
        for (int task = tid; task < 8 * 8 * 32; task += 256) {
            int ln = task & 31, kb = (task >> 5) & 7, nb = task >> 8;
            int g = ln >> 2, tt = ln & 3;
            int gn = bn + nb * 8 + g;
            int k = (ph * 8 + kb) * 16 + 2 * tt;
            float w0 = wsel(Wf, Wg, Wh, k,     gn);
            float w1 = wsel(Wf, Wg, Wh, k + 1, gn);
            float w2 = wsel(Wf, Wg, Wh, k + 8, gn);
            float w3 = wsel(Wf, Wg, Wh, k + 9, gn);
            uint32_t h0, l0, h1, l1;
            hilo2(make_float2(w0, w1), h0, l0);
            hilo2(make_float2(w2, w3), h1, l1);
            int idx = ((nb * 8 + kb) * 32 + ln) * 2;
            sBhi[idx] = h0; sBhi[idx + 1] = h1;
            sBlo[idx] = l0; sBlo[idx + 1] = l1;
        }
        __syncthreads();

        #pragma unroll
        for (int kb = 0; kb < 8; kb++) {
            const int kc = (ph * 8 + kb) * 16;
            uint32_t Ahi[4], Alo[4];
            float2 v;
            v = *(const float2*)&xr0[kc + 2 * t];     hilo2(v, Ahi[0], Alo[0]);
            v = *(const float2*)&xr1[kc + 2 * t];     hilo2(v, Ahi[1], Alo[1]);
            v = *(const float2*)&xr0[kc + 2 * t + 8]; hilo2(v, Ahi[2], Alo[2]);
            v = *(const float2*)&xr1[kc + 2 * t + 8]; hilo2(v, Ahi[3], Alo[3]);
            #pragma unroll
            for (int nb = 0; nb < 8; nb++) {
                uint2 bh2 = *(const uint2*)&sBhi[((nb * 8 + kb) * 32 + lane) * 2];
                uint2 bl2 = *(const uint2*)&sBlo[((nb * 8 + kb) * 32 + lane) * 2];
                mma16816(c[nb], Ahi, bh2.x, bh2.y);
                mma16816(c[nb], Ahi, bl2.x, bl2.y);
                mma16816(c[nb], Alo, bh2.x, bh2.y);
            }
        }
    }

    #pragma unroll
    for (int nb = 0; nb < 8; nb++) {
        int gn0 = bn + nb * 8 + 2 * t;
        float b0 = bsel(bf, bg, bh, gn0);
        float b1 = bsel(bf, bg, bh, gn0 + 1);
        float v00 = c[nb][0] + b0, v01 = c[nb][1] + b1;
        float v10 = c[nb][2] + b0, v11 = c[nb][3] + b1;
        if (gn0 < 32) {            // f: hi stream only
            int p = fpos(gn0);
            uint32_t h, l;
            hilo2(make_float2(v00, v01), h, l);
            g_f16hi[(size_t)m0 * 16 + p] = h;
            hilo2(make_float2(v10, v11), h, l);
            g_f16hi[(size_t)(m0 + 8) * 16 + p] = h;
        } else if (gn0 < 64) {     // g: hi + lo streams
            int p = fpos(gn0 - 32);
            uint32_t h, l;
            hilo2(make_float2(v00, v01), h, l);
            g_g16hi[(size_t)m0 * 16 + p] = h;
            g_g16lo[(size_t)m0 * 16 + p] = l;
            hilo2(make_float2(v10, v11), h, l);
            g_g16hi[(size_t)(m0 + 8) * 16 + p] = h;
            g_g16lo[(size_t)(m0 + 8) * 16 + p] = l;
        } else {                   // h^T permuted fp16
            int dv0 = gn0 - 64;
            int bb0 = m0 >> 12, pix0 = m0 & 4095;
            int m1r = m0 + 8, bb1 = m1r >> 12, pix1 = m1r & 4095;
            int pi0 = htperm(pix0), pi1 = htperm(pix1);
            size_t r00 = ((size_t)bb0 * DV + dv0) * HW;
            size_t r01 = ((size_t)bb0 * DV + dv0 + 1) * HW;
            size_t r10 = ((size_t)bb1 * DV + dv0) * HW;
            size_t r11 = ((size_t)bb1 * DV + dv0 + 1) * HW;
            g_ht_h[r00 + pi0] = __float2half_rn(v00);
            g_ht_h[r01 + pi0] = __float2half_rn(v01);
            g_ht_h[r10 + pi1] = __float2half_rn(v10);
            g_ht_h[r11 + pi1] = __float2half_rn(v11);
        }
    }
}

// ===========================================================================
// Kernel 2: mma.sync flash attention, 2 CTAs/SM.
// S = (Ghi+Glo)*Fhi (2 passes); p via ex2.approx.f16x2 (output IS P frag).
// ===========================================================================
__global__ void __launch_bounds__(256, 2) attn_kernel()
{
    __shared__ __align__(16) uint32_t sFhi[2][1024];
    __shared__ __align__(16) uint32_t sHt[2][4096];

    const int tid = threadIdx.x;
    const int w = tid >> 5, lane = tid & 31;
    const int gq = lane >> 2, t = lane & 3;
    const int b = blockIdx.y, q0 = blockIdx.x * 128;
    const size_t bbase = (size_t)b * HW;
    const int qr = q0 + w * 16;
    const float L2E = 1.4426950408889634f;

    // ---- G A-fragments (once) ----
    uint32_t Ahi[2][4], Alo[2][4];
    {
        const uint32_t* ghr0 = &g_g16hi[(bbase + qr + gq) * 16];
        const uint32_t* glr0 = &g_g16lo[(bbase + qr + gq) * 16];
        const uint32_t* ghr1 = ghr0 + 8 * 16;
        const uint32_t* glr1 = glr0 + 8 * 16;
        #pragma unroll
        for (int kb = 0; kb < 2; kb++) {
            uint2 u;
            u = *(const uint2*)&ghr0[kb * 8 + 2 * t]; Ahi[kb][0] = u.x; Ahi[kb][2] = u.y;
            u = *(const uint2*)&ghr1[kb * 8 + 2 * t]; Ahi[kb][1] = u.x; Ahi[kb][3] = u.y;
            u = *(const uint2*)&glr0[kb * 8 + 2 * t]; Alo[kb][0] = u.x; Alo[kb][2] = u.y;
            u = *(const uint2*)&glr1[kb * 8 + 2 * t]; Alo[kb][1] = u.x; Alo[kb][3] = u.y;
        }
    }

    auto stage = [&](int k0, int buf) {
        const uint32_t fhiB = smem_u32(&sFhi[buf][0]);
        const uint32_t htB  = smem_u32(&sHt[buf][0]);
        {   // F hi: 256 tasks of 16B
            int task = tid;
            int n = task >> 2, rem = task & 3;
            int kb = (rem >> 1) & 1, tp = rem & 1;
            size_t goff = (bbase + k0 + n) * 16 + kb * 8 + tp * 4;
            const uint32_t* gp = &g_f16hi[goff];
            int sidx = ((n >> 3) * 2 + kb) * 64 + ((n & 7) * 4 + 2 * tp) * 2;
            cpa16(fhiB + sidx * 4, gp);
        }
        #pragma unroll
        for (int i = 0; i < 4; i++) {   // Ht: 1024 tasks of 16B
            int task = tid + 256 * i;
            int n = task >> 3, rem = task & 7;
            int ks = (rem >> 1) & 3, tp = rem & 1;
            const uint32_t* hrow =
                (const uint32_t*)(g_ht_h + ((size_t)b * DV + n) * HW + k0);
            const uint32_t* gp = hrow + ks * 8 + 4 * tp;
            int sidx = ((n >> 3) * 4 + ks) * 64 + ((n & 7) * 4 + 2 * tp) * 2;
            cpa16(htB + sidx * 4, gp);
        }
        CP_COMMIT();
    };

    float O[16][4];
    #pragma unroll
    for (int i = 0; i < 16; i++)
        #pragma unroll
        for (int j = 0; j < 4; j++) O[i][j] = 0.0f;
    float m0 = -1e30f, m1 = -1e30f, l0 = 0.0f, l1 = 0.0f;

    stage(0, 0);

    for (int kt = 0; kt < 64; ++kt) {
        const int buf = kt & 1;
        __syncthreads();
        if (kt < 63) {
            stage((kt + 1) * 64, buf ^ 1);
            asm volatile("cp.async.wait_group 1;" ::: "memory");
        } else {
            asm volatile("cp.async.wait_group 0;" ::: "memory");
        }
        __syncthreads();

        const uint32_t* fhi = sFhi[buf];
        const uint32_t* ht  = sHt[buf];

        // ---- S = (Ghi + Glo) * Fhi ----
        float S[8][4];
        float mt0 = -1e30f, mt1 = -1e30f;
        #pragma unroll
        for (int nb = 0; nb < 8; nb++) {
            float* c = S[nb];
            c[0] = c[1] = c[2] = c[3] = 0.0f;
            uint2 bh0 = *(const uint2*)&fhi[(nb * 2 + 0) * 64 + lane * 2];
            uint2 bh1 = *(const uint2*)&fhi[(nb * 2 + 1) * 64 + lane * 2];
            mma16816(c, Ahi[0], bh0.x, bh0.y);
            mma16816(c, Ahi[1], bh1.x, bh1.y);
            mma16816(c, Alo[0], bh0.x, bh0.y);
            mma16816(c, Alo[1], bh1.x, bh1.y);
            mt0 = fmaxf(mt0, fmaxf(c[0], c[1]));
            mt1 = fmaxf(mt1, fmaxf(c[2], c[3]));
        }
        mt0 = fmaxf(mt0, __shfl_xor_sync(0xffffffffu, mt0, 1));
        mt0 = fmaxf(mt0, __shfl_xor_sync(0xffffffffu, mt0, 2));
        mt1 = fmaxf(mt1, __shfl_xor_sync(0xffffffffu, mt1, 1));
        mt1 = fmaxf(mt1, __shfl_xor_sync(0xffffffffu, mt1, 2));
        const bool newmax = (mt0 > m0) | (mt1 > m1);
        float mn0 = fmaxf(m0, mt0), mn1 = fmaxf(m1, mt1);
        float corr0 = __expf(m0 - mn0), corr1 = __expf(m1 - mn1);
        m0 = mn0; m1 = mn1;
        const float nm0 = -mn0 * L2E, nm1 = -mn1 * L2E;

        // ---- p = ex2((s - m)*log2e) in fp16x2; ex2 output IS the P frag ----
        uint32_t Pa[4][4];
        float ps0 = 0.0f, ps1 = 0.0f;
        #pragma unroll
        for (int nb = 0; nb < 8; nb++) {
            float t0 = fmaf(S[nb][0], L2E, nm0);
            float t1 = fmaf(S[nb][1], L2E, nm0);
            float t2 = fmaf(S[nb][2], L2E, nm1);
            float t3 = fmaf(S[nb][3], L2E, nm1);
            uint32_t P01 = ex2_f16x2(cvt_f16x2(t0, t1));
            uint32_t P23 = ex2_f16x2(cvt_f16x2(t2, t3));
            float2 q0 = h2f2(P01);
            float2 q1 = h2f2(P23);
            ps0 += q0.x + q0.y;
            ps1 += q1.x + q1.y;
            int j = nb >> 1, hi = (nb & 1) << 1;
            Pa[j][hi + 0] = P01;
            Pa[j][hi + 1] = P23;
        }
        l0 = l0 * corr0 + ps0;
        l1 = l1 * corr1 + ps1;

        if (newmax) {
            #pragma unroll
            for (int nb = 0; nb < 16; nb++) {
                O[nb][0] *= corr0; O[nb][1] *= corr0;
                O[nb][2] *= corr1; O[nb][3] *= corr1;
            }
        }
        #pragma unroll
        for (int nb = 0; nb < 16; nb++) {
            #pragma unroll
            for (int j = 0; j < 4; j++) {
                uint2 bb = *(const uint2*)&ht[(nb * 4 + j) * 64 + lane * 2];
                mma16816(O[nb], Pa[j], bb.x, bb.y);
            }
        }
    }

    l0 += __shfl_xor_sync(0xffffffffu, l0, 1);
    l0 += __shfl_xor_sync(0xffffffffu, l0, 2);
    l1 += __shfl_xor_sync(0xffffffffu, l1, 1);
    l1 += __shfl_xor_sync(0xffffffffu, l1, 2);
    float rl0 = 1.0f / l0, rl1 = 1.0f / l1;

    float* out0 = &g_o[(bbase + qr + gq) * DV + 2 * t];
    float* out1 = &g_o[(bbase + qr + gq + 8) * DV + 2 * t];
    #pragma unroll
    for (int nb = 0; nb < 16; nb++) {
        *(float2*)&out0[nb * 8] = make_float2(O[nb][0] * rl0, O[nb][1] * rl0);
        *(float2*)&out1[nb * 8] = make_float2(O[nb][2] * rl1, O[nb][3] * rl1);
    }
}

// ===========================================================================
// Kernel 3: out = x + o@Wo + bo (unchanged).
// ===========================================================================
__global__ __launch_bounds__(256) void out_mma(
    const float* __restrict__ x,
    const float* __restrict__ Wo,
    const float* __restrict__ bo,
    float* __restrict__ out)
{
    __shared__ uint32_t sBhi[8 * 8 * 64];
    __shared__ uint32_t sBlo[8 * 8 * 64];

    const int tid = threadIdx.x;
    const int w = tid >> 5, lane = tid & 31;
    const int gq = lane >> 2, t = lane & 3;
    const int bm = blockIdx.x * 128;
    const int bn = blockIdx.y * 64;

    #pragma unroll
    for (int task = tid; task < 8 * 8 * 32; task += 256) {
        int ln = task & 31, kb = (task >> 5) & 7, nb = task >> 8;
        int g = ln >> 2, tt = ln & 3;
        int gn = bn + nb * 8 + g;
        int k = kb * 16 + 2 * tt;
        float w0 = Wo[(size_t)(k)     * CH + gn];
        float w1 = Wo[(size_t)(k + 1) * CH + gn];
        float w2 = Wo[(size_t)(k + 8) * CH + gn];
        float w3 = Wo[(size_t)(k + 9) * CH + gn];
        uint32_t h0, l0, h1, l1;
        hilo2(make_float2(w0, w1), h0, l0);
        hilo2(make_float2(w2, w3), h1, l1);
        int idx = ((nb * 8 + kb) * 32 + ln) * 2;
        sBhi[idx] = h0; sBhi[idx + 1] = h1;
        sBlo[idx] = l0; sBlo[idx + 1] = l1;
    }
    __syncthreads();

    const int m0 = bm + w * 16 + gq;
    const float* ar0 = &g_o[(size_t)m0 * DV];
    const float* ar1 = ar0 + 8 * DV;

    float c[8][4];
    #pragma unroll
    for (int nb = 0; nb < 8; nb++)
        #pragma unroll
        for (int j = 0; j < 4; j++) c[nb][j] = 0.0f;

    #pragma unroll
    for (int kb = 0; kb < 8; kb++) {
        const int kc = kb * 16;
        uint32_t Ahi[4], Alo[4];
        float2 v;
        v = *(const float2*)&ar0[kc + 2 * t];     hilo2(v, Ahi[0], Alo[0]);
        v = *(const float2*)&ar1[kc + 2 * t];     hilo2(v, Ahi[1], Alo[1]);
        v = *(const float2*)&ar0[kc + 2 * t + 8]; hilo2(v, Ahi[2], Alo[2]);
        v = *(const float2*)&ar1[kc + 2 * t + 8]; hilo2(v, Ahi[3], Alo[3]);
        #pragma unroll
        for (int nb = 0; nb < 8; nb++) {
            uint2 bh2 = *(const uint2*)&sBhi[((nb * 8 + kb) * 32 + lane) * 2];
            uint2 bl2 = *(const uint2*)&sBlo[((nb * 8 + kb) * 32 + lane) * 2];
            mma16816(c[nb], Ahi, bh2.x, bh2.y);
            mma16816(c[nb], Ahi, bl2.x, bl2.y);
            mma16816(c[nb], Alo, bh2.x, bh2.y);
        }
    }

    #pragma unroll
    for (int nb = 0; nb < 8; nb++) {
        int gn0 = bn + nb * 8 + 2 * t;
        float2 bb = *(const float2*)&bo[gn0];
        float2 x0 = *(const float2*)&x[(size_t)m0 * CH + gn0];
        float2 x1 = *(const float2*)&x[(size_t)(m0 + 8) * CH + gn0];
        *(float2*)&out[(size_t)m0 * CH + gn0] =
            make_float2(x0.x + c[nb][0] + bb.x, x0.y + c[nb][1] + bb.y);
        *(float2*)&out[(size_t)(m0 + 8) * CH + gn0] =
            make_float2(x1.x + c[nb][2] + bb.x, x1.y + c[nb][3] + bb.y);
    }
}

// ===========================================================================
extern "C" void kernel_launch(void* const* d_in, const int* in_sizes, int n_in,
                              void* d_out, int out_size)
{
    const float* x  = (const float*)d_in[0];
    const float* Wf = (const float*)d_in[1];
    const float* bf = (const float*)d_in[2];
    const float* Wg = (const float*)d_in[3];
    const float* bg = (const float*)d_in[4];
    const float* Wh = (const float*)d_in[5];
    const float* bh = (const float*)d_in[6];
    const float* Wo = (const float*)d_in[7];
    const float* bo = (const float*)d_in[8];
    float* out = (float*)d_out;

    proj_mma<<<dim3(MTOT / 128, 3), 256>>>(x, Wf, bf, Wg, bg, Wh, bh);
    attn_kernel<<<dim3(HW / 128, BATCH), 256>>>();
    out_mma<<<dim3(MTOT / 128, 4), 256>>>(x, Wo, bo, out);
}

// round 9
// speedup vs baseline: 36.3461x; 1.0210x over previous
#include <cuda_runtime.h>
#include <cuda_fp16.h>
#include <cstdint>

// ---------------------------------------------------------------------------
// SelfAttention_2826088481408 — GB300 sm_103a (base sm_103 PTX target)
// B=16, hw=4096, C=256, d=32, dv=128
// R9: proj 2-pass for h blocks; out single-pass fp16; attn 3-buffer pipeline
//     with one barrier per key tile.
// ---------------------------------------------------------------------------

#define BATCH 16
#define HW    4096
#define CH    256
#define DK    32
#define DV    128
#define MTOT  (BATCH * HW)

__device__ __align__(16) uint32_t g_f16hi[(size_t)MTOT * 16];
__device__ __align__(16) uint32_t g_g16hi[(size_t)MTOT * 16];
__device__ __align__(16) uint32_t g_g16lo[(size_t)MTOT * 16];
__device__ __align__(16) __half g_ht_h[(size_t)BATCH * DV * HW];
__device__ float g_o[(size_t)MTOT * DV];

// ---- mma.sync m16n8k16 f16 -------------------------------------------------
__device__ __forceinline__ void mma16816(float* c, const uint32_t* a,
                                         uint32_t b0, uint32_t b1) {
    asm volatile(
        "mma.sync.aligned.m16n8k16.row.col.f32.f16.f16.f32 "
        "{%0,%1,%2,%3}, {%4,%5,%6,%7}, {%8,%9}, {%0,%1,%2,%3};"
        : "+f"(c[0]), "+f"(c[1]), "+f"(c[2]), "+f"(c[3])
        : "r"(a[0]), "r"(a[1]), "r"(a[2]), "r"(a[3]), "r"(b0), "r"(b1));
}

__device__ __forceinline__ void hilo2(float2 v, uint32_t& hi, uint32_t& lo) {
    __half hx = __float2half_rn(v.x), hy = __float2half_rn(v.y);
    float rx = v.x - __half2float(hx);
    float ry = v.y - __half2float(hy);
    __half2 h = __halves2half2(hx, hy);
    __half2 l = __floats2half2_rn(rx, ry);
    hi = *(uint32_t*)&h;
    lo = *(uint32_t*)&l;
}

// pack two floats to f16x2 (x -> low, y -> high)
__device__ __forceinline__ uint32_t cvt_f16x2(float x, float y) {
    uint32_t r;
    asm("cvt.rn.f16x2.f32 %0, %1, %2;" : "=r"(r) : "f"(y), "f"(x));
    return r;
}
__device__ __forceinline__ uint32_t ex2_f16x2(uint32_t a) {
    uint32_t r;
    asm("ex2.approx.f16x2 %0, %1;" : "=r"(r) : "r"(a));
    return r;
}
__device__ __forceinline__ float2 h2f2(uint32_t p) {
    __half2 h = *(__half2*)&p;
    return __half22float2(h);
}

__device__ __forceinline__ uint32_t smem_u32(const void* p) {
    uint32_t a;
    asm("{ .reg .u64 t; cvta.to.shared.u64 t, %1; cvt.u32.u64 %0, t; }"
        : "=r"(a) : "l"(p));
    return a;
}
__device__ __forceinline__ void cpa16(uint32_t s, const void* g) {
    asm volatile(
        "{ .reg .u64 gp; cvta.to.global.u64 gp, %1;"
        "  cp.async.cg.shared.global [%0], [gp], 16; }"
        :: "r"(s), "l"(g) : "memory");
}
#define CP_COMMIT() asm volatile("cp.async.commit_group;" ::: "memory")

__device__ __forceinline__ int fpos(int c) {
    int j = c >> 1, kb = j >> 3, j8 = j & 7;
    return kb * 8 + (j8 & 3) * 2 + (j8 >> 2);
}
__device__ __forceinline__ int htperm(int pix) {
    int j = (pix >> 1) & 7;
    return (pix >> 4) * 16 + ((j & 3) * 2 + (j >> 2)) * 2 + (pix & 1);
}

// ===========================================================================
// Kernel 1: proj GEMM. 3-pass for f+g block (y==0), 2-pass for h blocks.
// ===========================================================================
__device__ __forceinline__ float wsel(
    const float* __restrict__ Wf, const float* __restrict__ Wg,
    const float* __restrict__ Wh, int k, int gn)
{
    if (gn < 32)  return Wf[k * 32 + gn];
    if (gn < 64)  return Wg[k * 32 + gn - 32];
    return Wh[k * 128 + gn - 64];
}
__device__ __forceinline__ float bsel(
    const float* __restrict__ bf, const float* __restrict__ bg,
    const float* __restrict__ bh, int gn)
{
    if (gn < 32)  return bf[gn];
    if (gn < 64)  return bg[gn - 32];
    return bh[gn - 64];
}

__global__ __launch_bounds__(256) void proj_mma(
    const float* __restrict__ x,
    const float* __restrict__ Wf, const float* __restrict__ bf,
    const float* __restrict__ Wg, const float* __restrict__ bg,
    const float* __restrict__ Wh, const float* __restrict__ bh)
{
    __shared__ uint32_t sBhi[8 * 8 * 64];
    __shared__ uint32_t sBlo[8 * 8 * 64];

    const int tid = threadIdx.x;
    const int w = tid >> 5, lane = tid & 31;
    const int gq = lane >> 2, t = lane & 3;
    const int bm = blockIdx.x * 128;
    const int bn = blockIdx.y * 64;
    const bool third = (blockIdx.y == 0);   // f+g block needs 3rd pass (g accuracy)

    const int m0 = bm + w * 16 + gq;
    const float* xr0 = &x[(size_t)m0 * CH];
    const float* xr1 = xr0 + 8 * CH;

    float c[8][4];
    #pragma unroll
    for (int nb = 0; nb < 8; nb++)
        #pragma unroll
        for (int j = 0; j < 4; j++) c[nb][j] = 0.0f;

    #pragma unroll
    for (int ph = 0; ph < 2; ph++) {
        __syncthreads();
        #pragma unroll
        for (int task = tid; task < 8 * 8 * 32; task += 256) {
            int ln = task & 31, kb = (task >> 5) & 7, nb = task >> 8;
            int g = ln >> 2, tt = ln & 3;
            int gn = bn + nb * 8 + g;
            int k = (ph * 8 + kb) * 16 + 2 * tt;
            float w0 = wsel(Wf, Wg, Wh, k,     gn);
            float w1 = wsel(Wf, Wg, Wh, k + 1, gn);
            float w2 = wsel(Wf, Wg, Wh, k + 8, gn);
            float w3 = wsel(Wf, Wg, Wh, k + 9, gn);
            uint32_t h0, l0, h1, l1;
            hilo2(make_float2(w0, w1), h0, l0);
            hilo2(make_float2(w2, w3), h1, l1);
            int idx = ((nb * 8 + kb) * 32 + ln) * 2;
            sBhi[idx] = h0; sBhi[idx + 1] = h1;
            sBlo[idx] = l0; sBlo[idx + 1] = l1;
        }
        __syncthreads();

        #pragma unroll
        for (int kb = 0; kb < 8; kb++) {
            const int kc = (ph * 8 + kb) * 16;
            uint32_t Ahi[4], Alo[4];
            float2 v;
            v = *(const float2*)&xr0[kc + 2 * t];     hilo2(v, Ahi[0], Alo[0]);
            v = *(const float2*)&xr1[kc + 2 * t];     hilo2(v, Ahi[1], Alo[1]);
            v = *(const float2*)&xr0[kc + 2 * t + 8]; hilo2(v, Ahi[2], Alo[2]);
            v = *(const float2*)&xr1[kc + 2 * t + 8]; hilo2(v, Ahi[3], Alo[3]);
            #pragma unroll
            for (int nb = 0; nb < 8; nb++) {
                uint2 bh2 = *(const uint2*)&sBhi[((nb * 8 + kb) * 32 + lane) * 2];
                uint2 bl2 = *(const uint2*)&sBlo[((nb * 8 + kb) * 32 + lane) * 2];
                mma16816(c[nb], Ahi, bh2.x, bh2.y);
                mma16816(c[nb], Ahi, bl2.x, bl2.y);
                if (third) mma16816(c[nb], Alo, bh2.x, bh2.y);
            }
        }
    }

    #pragma unroll
    for (int nb = 0; nb < 8; nb++) {
        int gn0 = bn + nb * 8 + 2 * t;
        float b0 = bsel(bf, bg, bh, gn0);
        float b1 = bsel(bf, bg, bh, gn0 + 1);
        float v00 = c[nb][0] + b0, v01 = c[nb][1] + b1;
        float v10 = c[nb][2] + b0, v11 = c[nb][3] + b1;
        if (gn0 < 32) {            // f: hi stream only
            int p = fpos(gn0);
            uint32_t h, l;
            hilo2(make_float2(v00, v01), h, l);
            g_f16hi[(size_t)m0 * 16 + p] = h;
            hilo2(make_float2(v10, v11), h, l);
            g_f16hi[(size_t)(m0 + 8) * 16 + p] = h;
        } else if (gn0 < 64) {     // g: hi + lo streams
            int p = fpos(gn0 - 32);
            uint32_t h, l;
            hilo2(make_float2(v00, v01), h, l);
            g_g16hi[(size_t)m0 * 16 + p] = h;
            g_g16lo[(size_t)m0 * 16 + p] = l;
            hilo2(make_float2(v10, v11), h, l);
            g_g16hi[(size_t)(m0 + 8) * 16 + p] = h;
            g_g16lo[(size_t)(m0 + 8) * 16 + p] = l;
        } else {                   // h^T permuted fp16
            int dv0 = gn0 - 64;
            int bb0 = m0 >> 12, pix0 = m0 & 4095;
            int m1r = m0 + 8, bb1 = m1r >> 12, pix1 = m1r & 4095;
            int pi0 = htperm(pix0), pi1 = htperm(pix1);
            size_t r00 = ((size_t)bb0 * DV + dv0) * HW;
            size_t r01 = ((size_t)bb0 * DV + dv0 + 1) * HW;
            size_t r10 = ((size_t)bb1 * DV + dv0) * HW;
            size_t r11 = ((size_t)bb1 * DV + dv0 + 1) * HW;
            g_ht_h[r00 + pi0] = __float2half_rn(v00);
            g_ht_h[r01 + pi0] = __float2half_rn(v01);
            g_ht_h[r10 + pi1] = __float2half_rn(v10);
            g_ht_h[r11 + pi1] = __float2half_rn(v11);
        }
    }
}

// ===========================================================================
// Kernel 2: mma.sync flash attention, 2 CTAs/SM, 3-buffer cp.async pipeline,
// ONE __syncthreads per key tile.
// ===========================================================================
#define TILE_SMEM 20480            // per-buffer bytes: F 4096 + Ht 16384
#define ATTN_SMEM (3 * TILE_SMEM)  // 61440

__global__ void __launch_bounds__(256, 2) attn_kernel()
{
    extern __shared__ __align__(16) char dsm[];

    const int tid = threadIdx.x;
    const int w = tid >> 5, lane = tid & 31;
    const int gq = lane >> 2, t = lane & 3;
    const int b = blockIdx.y, q0 = blockIdx.x * 128;
    const size_t bbase = (size_t)b * HW;
    const int qr = q0 + w * 16;
    const float L2E = 1.4426950408889634f;
    const uint32_t sbase = smem_u32(dsm);

    // ---- G A-fragments (once) ----
    uint32_t Ahi[2][4], Alo[2][4];
    {
        const uint32_t* ghr0 = &g_g16hi[(bbase + qr + gq) * 16];
        const uint32_t* glr0 = &g_g16lo[(bbase + qr + gq) * 16];
        const uint32_t* ghr1 = ghr0 + 8 * 16;
        const uint32_t* glr1 = glr0 + 8 * 16;
        #pragma unroll
        for (int kb = 0; kb < 2; kb++) {
            uint2 u;
            u = *(const uint2*)&ghr0[kb * 8 + 2 * t]; Ahi[kb][0] = u.x; Ahi[kb][2] = u.y;
            u = *(const uint2*)&ghr1[kb * 8 + 2 * t]; Ahi[kb][1] = u.x; Ahi[kb][3] = u.y;
            u = *(const uint2*)&glr0[kb * 8 + 2 * t]; Alo[kb][0] = u.x; Alo[kb][2] = u.y;
            u = *(const uint2*)&glr1[kb * 8 + 2 * t]; Alo[kb][1] = u.x; Alo[kb][3] = u.y;
        }
    }

    auto stage = [&](int k0, int buf) {
        const uint32_t fhiB = sbase + buf * TILE_SMEM;
        const uint32_t htB  = fhiB + 4096;
        {   // F hi: 256 tasks of 16B
            int task = tid;
            int n = task >> 2, rem = task & 3;
            int kb = (rem >> 1) & 1, tp = rem & 1;
            size_t goff = (bbase + k0 + n) * 16 + kb * 8 + tp * 4;
            const uint32_t* gp = &g_f16hi[goff];
            int sidx = ((n >> 3) * 2 + kb) * 64 + ((n & 7) * 4 + 2 * tp) * 2;
            cpa16(fhiB + sidx * 4, gp);
        }
        #pragma unroll
        for (int i = 0; i < 4; i++) {   // Ht: 1024 tasks of 16B
            int task = tid + 256 * i;
            int n = task >> 3, rem = task & 7;
            int ks = (rem >> 1) & 3, tp = rem & 1;
            const uint32_t* hrow =
                (const uint32_t*)(g_ht_h + ((size_t)b * DV + n) * HW + k0);
            const uint32_t* gp = hrow + ks * 8 + 4 * tp;
            int sidx = ((n >> 3) * 4 + ks) * 64 + ((n & 7) * 4 + 2 * tp) * 2;
            cpa16(htB + sidx * 4, gp);
        }
        CP_COMMIT();
    };

    float O[16][4];
    #pragma unroll
    for (int i = 0; i < 16; i++)
        #pragma unroll
        for (int j = 0; j < 4; j++) O[i][j] = 0.0f;
    float m0 = -1e30f, m1 = -1e30f, l0 = 0.0f, l1 = 0.0f;

    stage(0, 0);        // group 0
    stage(64, 1);       // group 1

    int buf = 0;
    for (int kt = 0; kt < 64; ++kt) {
        if (kt == 63) {
            asm volatile("cp.async.wait_group 0;" ::: "memory");
        } else {
            asm volatile("cp.async.wait_group 1;" ::: "memory");
        }
        __syncthreads();   // tile kt visible; compute kt-1 done (frees buf kt+2)
        if (kt + 2 < 64) {
            int nbuf = buf + 2; if (nbuf >= 3) nbuf -= 3;
            stage((kt + 2) * 64, nbuf);
        }

        const uint32_t* fhi = (const uint32_t*)(dsm + buf * TILE_SMEM);
        const uint32_t* ht  = (const uint32_t*)(dsm + buf * TILE_SMEM + 4096);

        // ---- S = (Ghi + Glo) * Fhi ----
        float S[8][4];
        float mt0 = -1e30f, mt1 = -1e30f;
        #pragma unroll
        for (int nb = 0; nb < 8; nb++) {
            float* c = S[nb];
            c[0] = c[1] = c[2] = c[3] = 0.0f;
            uint2 bh0 = *(const uint2*)&fhi[(nb * 2 + 0) * 64 + lane * 2];
            uint2 bh1 = *(const uint2*)&fhi[(nb * 2 + 1) * 64 + lane * 2];
            mma16816(c, Ahi[0], bh0.x, bh0.y);
            mma16816(c, Ahi[1], bh1.x, bh1.y);
            mma16816(c, Alo[0], bh0.x, bh0.y);
            mma16816(c, Alo[1], bh1.x, bh1.y);
            mt0 = fmaxf(mt0, fmaxf(c[0], c[1]));
            mt1 = fmaxf(mt1, fmaxf(c[2], c[3]));
        }
        mt0 = fmaxf(mt0, __shfl_xor_sync(0xffffffffu, mt0, 1));
        mt0 = fmaxf(mt0, __shfl_xor_sync(0xffffffffu, mt0, 2));
        mt1 = fmaxf(mt1, __shfl_xor_sync(0xffffffffu, mt1, 1));
        mt1 = fmaxf(mt1, __shfl_xor_sync(0xffffffffu, mt1, 2));
        const bool newmax = (mt0 > m0) | (mt1 > m1);
        float mn0 = fmaxf(m0, mt0), mn1 = fmaxf(m1, mt1);
        float corr0 = __expf(m0 - mn0), corr1 = __expf(m1 - mn1);
        m0 = mn0; m1 = mn1;
        const float nm0 = -mn0 * L2E, nm1 = -mn1 * L2E;

        // ---- p = ex2((s - m)*log2e) in fp16x2; ex2 output IS the P frag ----
        uint32_t Pa[4][4];
        float ps0 = 0.0f, ps1 = 0.0f;
        #pragma unroll
        for (int nb = 0; nb < 8; nb++) {
            float t0 = fmaf(S[nb][0], L2E, nm0);
            float t1 = fmaf(S[nb][1], L2E, nm0);
            float t2 = fmaf(S[nb][2], L2E, nm1);
            float t3 = fmaf(S[nb][3], L2E, nm1);
            uint32_t P01 = ex2_f16x2(cvt_f16x2(t0, t1));
            uint32_t P23 = ex2_f16x2(cvt_f16x2(t2, t3));
            float2 q0 = h2f2(P01);
            float2 q1 = h2f2(P23);
            ps0 += q0.x + q0.y;
            ps1 += q1.x + q1.y;
            int j = nb >> 1, hi = (nb & 1) << 1;
            Pa[j][hi + 0] = P01;
            Pa[j][hi + 1] = P23;
        }
        l0 = l0 * corr0 + ps0;
        l1 = l1 * corr1 + ps1;

        if (newmax) {
            #pragma unroll
            for (int nb = 0; nb < 16; nb++) {
                O[nb][0] *= corr0; O[nb][1] *= corr0;
                O[nb][2] *= corr1; O[nb][3] *= corr1;
            }
        }
        #pragma unroll
        for (int nb = 0; nb < 16; nb++) {
            #pragma unroll
            for (int j = 0; j < 4; j++) {
                uint2 bb = *(const uint2*)&ht[(nb * 4 + j) * 64 + lane * 2];
                mma16816(O[nb], Pa[j], bb.x, bb.y);
            }
        }

        if (++buf == 3) buf = 0;
    }

    l0 += __shfl_xor_sync(0xffffffffu, l0, 1);
    l0 += __shfl_xor_sync(0xffffffffu, l0, 2);
    l1 += __shfl_xor_sync(0xffffffffu, l1, 1);
    l1 += __shfl_xor_sync(0xffffffffu, l1, 2);
    float rl0 = 1.0f / l0, rl1 = 1.0f / l1;

    float* out0 = &g_o[(bbase + qr + gq) * DV + 2 * t];
    float* out1 = &g_o[(bbase + qr + gq + 8) * DV + 2 * t];
    #pragma unroll
    for (int nb = 0; nb < 16; nb++) {
        *(float2*)&out0[nb * 8] = make_float2(O[nb][0] * rl0, O[nb][1] * rl0);
        *(float2*)&out1[nb * 8] = make_float2(O[nb][2] * rl1, O[nb][3] * rl1);
    }
}

// ===========================================================================
// Kernel 3: out = x + o@Wo + bo. Single-pass fp16 (o*Wo term is ~0.3 of out;
// fp16 product error ~1e-4 on the result).
// ===========================================================================
__global__ __launch_bounds__(256) void out_mma(
    const float* __restrict__ x,
    const float* __restrict__ Wo,
    const float* __restrict__ bo,
    float* __restrict__ out)
{
    __shared__ uint32_t sBhi[8 * 8 * 64];

    const int tid = threadIdx.x;
    const int w = tid >> 5, lane = tid & 31;
    const int gq = lane >> 2, t = lane & 3;
    const int bm = blockIdx.x * 128;
    const int bn = blockIdx.y * 64;

    #pragma unroll
    for (int task = tid; task < 8 * 8 * 32; task += 256) {
        int ln = task & 31, kb = (task >> 5) & 7, nb = task >> 8;
        int g = ln >> 2, tt = ln & 3;
        int gn = bn + nb * 8 + g;
        int k = kb * 16 + 2 * tt;
        float w0 = Wo[(size_t)(k)     * CH + gn];
        float w1 = Wo[(size_t)(k + 1) * CH + gn];
        float w2 = Wo[(size_t)(k + 8) * CH + gn];
        float w3 = Wo[(size_t)(k + 9) * CH + gn];
        int idx = ((nb * 8 + kb) * 32 + ln) * 2;
        sBhi[idx]     = cvt_f16x2(w0, w1);
        sBhi[idx + 1] = cvt_f16x2(w2, w3);
    }
    __syncthreads();

    const int m0 = bm + w * 16 + gq;
    const float* ar0 = &g_o[(size_t)m0 * DV];
    const float* ar1 = ar0 + 8 * DV;

    float c[8][4];
    #pragma unroll
    for (int nb = 0; nb < 8; nb++)
        #pragma unroll
        for (int j = 0; j < 4; j++) c[nb][j] = 0.0f;

    #pragma unroll
    for (int kb = 0; kb < 8; kb++) {
        const int kc = kb * 16;
        uint32_t Ahi[4];
        float2 v;
        v = *(const float2*)&ar0[kc + 2 * t];     Ahi[0] = cvt_f16x2(v.x, v.y);
        v = *(const float2*)&ar1[kc + 2 * t];     Ahi[1] = cvt_f16x2(v.x, v.y);
        v = *(const float2*)&ar0[kc + 2 * t + 8]; Ahi[2] = cvt_f16x2(v.x, v.y);
        v = *(const float2*)&ar1[kc + 2 * t + 8]; Ahi[3] = cvt_f16x2(v.x, v.y);
        #pragma unroll
        for (int nb = 0; nb < 8; nb++) {
            uint2 bh2 = *(const uint2*)&sBhi[((nb * 8 + kb) * 32 + lane) * 2];
            mma16816(c[nb], Ahi, bh2.x, bh2.y);
        }
    }

    #pragma unroll
    for (int nb = 0; nb < 8; nb++) {
        int gn0 = bn + nb * 8 + 2 * t;
        float2 bb = *(const float2*)&bo[gn0];
        float2 x0 = *(const float2*)&x[(size_t)m0 * CH + gn0];
        float2 x1 = *(const float2*)&x[(size_t)(m0 + 8) * CH + gn0];
        *(float2*)&out[(size_t)m0 * CH + gn0] =
            make_float2(x0.x + c[nb][0] + bb.x, x0.y + c[nb][1] + bb.y);
        *(float2*)&out[(size_t)(m0 + 8) * CH + gn0] =
            make_float2(x1.x + c[nb][2] + bb.x, x1.y + c[nb][3] + bb.y);
    }
}

// ===========================================================================
extern "C" void kernel_launch(void* const* d_in, const int* in_sizes, int n_in,
                              void* d_out, int out_size)
{
    const float* x  = (const float*)d_in[0];
    const float* Wf = (const float*)d_in[1];
    const float* bf = (const float*)d_in[2];
    const float* Wg = (const float*)d_in[3];
    const float* bg = (const float*)d_in[4];
    const float* Wh = (const float*)d_in[5];
    const float* bh = (const float*)d_in[6];
    const float* Wo = (const float*)d_in[7];
    const float* bo = (const float*)d_in[8];
    float* out = (float*)d_out;

    proj_mma<<<dim3(MTOT / 128, 3), 256>>>(x, Wf, bf, Wg, bg, Wh, bh);

    cudaFuncSetAttribute(attn_kernel, cudaFuncAttributeMaxDynamicSharedMemorySize,
                         ATTN_SMEM);
    attn_kernel<<<dim3(HW / 128, BATCH), 256, ATTN_SMEM>>>();

    out_mma<<<dim3(MTOT / 128, 4), 256>>>(x, Wo, bo, out);
}

// round 11
// speedup vs baseline: 39.2760x; 1.0806x over previous
#include <cuda_runtime.h>
#include <cuda_fp16.h>
#include <cstdint>

// ---------------------------------------------------------------------------
// SelfAttention_2826088481408 — GB300 sm_103a (base sm_103 PTX target)
// B=16, hw=4096, C=256, d=32, dv=128
// R11: R10 with htperm segment stride fixed (128 -> 64). LDS.128 fragment
//      layouts, 4-buffer pipeline, proj/out A-register prefetch.
// ---------------------------------------------------------------------------

#define BATCH 16
#define HW    4096
#define CH    256
#define DK    32
#define DV    128
#define MTOT  (BATCH * HW)

__device__ __align__(16) uint32_t g_f16hi[(size_t)MTOT * 16];
__device__ __align__(16) uint32_t g_g16hi[(size_t)MTOT * 16];
__device__ __align__(16) uint32_t g_g16lo[(size_t)MTOT * 16];
__device__ __align__(16) __half g_ht_h[(size_t)BATCH * DV * HW];
__device__ float g_o[(size_t)MTOT * DV];

// ---- mma.sync m16n8k16 f16 -------------------------------------------------
__device__ __forceinline__ void mma16816(float* c, const uint32_t* a,
                                         uint32_t b0, uint32_t b1) {
    asm volatile(
        "mma.sync.aligned.m16n8k16.row.col.f32.f16.f16.f32 "
        "{%0,%1,%2,%3}, {%4,%5,%6,%7}, {%8,%9}, {%0,%1,%2,%3};"
        : "+f"(c[0]), "+f"(c[1]), "+f"(c[2]), "+f"(c[3])
        : "r"(a[0]), "r"(a[1]), "r"(a[2]), "r"(a[3]), "r"(b0), "r"(b1));
}

__device__ __forceinline__ void hilo2(float2 v, uint32_t& hi, uint32_t& lo) {
    __half hx = __float2half_rn(v.x), hy = __float2half_rn(v.y);
    float rx = v.x - __half2float(hx);
    float ry = v.y - __half2float(hy);
    __half2 h = __halves2half2(hx, hy);
    __half2 l = __floats2half2_rn(rx, ry);
    hi = *(uint32_t*)&h;
    lo = *(uint32_t*)&l;
}

__device__ __forceinline__ uint32_t cvt_f16x2(float x, float y) {
    uint32_t r;
    asm("cvt.rn.f16x2.f32 %0, %1, %2;" : "=r"(r) : "f"(y), "f"(x));
    return r;
}
__device__ __forceinline__ uint32_t ex2_f16x2(uint32_t a) {
    uint32_t r;
    asm("ex2.approx.f16x2 %0, %1;" : "=r"(r) : "r"(a));
    return r;
}
__device__ __forceinline__ float2 h2f2(uint32_t p) {
    __half2 h = *(__half2*)&p;
    return __half22float2(h);
}

__device__ __forceinline__ uint32_t smem_u32(const void* p) {
    uint32_t a;
    asm("{ .reg .u64 t; cvta.to.shared.u64 t, %1; cvt.u32.u64 %0, t; }"
        : "=r"(a) : "l"(p));
    return a;
}
__device__ __forceinline__ void cpa16(uint32_t s, const void* g) {
    asm volatile(
        "{ .reg .u64 gp; cvta.to.global.u64 gp, %1;"
        "  cp.async.cg.shared.global [%0], [gp], 16; }"
        :: "r"(s), "l"(g) : "memory");
}
#define CP_COMMIT() asm volatile("cp.async.commit_group;" ::: "memory")

// fragment-stream position for even channel c: lane tt's 4 regs contiguous.
__device__ __forceinline__ int fpos(int c) {
    int j = c >> 1;
    return (j & 3) * 4 + (j >> 3) * 2 + ((j >> 2) & 1);
}
// permuted h^T half-index: 64-key segments, 64 halves each (stride 64!).
__device__ __forceinline__ int htperm(int pix) {
    int p = (pix & 63) >> 1;
    int tt = p & 3, jj = p >> 3, half = (p >> 2) & 1;
    int upos = (jj >> 1) * 16 + tt * 4 + (jj & 1) * 2 + half;
    return (pix >> 6) * 64 + upos * 2 + (pix & 1);
}

// ===========================================================================
// Kernel 1: proj GEMM. 3-pass for f+g block, 2-pass for h blocks.
// A-operand register prefetch.
// ===========================================================================
__device__ __forceinline__ float wsel(
    const float* __restrict__ Wf, const float* __restrict__ Wg,
    const float* __restrict__ Wh, int k, int gn)
{
    if (gn < 32)  return Wf[k * 32 + gn];
    if (gn < 64)  return Wg[k * 32 + gn - 32];
    return Wh[k * 128 + gn - 64];
}
__device__ __forceinline__ float bsel(
    const float* __restrict__ bf, const float* __restrict__ bg,
    const float* __restrict__ bh, int gn)
{
    if (gn < 32)  return bf[gn];
    if (gn < 64)  return bg[gn - 32];
    return bh[gn - 64];
}

__global__ __launch_bounds__(256) void proj_mma(
    const float* __restrict__ x,
    const float* __restrict__ Wf, const float* __restrict__ bf,
    const float* __restrict__ Wg, const float* __restrict__ bg,
    const float* __restrict__ Wh, const float* __restrict__ bh)
{
    __shared__ uint32_t sBhi[8 * 8 * 64];
    __shared__ uint32_t sBlo[8 * 8 * 64];

    const int tid = threadIdx.x;
    const int w = tid >> 5, lane = tid & 31;
    const int gq = lane >> 2, t = lane & 3;
    const int bm = blockIdx.x * 128;
    const int bn = blockIdx.y * 64;
    const bool third = (blockIdx.y == 0);

    const int m0 = bm + w * 16 + gq;
    const float* xr0 = &x[(size_t)m0 * CH];
    const float* xr1 = xr0 + 8 * CH;

    float c[8][4];
    #pragma unroll
    for (int nb = 0; nb < 8; nb++)
        #pragma unroll
        for (int j = 0; j < 4; j++) c[nb][j] = 0.0f;

    #pragma unroll
    for (int ph = 0; ph < 2; ph++) {
        __syncthreads();
        #pragma unroll
        for (int task = tid; task < 8 * 8 * 32; task += 256) {
            int ln = task & 31, kb = (task >> 5) & 7, nb = task >> 8;
            int g = ln >> 2, tt = ln & 3;
            int gn = bn + nb * 8 + g;
            int k = (ph * 8 + kb) * 16 + 2 * tt;
            float w0 = wsel(Wf, Wg, Wh, k,     gn);
            float w1 = wsel(Wf, Wg, Wh, k + 1, gn);
            float w2 = wsel(Wf, Wg, Wh, k + 8, gn);
            float w3 = wsel(Wf, Wg, Wh, k + 9, gn);
            uint32_t h0, l0, h1, l1;
            hilo2(make_float2(w0, w1), h0, l0);
            hilo2(make_float2(w2, w3), h1, l1);
            int idx = ((nb * 8 + kb) * 32 + ln) * 2;
            sBhi[idx] = h0; sBhi[idx + 1] = h1;
            sBlo[idx] = l0; sBlo[idx + 1] = l1;
        }
        __syncthreads();

        float2 n0_ = *(const float2*)&xr0[(ph * 8) * 16 + 2 * t];
        float2 n1_ = *(const float2*)&xr1[(ph * 8) * 16 + 2 * t];
        float2 n2_ = *(const float2*)&xr0[(ph * 8) * 16 + 2 * t + 8];
        float2 n3_ = *(const float2*)&xr1[(ph * 8) * 16 + 2 * t + 8];
        #pragma unroll
        for (int kb = 0; kb < 8; kb++) {
            float2 c0 = n0_, c1 = n1_, c2 = n2_, c3 = n3_;
            if (kb < 7) {
                const int kn = (ph * 8 + kb + 1) * 16;
                n0_ = *(const float2*)&xr0[kn + 2 * t];
                n1_ = *(const float2*)&xr1[kn + 2 * t];
                n2_ = *(const float2*)&xr0[kn + 2 * t + 8];
                n3_ = *(const float2*)&xr1[kn + 2 * t + 8];
            }
            uint32_t Ahi[4], Alo[4];
            hilo2(c0, Ahi[0], Alo[0]);
            hilo2(c1, Ahi[1], Alo[1]);
            hilo2(c2, Ahi[2], Alo[2]);
            hilo2(c3, Ahi[3], Alo[3]);
            #pragma unroll
            for (int nb = 0; nb < 8; nb++) {
                uint2 bh2 = *(const uint2*)&sBhi[((nb * 8 + kb) * 32 + lane) * 2];
                uint2 bl2 = *(const uint2*)&sBlo[((nb * 8 + kb) * 32 + lane) * 2];
                mma16816(c[nb], Ahi, bh2.x, bh2.y);
                mma16816(c[nb], Ahi, bl2.x, bl2.y);
                if (third) mma16816(c[nb], Alo, bh2.x, bh2.y);
            }
        }
    }

    #pragma unroll
    for (int nb = 0; nb < 8; nb++) {
        int gn0 = bn + nb * 8 + 2 * t;
        float b0 = bsel(bf, bg, bh, gn0);
        float b1 = bsel(bf, bg, bh, gn0 + 1);
        float v00 = c[nb][0] + b0, v01 = c[nb][1] + b1;
        float v10 = c[nb][2] + b0, v11 = c[nb][3] + b1;
        if (gn0 < 32) {            // f: hi stream only
            int p = fpos(gn0);
            uint32_t h, l;
            hilo2(make_float2(v00, v01), h, l);
            g_f16hi[(size_t)m0 * 16 + p] = h;
            hilo2(make_float2(v10, v11), h, l);
            g_f16hi[(size_t)(m0 + 8) * 16 + p] = h;
        } else if (gn0 < 64) {     // g: hi + lo streams
            int p = fpos(gn0 - 32);
            uint32_t h, l;
            hilo2(make_float2(v00, v01), h, l);
            g_g16hi[(size_t)m0 * 16 + p] = h;
            g_g16lo[(size_t)m0 * 16 + p] = l;
            hilo2(make_float2(v10, v11), h, l);
            g_g16hi[(size_t)(m0 + 8) * 16 + p] = h;
            g_g16lo[(size_t)(m0 + 8) * 16 + p] = l;
        } else {                   // h^T permuted fp16
            int dv0 = gn0 - 64;
            int bb0 = m0 >> 12, pix0 = m0 & 4095;
            int m1r = m0 + 8, bb1 = m1r >> 12, pix1 = m1r & 4095;
            int pi0 = htperm(pix0), pi1 = htperm(pix1);
            size_t r00 = ((size_t)bb0 * DV + dv0) * HW;
            size_t r01 = ((size_t)bb0 * DV + dv0 + 1) * HW;
            size_t r10 = ((size_t)bb1 * DV + dv0) * HW;
            size_t r11 = ((size_t)bb1 * DV + dv0 + 1) * HW;
            g_ht_h[r00 + pi0] = __float2half_rn(v00);
            g_ht_h[r01 + pi0] = __float2half_rn(v01);
            g_ht_h[r10 + pi1] = __float2half_rn(v10);
            g_ht_h[r11 + pi1] = __float2half_rn(v11);
        }
    }
}

// ===========================================================================
// Kernel 2: mma.sync flash attention, 2 CTAs/SM, 4-buffer pipeline (3 ahead),
// LDS.128 fragment reads. SMEM per buffer: F 4KB @0, Ht 16KB @4096.
// ===========================================================================
#define TILE_SMEM 20480
#define ATTN_SMEM (4 * TILE_SMEM)   // 81920

__global__ void __launch_bounds__(256, 2) attn_kernel()
{
    extern __shared__ __align__(16) char dsm[];

    const int tid = threadIdx.x;
    const int w = tid >> 5, lane = tid & 31;
    const int gq = lane >> 2, t = lane & 3;
    const int b = blockIdx.y, q0 = blockIdx.x * 128;
    const size_t bbase = (size_t)b * HW;
    const int qr = q0 + w * 16;
    const float L2E = 1.4426950408889634f;
    const uint32_t sbase = smem_u32(dsm);

    // ---- G A-fragments (once): one uint4 per row per stream ----
    uint32_t Ahi[2][4], Alo[2][4];
    {
        const uint32_t* gh = &g_g16hi[(bbase + qr + gq) * 16];
        const uint32_t* gl = &g_g16lo[(bbase + qr + gq) * 16];
        uint4 u;
        u = *(const uint4*)&gh[4 * t];
        Ahi[0][0] = u.x; Ahi[0][2] = u.y; Ahi[1][0] = u.z; Ahi[1][2] = u.w;
        u = *(const uint4*)&gh[8 * 16 + 4 * t];
        Ahi[0][1] = u.x; Ahi[0][3] = u.y; Ahi[1][1] = u.z; Ahi[1][3] = u.w;
        u = *(const uint4*)&gl[4 * t];
        Alo[0][0] = u.x; Alo[0][2] = u.y; Alo[1][0] = u.z; Alo[1][2] = u.w;
        u = *(const uint4*)&gl[8 * 16 + 4 * t];
        Alo[0][1] = u.x; Alo[0][3] = u.y; Alo[1][1] = u.z; Alo[1][3] = u.w;
    }

    auto stage = [&](int k0, int buf) {
        const uint32_t base = sbase + buf * TILE_SMEM;
        {   // F: 256 tasks of 16B (near-identity copy)
            int n = tid >> 2, tt = tid & 3;
            const uint32_t* gp = &g_f16hi[(bbase + k0 + n) * 16 + tt * 4];
            uint32_t dst = base + (((n >> 3) * 128) + (n & 7) * 16 + tt * 4) * 4;
            cpa16(dst, gp);
        }
        #pragma unroll
        for (int i = 0; i < 4; i++) {   // Ht: 1024 tasks of 16B
            int task = tid + 256 * i;
            int d = task >> 3, cc = (task >> 2) & 1, tt = task & 3;
            const uint32_t* gp =
                (const uint32_t*)(g_ht_h + ((size_t)b * DV + d) * HW) +
                (k0 >> 1) + cc * 16 + tt * 4;
            uint32_t dst = base + 4096 +
                (((d >> 3) * 256) + cc * 128 + ((d & 7) * 4 + tt) * 4) * 4;
            cpa16(dst, gp);
        }
        CP_COMMIT();
    };

    float O[16][4];
    #pragma unroll
    for (int i = 0; i < 16; i++)
        #pragma unroll
        for (int j = 0; j < 4; j++) O[i][j] = 0.0f;
    float m0 = -1e30f, m1 = -1e30f, l0 = 0.0f, l1 = 0.0f;

    stage(0, 0);
    stage(64, 1);
    stage(128, 2);

    for (int kt = 0; kt < 64; ++kt) {
        if (kt < 62) {
            asm volatile("cp.async.wait_group 2;" ::: "memory");
        } else if (kt == 62) {
            asm volatile("cp.async.wait_group 1;" ::: "memory");
        } else {
            asm volatile("cp.async.wait_group 0;" ::: "memory");
        }
        __syncthreads();
        if (kt + 3 < 64) stage((kt + 3) * 64, (kt + 3) & 3);

        const int buf = kt & 3;
        const uint32_t* fhi = (const uint32_t*)(dsm + buf * TILE_SMEM);
        const uint32_t* ht  = fhi + 1024;

        // ---- S = (Ghi + Glo) * Fhi, one LDS.128 per nb ----
        float S[8][4];
        float mt0 = -1e30f, mt1 = -1e30f;
        #pragma unroll
        for (int nb = 0; nb < 8; nb++) {
            float* c = S[nb];
            c[0] = c[1] = c[2] = c[3] = 0.0f;
            uint4 B4 = *(const uint4*)&fhi[nb * 128 + lane * 4];
            mma16816(c, Ahi[0], B4.x, B4.y);
            mma16816(c, Ahi[1], B4.z, B4.w);
            mma16816(c, Alo[0], B4.x, B4.y);
            mma16816(c, Alo[1], B4.z, B4.w);
            mt0 = fmaxf(mt0, fmaxf(c[0], c[1]));
            mt1 = fmaxf(mt1, fmaxf(c[2], c[3]));
        }
        mt0 = fmaxf(mt0, __shfl_xor_sync(0xffffffffu, mt0, 1));
        mt0 = fmaxf(mt0, __shfl_xor_sync(0xffffffffu, mt0, 2));
        mt1 = fmaxf(mt1, __shfl_xor_sync(0xffffffffu, mt1, 1));
        mt1 = fmaxf(mt1, __shfl_xor_sync(0xffffffffu, mt1, 2));
        const bool newmax = (mt0 > m0) | (mt1 > m1);
        float mn0 = fmaxf(m0, mt0), mn1 = fmaxf(m1, mt1);
        float corr0 = __expf(m0 - mn0), corr1 = __expf(m1 - mn1);
        m0 = mn0; m1 = mn1;
        const float nm0 = -mn0 * L2E, nm1 = -mn1 * L2E;

        // ---- p = ex2((s-m)*log2e) fp16x2; output IS the P fragment ----
        uint32_t Pa[4][4];
        float ps0 = 0.0f, ps1 = 0.0f;
        #pragma unroll
        for (int nb = 0; nb < 8; nb++) {
            float t0 = fmaf(S[nb][0], L2E, nm0);
            float t1 = fmaf(S[nb][1], L2E, nm0);
            float t2 = fmaf(S[nb][2], L2E, nm1);
            float t3 = fmaf(S[nb][3], L2E, nm1);
            uint32_t P01 = ex2_f16x2(cvt_f16x2(t0, t1));
            uint32_t P23 = ex2_f16x2(cvt_f16x2(t2, t3));
            float2 q0 = h2f2(P01);
            float2 q1 = h2f2(P23);
            ps0 += q0.x + q0.y;
            ps1 += q1.x + q1.y;
            int j = nb >> 1, hi = (nb & 1) << 1;
            Pa[j][hi + 0] = P01;
            Pa[j][hi + 1] = P23;
        }
        l0 = l0 * corr0 + ps0;
        l1 = l1 * corr1 + ps1;

        if (newmax) {
            #pragma unroll
            for (int nb = 0; nb < 16; nb++) {
                O[nb][0] *= corr0; O[nb][1] *= corr0;
                O[nb][2] *= corr1; O[nb][3] *= corr1;
            }
        }
        // ---- O += P @ Ht, two LDS.128 per nb ----
        #pragma unroll
        for (int nb = 0; nb < 16; nb++) {
            uint4 H0 = *(const uint4*)&ht[nb * 256 + lane * 4];
            uint4 H1 = *(const uint4*)&ht[nb * 256 + 128 + lane * 4];
            mma16816(O[nb], Pa[0], H0.x, H0.y);
            mma16816(O[nb], Pa[1], H0.z, H0.w);
            mma16816(O[nb], Pa[2], H1.x, H1.y);
            mma16816(O[nb], Pa[3], H1.z, H1.w);
        }
    }

    l0 += __shfl_xor_sync(0xffffffffu, l0, 1);
    l0 += __shfl_xor_sync(0xffffffffu, l0, 2);
    l1 += __shfl_xor_sync(0xffffffffu, l1, 1);
    l1 += __shfl_xor_sync(0xffffffffu, l1, 2);
    float rl0 = 1.0f / l0, rl1 = 1.0f / l1;

    float* out0 = &g_o[(bbase + qr + gq) * DV + 2 * t];
    float* out1 = &g_o[(bbase + qr + gq + 8) * DV + 2 * t];
    #pragma unroll
    for (int nb = 0; nb < 16; nb++) {
        *(float2*)&out0[nb * 8] = make_float2(O[nb][0] * rl0, O[nb][1] * rl0);
        *(float2*)&out1[nb * 8] = make_float2(O[nb][2] * rl1, O[nb][3] * rl1);
    }
}

// ===========================================================================
// Kernel 3: out = x + o@Wo + bo, single-pass fp16, A-register prefetch.
// ===========================================================================
__global__ __launch_bounds__(256) void out_mma(
    const float* __restrict__ x,
    const float* __restrict__ Wo,
    const float* __restrict__ bo,
    float* __restrict__ out)
{
    __shared__ uint32_t sBhi[8 * 8 * 64];

    const int tid = threadIdx.x;
    const int w = tid >> 5, lane = tid & 31;
    const int gq = lane >> 2, t = lane & 3;
    const int bm = blockIdx.x * 128;
    const int bn = blockIdx.y * 64;

    #pragma unroll
    for (int task = tid; task < 8 * 8 * 32; task += 256) {
        int ln = task & 31, kb = (task >> 5) & 7, nb = task >> 8;
        int g = ln >> 2, tt = ln & 3;
        int gn = bn + nb * 8 + g;
        int k = kb * 16 + 2 * tt;
        float w0 = Wo[(size_t)(k)     * CH + gn];
        float w1 = Wo[(size_t)(k + 1) * CH + gn];
        float w2 = Wo[(size_t)(k + 8) * CH + gn];
        float w3 = Wo[(size_t)(k + 9) * CH + gn];
        int idx = ((nb * 8 + kb) * 32 + ln) * 2;
        sBhi[idx]     = cvt_f16x2(w0, w1);
        sBhi[idx + 1] = cvt_f16x2(w2, w3);
    }
    __syncthreads();

    const int m0 = bm + w * 16 + gq;
    const float* ar0 = &g_o[(size_t)m0 * DV];
    const float* ar1 = ar0 + 8 * DV;

    float c[8][4];
    #pragma unroll
    for (int nb = 0; nb < 8; nb++)
        #pragma unroll
        for (int j = 0; j < 4; j++) c[nb][j] = 0.0f;

    float2 n0_ = *(const float2*)&ar0[2 * t];
    float2 n1_ = *(const float2*)&ar1[2 * t];
    float2 n2_ = *(const float2*)&ar0[2 * t + 8];
    float2 n3_ = *(const float2*)&ar1[2 * t + 8];
    #pragma unroll
    for (int kb = 0; kb < 8; kb++) {
        float2 c0 = n0_, c1 = n1_, c2 = n2_, c3 = n3_;
        if (kb < 7) {
            const int kn = (kb + 1) * 16;
            n0_ = *(const float2*)&ar0[kn + 2 * t];
            n1_ = *(const float2*)&ar1[kn + 2 * t];
            n2_ = *(const float2*)&ar0[kn + 2 * t + 8];
            n3_ = *(const float2*)&ar1[kn + 2 * t + 8];
        }
        uint32_t Ahi[4];
        Ahi[0] = cvt_f16x2(c0.x, c0.y);
        Ahi[1] = cvt_f16x2(c1.x, c1.y);
        Ahi[2] = cvt_f16x2(c2.x, c2.y);
        Ahi[3] = cvt_f16x2(c3.x, c3.y);
        #pragma unroll
        for (int nb = 0; nb < 8; nb++) {
            uint2 bh2 = *(const uint2*)&sBhi[((nb * 8 + kb) * 32 + lane) * 2];
            mma16816(c[nb], Ahi, bh2.x, bh2.y);
        }
    }

    #pragma unroll
    for (int nb = 0; nb < 8; nb++) {
        int gn0 = bn + nb * 8 + 2 * t;
        float2 bb = *(const float2*)&bo[gn0];
        float2 x0 = *(const float2*)&x[(size_t)m0 * CH + gn0];
        float2 x1 = *(const float2*)&x[(size_t)(m0 + 8) * CH + gn0];
        *(float2*)&out[(size_t)m0 * CH + gn0] =
            make_float2(x0.x + c[nb][0] + bb.x, x0.y + c[nb][1] + bb.y);
        *(float2*)&out[(size_t)(m0 + 8) * CH + gn0] =
            make_float2(x1.x + c[nb][2] + bb.x, x1.y + c[nb][3] + bb.y);
    }
}

// ===========================================================================
extern "C" void kernel_launch(void* const* d_in, const int* in_sizes, int n_in,
                              void* d_out, int out_size)
{
    const float* x  = (const float*)d_in[0];
    const float* Wf = (const float*)d_in[1];
    const float* bf = (const float*)d_in[2];
    const float* Wg = (const float*)d_in[3];
    const float* bg = (const float*)d_in[4];
    const float* Wh = (const float*)d_in[5];
    const float* bh = (const float*)d_in[6];
    const float* Wo = (const float*)d_in[7];
    const float* bo = (const float*)d_in[8];
    float* out = (float*)d_out;

    proj_mma<<<dim3(MTOT / 128, 3), 256>>>(x, Wf, bf, Wg, bg, Wh, bh);

    cudaFuncSetAttribute(attn_kernel, cudaFuncAttributeMaxDynamicSharedMemorySize,
                         ATTN_SMEM);
    attn_kernel<<<dim3(HW / 128, BATCH), 256, ATTN_SMEM>>>();

    out_mma<<<dim3(MTOT / 128, 4), 256>>>(x, Wo, bo, out);
}

// round 12
// speedup vs baseline: 43.0216x; 1.0954x over previous
#include <cuda_runtime.h>
#include <cuda_fp16.h>
#include <cstdint>

// ---------------------------------------------------------------------------
// SelfAttention_2826088481408 — GB300 sm_103a (base sm_103 PTX target)
// B=16, hw=4096, C=256, d=32, dv=128
// R12: single-pass fp16 QK (Glo dropped), l accumulated via ones-MMA,
//      proj uniformly 2-pass. LDS.128 layouts + 4-buffer pipeline from R11.
// ---------------------------------------------------------------------------

#define BATCH 16
#define HW    4096
#define CH    256
#define DK    32
#define DV    128
#define MTOT  (BATCH * HW)

__device__ __align__(16) uint32_t g_f16hi[(size_t)MTOT * 16];
__device__ __align__(16) uint32_t g_g16hi[(size_t)MTOT * 16];
__device__ __align__(16) __half g_ht_h[(size_t)BATCH * DV * HW];
__device__ float g_o[(size_t)MTOT * DV];

// ---- mma.sync m16n8k16 f16 -------------------------------------------------
__device__ __forceinline__ void mma16816(float* c, const uint32_t* a,
                                         uint32_t b0, uint32_t b1) {
    asm volatile(
        "mma.sync.aligned.m16n8k16.row.col.f32.f16.f16.f32 "
        "{%0,%1,%2,%3}, {%4,%5,%6,%7}, {%8,%9}, {%0,%1,%2,%3};"
        : "+f"(c[0]), "+f"(c[1]), "+f"(c[2]), "+f"(c[3])
        : "r"(a[0]), "r"(a[1]), "r"(a[2]), "r"(a[3]), "r"(b0), "r"(b1));
}

__device__ __forceinline__ void hilo2(float2 v, uint32_t& hi, uint32_t& lo) {
    __half hx = __float2half_rn(v.x), hy = __float2half_rn(v.y);
    float rx = v.x - __half2float(hx);
    float ry = v.y - __half2float(hy);
    __half2 h = __halves2half2(hx, hy);
    __half2 l = __floats2half2_rn(rx, ry);
    hi = *(uint32_t*)&h;
    lo = *(uint32_t*)&l;
}

__device__ __forceinline__ uint32_t cvt_f16x2(float x, float y) {
    uint32_t r;
    asm("cvt.rn.f16x2.f32 %0, %1, %2;" : "=r"(r) : "f"(y), "f"(x));
    return r;
}
__device__ __forceinline__ uint32_t ex2_f16x2(uint32_t a) {
    uint32_t r;
    asm("ex2.approx.f16x2 %0, %1;" : "=r"(r) : "r"(a));
    return r;
}

__device__ __forceinline__ uint32_t smem_u32(const void* p) {
    uint32_t a;
    asm("{ .reg .u64 t; cvta.to.shared.u64 t, %1; cvt.u32.u64 %0, t; }"
        : "=r"(a) : "l"(p));
    return a;
}
__device__ __forceinline__ void cpa16(uint32_t s, const void* g) {
    asm volatile(
        "{ .reg .u64 gp; cvta.to.global.u64 gp, %1;"
        "  cp.async.cg.shared.global [%0], [gp], 16; }"
        :: "r"(s), "l"(g) : "memory");
}
#define CP_COMMIT() asm volatile("cp.async.commit_group;" ::: "memory")

// fragment-stream position for even channel c: lane tt's 4 regs contiguous.
__device__ __forceinline__ int fpos(int c) {
    int j = c >> 1;
    return (j & 3) * 4 + (j >> 3) * 2 + ((j >> 2) & 1);
}
// permuted h^T half-index: 64-key segments, 64 halves each.
__device__ __forceinline__ int htperm(int pix) {
    int p = (pix & 63) >> 1;
    int tt = p & 3, jj = p >> 3, half = (p >> 2) & 1;
    int upos = (jj >> 1) * 16 + tt * 4 + (jj & 1) * 2 + half;
    return (pix >> 6) * 64 + upos * 2 + (pix & 1);
}

// ===========================================================================
// Kernel 1: proj GEMM, uniformly 2-pass (x hi+lo vs W hi).
// ===========================================================================
__device__ __forceinline__ float wsel(
    const float* __restrict__ Wf, const float* __restrict__ Wg,
    const float* __restrict__ Wh, int k, int gn)
{
    if (gn < 32)  return Wf[k * 32 + gn];
    if (gn < 64)  return Wg[k * 32 + gn - 32];
    return Wh[k * 128 + gn - 64];
}
__device__ __forceinline__ float bsel(
    const float* __restrict__ bf, const float* __restrict__ bg,
    const float* __restrict__ bh, int gn)
{
    if (gn < 32)  return bf[gn];
    if (gn < 64)  return bg[gn - 32];
    return bh[gn - 64];
}

__global__ __launch_bounds__(256) void proj_mma(
    const float* __restrict__ x,
    const float* __restrict__ Wf, const float* __restrict__ bf,
    const float* __restrict__ Wg, const float* __restrict__ bg,
    const float* __restrict__ Wh, const float* __restrict__ bh)
{
    __shared__ uint32_t sBhi[8 * 8 * 64];
    __shared__ uint32_t sBlo[8 * 8 * 64];

    const int tid = threadIdx.x;
    const int w = tid >> 5, lane = tid & 31;
    const int gq = lane >> 2, t = lane & 3;
    const int bm = blockIdx.x * 128;
    const int bn = blockIdx.y * 64;

    const int m0 = bm + w * 16 + gq;
    const float* xr0 = &x[(size_t)m0 * CH];
    const float* xr1 = xr0 + 8 * CH;

    float c[8][4];
    #pragma unroll
    for (int nb = 0; nb < 8; nb++)
        #pragma unroll
        for (int j = 0; j < 4; j++) c[nb][j] = 0.0f;

    #pragma unroll
    for (int ph = 0; ph < 2; ph++) {
        __syncthreads();
        #pragma unroll
        for (int task = tid; task < 8 * 8 * 32; task += 256) {
            int ln = task & 31, kb = (task >> 5) & 7, nb = task >> 8;
            int g = ln >> 2, tt = ln & 3;
            int gn = bn + nb * 8 + g;
            int k = (ph * 8 + kb) * 16 + 2 * tt;
            float w0 = wsel(Wf, Wg, Wh, k,     gn);
            float w1 = wsel(Wf, Wg, Wh, k + 1, gn);
            float w2 = wsel(Wf, Wg, Wh, k + 8, gn);
            float w3 = wsel(Wf, Wg, Wh, k + 9, gn);
            uint32_t h0, l0, h1, l1;
            hilo2(make_float2(w0, w1), h0, l0);
            hilo2(make_float2(w2, w3), h1, l1);
            int idx = ((nb * 8 + kb) * 32 + ln) * 2;
            sBhi[idx] = h0; sBhi[idx + 1] = h1;
            sBlo[idx] = l0; sBlo[idx + 1] = l1;
        }
        __syncthreads();

        float2 n0_ = *(const float2*)&xr0[(ph * 8) * 16 + 2 * t];
        float2 n1_ = *(const float2*)&xr1[(ph * 8) * 16 + 2 * t];
        float2 n2_ = *(const float2*)&xr0[(ph * 8) * 16 + 2 * t + 8];
        float2 n3_ = *(const float2*)&xr1[(ph * 8) * 16 + 2 * t + 8];
        #pragma unroll
        for (int kb = 0; kb < 8; kb++) {
            float2 c0 = n0_, c1 = n1_, c2 = n2_, c3 = n3_;
            if (kb < 7) {
                const int kn = (ph * 8 + kb + 1) * 16;
                n0_ = *(const float2*)&xr0[kn + 2 * t];
                n1_ = *(const float2*)&xr1[kn + 2 * t];
                n2_ = *(const float2*)&xr0[kn + 2 * t + 8];
                n3_ = *(const float2*)&xr1[kn + 2 * t + 8];
            }
            uint32_t Ahi[4], Alo[4];
            hilo2(c0, Ahi[0], Alo[0]);
            hilo2(c1, Ahi[1], Alo[1]);
            hilo2(c2, Ahi[2], Alo[2]);
            hilo2(c3, Ahi[3], Alo[3]);
            #pragma unroll
            for (int nb = 0; nb < 8; nb++) {
                uint2 bh2 = *(const uint2*)&sBhi[((nb * 8 + kb) * 32 + lane) * 2];
                uint2 bl2 = *(const uint2*)&sBlo[((nb * 8 + kb) * 32 + lane) * 2];
                mma16816(c[nb], Ahi, bh2.x, bh2.y);
                mma16816(c[nb], Ahi, bl2.x, bl2.y);
            }
        }
    }

    #pragma unroll
    for (int nb = 0; nb < 8; nb++) {
        int gn0 = bn + nb * 8 + 2 * t;
        float b0 = bsel(bf, bg, bh, gn0);
        float b1 = bsel(bf, bg, bh, gn0 + 1);
        float v00 = c[nb][0] + b0, v01 = c[nb][1] + b1;
        float v10 = c[nb][2] + b0, v11 = c[nb][3] + b1;
        if (gn0 < 32) {            // f stream (fp16 hi)
            int p = fpos(gn0);
            uint32_t h, l;
            hilo2(make_float2(v00, v01), h, l);
            g_f16hi[(size_t)m0 * 16 + p] = h;
            hilo2(make_float2(v10, v11), h, l);
            g_f16hi[(size_t)(m0 + 8) * 16 + p] = h;
        } else if (gn0 < 64) {     // g stream (fp16 hi)
            int p = fpos(gn0 - 32);
            uint32_t h, l;
            hilo2(make_float2(v00, v01), h, l);
            g_g16hi[(size_t)m0 * 16 + p] = h;
            hilo2(make_float2(v10, v11), h, l);
            g_g16hi[(size_t)(m0 + 8) * 16 + p] = h;
        } else {                   // h^T permuted fp16
            int dv0 = gn0 - 64;
            int bb0 = m0 >> 12, pix0 = m0 & 4095;
            int m1r = m0 + 8, bb1 = m1r >> 12, pix1 = m1r & 4095;
            int pi0 = htperm(pix0), pi1 = htperm(pix1);
            size_t r00 = ((size_t)bb0 * DV + dv0) * HW;
            size_t r01 = ((size_t)bb0 * DV + dv0 + 1) * HW;
            size_t r10 = ((size_t)bb1 * DV + dv0) * HW;
            size_t r11 = ((size_t)bb1 * DV + dv0 + 1) * HW;
            g_ht_h[r00 + pi0] = __float2half_rn(v00);
            g_ht_h[r01 + pi0] = __float2half_rn(v01);
            g_ht_h[r10 + pi1] = __float2half_rn(v10);
            g_ht_h[r11 + pi1] = __float2half_rn(v11);
        }
    }
}

// ===========================================================================
// Kernel 2: mma.sync flash attention, 2 CTAs/SM, 4-buffer pipeline,
// single-pass fp16 QK, l via ones-MMA.
// ===========================================================================
#define TILE_SMEM 20480
#define ATTN_SMEM (4 * TILE_SMEM)   // 81920

__global__ void __launch_bounds__(256, 2) attn_kernel()
{
    extern __shared__ __align__(16) char dsm[];

    const int tid = threadIdx.x;
    const int w = tid >> 5, lane = tid & 31;
    const int gq = lane >> 2, t = lane & 3;
    const int b = blockIdx.y, q0 = blockIdx.x * 128;
    const size_t bbase = (size_t)b * HW;
    const int qr = q0 + w * 16;
    const float L2E = 1.4426950408889634f;
    const uint32_t sbase = smem_u32(dsm);
    const uint32_t ONES = 0x3C003C00u;   // (1.0h, 1.0h)

    // ---- G A-fragments (hi only, once) ----
    uint32_t Ahi[2][4];
    {
        const uint32_t* gh = &g_g16hi[(bbase + qr + gq) * 16];
        uint4 u;
        u = *(const uint4*)&gh[4 * t];
        Ahi[0][0] = u.x; Ahi[0][2] = u.y; Ahi[1][0] = u.z; Ahi[1][2] = u.w;
        u = *(const uint4*)&gh[8 * 16 + 4 * t];
        Ahi[0][1] = u.x; Ahi[0][3] = u.y; Ahi[1][1] = u.z; Ahi[1][3] = u.w;
    }

    auto stage = [&](int k0, int buf) {
        const uint32_t base = sbase + buf * TILE_SMEM;
        {   // F: 256 tasks of 16B
            int n = tid >> 2, tt = tid & 3;
            const uint32_t* gp = &g_f16hi[(bbase + k0 + n) * 16 + tt * 4];
            uint32_t dst = base + (((n >> 3) * 128) + (n & 7) * 16 + tt * 4) * 4;
            cpa16(dst, gp);
        }
        #pragma unroll
        for (int i = 0; i < 4; i++) {   // Ht: 1024 tasks of 16B
            int task = tid + 256 * i;
            int d = task >> 3, cc = (task >> 2) & 1, tt = task & 3;
            const uint32_t* gp =
                (const uint32_t*)(g_ht_h + ((size_t)b * DV + d) * HW) +
                (k0 >> 1) + cc * 16 + tt * 4;
            uint32_t dst = base + 4096 +
                (((d >> 3) * 256) + cc * 128 + ((d & 7) * 4 + tt) * 4) * 4;
            cpa16(dst, gp);
        }
        CP_COMMIT();
    };

    float O[16][4];
    #pragma unroll
    for (int i = 0; i < 16; i++)
        #pragma unroll
        for (int j = 0; j < 4; j++) O[i][j] = 0.0f;
    float Lc[4] = {0.0f, 0.0f, 0.0f, 0.0f};
    float m0 = -1e30f, m1 = -1e30f;

    stage(0, 0);
    stage(64, 1);
    stage(128, 2);

    for (int kt = 0; kt < 64; ++kt) {
        if (kt < 62) {
            asm volatile("cp.async.wait_group 2;" ::: "memory");
        } else if (kt == 62) {
            asm volatile("cp.async.wait_group 1;" ::: "memory");
        } else {
            asm volatile("cp.async.wait_group 0;" ::: "memory");
        }
        __syncthreads();
        if (kt + 3 < 64) stage((kt + 3) * 64, (kt + 3) & 3);

        const int buf = kt & 3;
        const uint32_t* fhi = (const uint32_t*)(dsm + buf * TILE_SMEM);
        const uint32_t* ht  = fhi + 1024;

        // ---- S = Ghi * Fhi (single pass), one LDS.128 per nb ----
        float S[8][4];
        float mt0 = -1e30f, mt1 = -1e30f;
        #pragma unroll
        for (int nb = 0; nb < 8; nb++) {
            float* c = S[nb];
            c[0] = c[1] = c[2] = c[3] = 0.0f;
            uint4 B4 = *(const uint4*)&fhi[nb * 128 + lane * 4];
            mma16816(c, Ahi[0], B4.x, B4.y);
            mma16816(c, Ahi[1], B4.z, B4.w);
            mt0 = fmaxf(mt0, fmaxf(c[0], c[1]));
            mt1 = fmaxf(mt1, fmaxf(c[2], c[3]));
        }
        mt0 = fmaxf(mt0, __shfl_xor_sync(0xffffffffu, mt0, 1));
        mt0 = fmaxf(mt0, __shfl_xor_sync(0xffffffffu, mt0, 2));
        mt1 = fmaxf(mt1, __shfl_xor_sync(0xffffffffu, mt1, 1));
        mt1 = fmaxf(mt1, __shfl_xor_sync(0xffffffffu, mt1, 2));
        const bool newmax = (mt0 > m0) | (mt1 > m1);
        float mn0 = fmaxf(m0, mt0), mn1 = fmaxf(m1, mt1);
        float corr0 = __expf(m0 - mn0), corr1 = __expf(m1 - mn1);
        m0 = mn0; m1 = mn1;
        const float nm0 = -mn0 * L2E, nm1 = -mn1 * L2E;

        // ---- p = ex2((s-m)*log2e) fp16x2; output IS the P fragment ----
        uint32_t Pa[4][4];
        #pragma unroll
        for (int nb = 0; nb < 8; nb++) {
            float t0 = fmaf(S[nb][0], L2E, nm0);
            float t1 = fmaf(S[nb][1], L2E, nm0);
            float t2 = fmaf(S[nb][2], L2E, nm1);
            float t3 = fmaf(S[nb][3], L2E, nm1);
            int j = nb >> 1, hi = (nb & 1) << 1;
            Pa[j][hi + 0] = ex2_f16x2(cvt_f16x2(t0, t1));
            Pa[j][hi + 1] = ex2_f16x2(cvt_f16x2(t2, t3));
        }

        if (newmax) {
            #pragma unroll
            for (int nb = 0; nb < 16; nb++) {
                O[nb][0] *= corr0; O[nb][1] *= corr0;
                O[nb][2] *= corr1; O[nb][3] *= corr1;
            }
            Lc[0] *= corr0; Lc[1] *= corr0;
            Lc[2] *= corr1; Lc[3] *= corr1;
        }
        // ---- l += P @ ones (4 mma, no LDS) ----
        #pragma unroll
        for (int j = 0; j < 4; j++) mma16816(Lc, Pa[j], ONES, ONES);

        // ---- O += P @ Ht, two LDS.128 per nb ----
        #pragma unroll
        for (int nb = 0; nb < 16; nb++) {
            uint4 H0 = *(const uint4*)&ht[nb * 256 + lane * 4];
            uint4 H1 = *(const uint4*)&ht[nb * 256 + 128 + lane * 4];
            mma16816(O[nb], Pa[0], H0.x, H0.y);
            mma16816(O[nb], Pa[1], H0.z, H0.w);
            mma16816(O[nb], Pa[2], H1.x, H1.y);
            mma16816(O[nb], Pa[3], H1.z, H1.w);
        }
    }

    // all columns of Lc are the row sum -> no shuffles needed
    float rl0 = 1.0f / Lc[0], rl1 = 1.0f / Lc[2];

    float* out0 = &g_o[(bbase + qr + gq) * DV + 2 * t];
    float* out1 = &g_o[(bbase + qr + gq + 8) * DV + 2 * t];
    #pragma unroll
    for (int nb = 0; nb < 16; nb++) {
        *(float2*)&out0[nb * 8] = make_float2(O[nb][0] * rl0, O[nb][1] * rl0);
        *(float2*)&out1[nb * 8] = make_float2(O[nb][2] * rl1, O[nb][3] * rl1);
    }
}

// ===========================================================================
// Kernel 3: out = x + o@Wo + bo, single-pass fp16, A-register prefetch.
// ===========================================================================
__global__ __launch_bounds__(256) void out_mma(
    const float* __restrict__ x,
    const float* __restrict__ Wo,
    const float* __restrict__ bo,
    float* __restrict__ out)
{
    __shared__ uint32_t sBhi[8 * 8 * 64];

    const int tid = threadIdx.x;
    const int w = tid >> 5, lane = tid & 31;
    const int gq = lane >> 2, t = lane & 3;
    const int bm = blockIdx.x * 128;
    const int bn = blockIdx.y * 64;

    #pragma unroll
    for (int task = tid; task < 8 * 8 * 32; task += 256) {
        int ln = task & 31, kb = (task >> 5) & 7, nb = task >> 8;
        int g = ln >> 2, tt = ln & 3;
        int gn = bn + nb * 8 + g;
        int k = kb * 16 + 2 * tt;
        float w0 = Wo[(size_t)(k)     * CH + gn];
        float w1 = Wo[(size_t)(k + 1) * CH + gn];
        float w2 = Wo[(size_t)(k + 8) * CH + gn];
        float w3 = Wo[(size_t)(k + 9) * CH + gn];
        int idx = ((nb * 8 + kb) * 32 + ln) * 2;
        sBhi[idx]     = cvt_f16x2(w0, w1);
        sBhi[idx + 1] = cvt_f16x2(w2, w3);
    }
    __syncthreads();

    const int m0 = bm + w * 16 + gq;
    const float* ar0 = &g_o[(size_t)m0 * DV];
    const float* ar1 = ar0 + 8 * DV;

    float c[8][4];
    #pragma unroll
    for (int nb = 0; nb < 8; nb++)
        #pragma unroll
        for (int j = 0; j < 4; j++) c[nb][j] = 0.0f;

    float2 n0_ = *(const float2*)&ar0[2 * t];
    float2 n1_ = *(const float2*)&ar1[2 * t];
    float2 n2_ = *(const float2*)&ar0[2 * t + 8];
    float2 n3_ = *(const float2*)&ar1[2 * t + 8];
    #pragma unroll
    for (int kb = 0; kb < 8; kb++) {
        float2 c0 = n0_, c1 = n1_, c2 = n2_, c3 = n3_;
        if (kb < 7) {
            const int kn = (kb + 1) * 16;
            n0_ = *(const float2*)&ar0[kn + 2 * t];
            n1_ = *(const float2*)&ar1[kn + 2 * t];
            n2_ = *(const float2*)&ar0[kn + 2 * t + 8];
            n3_ = *(const float2*)&ar1[kn + 2 * t + 8];
        }
        uint32_t Ahi[4];
        Ahi[0] = cvt_f16x2(c0.x, c0.y);
        Ahi[1] = cvt_f16x2(c1.x, c1.y);
        Ahi[2] = cvt_f16x2(c2.x, c2.y);
        Ahi[3] = cvt_f16x2(c3.x, c3.y);
        #pragma unroll
        for (int nb = 0; nb < 8; nb++) {
            uint2 bh2 = *(const uint2*)&sBhi[((nb * 8 + kb) * 32 + lane) * 2];
            mma16816(c[nb], Ahi, bh2.x, bh2.y);
        }
    }

    #pragma unroll
    for (int nb = 0; nb < 8; nb++) {
        int gn0 = bn + nb * 8 + 2 * t;
        float2 bb = *(const float2*)&bo[gn0];
        float2 x0 = *(const float2*)&x[(size_t)m0 * CH + gn0];
        float2 x1 = *(const float2*)&x[(size_t)(m0 + 8) * CH + gn0];
        *(float2*)&out[(size_t)m0 * CH + gn0] =
            make_float2(x0.x + c[nb][0] + bb.x, x0.y + c[nb][1] + bb.y);
        *(float2*)&out[(size_t)(m0 + 8) * CH + gn0] =
            make_float2(x1.x + c[nb][2] + bb.x, x1.y + c[nb][3] + bb.y);
    }
}

// ===========================================================================
extern "C" void kernel_launch(void* const* d_in, const int* in_sizes, int n_in,
                              void* d_out, int out_size)
{
    const float* x  = (const float*)d_in[0];
    const float* Wf = (const float*)d_in[1];
    const float* bf = (const float*)d_in[2];
    const float* Wg = (const float*)d_in[3];
    const float* bg = (const float*)d_in[4];
    const float* Wh = (const float*)d_in[5];
    const float* bh = (const float*)d_in[6];
    const float* Wo = (const float*)d_in[7];
    const float* bo = (const float*)d_in[8];
    float* out = (float*)d_out;

    proj_mma<<<dim3(MTOT / 128, 3), 256>>>(x, Wf, bf, Wg, bg, Wh, bh);

    cudaFuncSetAttribute(attn_kernel, cudaFuncAttributeMaxDynamicSharedMemorySize,
                         ATTN_SMEM);
    attn_kernel<<<dim3(HW / 128, BATCH), 256, ATTN_SMEM>>>();

    out_mma<<<dim3(MTOT / 128, 4), 256>>>(x, Wo, bo, out);
}

// round 14
// speedup vs baseline: 45.2605x; 1.0520x over previous
#include <cuda_runtime.h>
#include <cuda_fp16.h>
#include <cstdint>

// ---------------------------------------------------------------------------
// SelfAttention_2826088481408 — GB300 sm_103a (base sm_103 PTX target)
// B=16, hw=4096, C=256, d=32, dv=128
// R14: R13 with prep_w item-count fix (12288 proj items, not 24576).
//      Weights pre-converted once; proj/out staging = identity cp.async.
// ---------------------------------------------------------------------------

#define BATCH 16
#define HW    4096
#define CH    256
#define DK    32
#define DV    128
#define MTOT  (BATCH * HW)

__device__ __align__(16) uint32_t g_f16hi[(size_t)MTOT * 16];
__device__ __align__(16) uint32_t g_g16hi[(size_t)MTOT * 16];
__device__ __align__(16) __half g_ht_h[(size_t)BATCH * DV * HW];
__device__ float g_o[(size_t)MTOT * DV];

// pre-converted weights, fragment-major:
// g_wp_*: [y(3)][ph(2)] blocks of 4096 words  (proj W hi/lo)
// g_wo_hi: [bn(4)] blocks of 4096 words       (Wo hi)
__device__ __align__(16) uint32_t g_wp_hi[3 * 2 * 4096];
__device__ __align__(16) uint32_t g_wp_lo[3 * 2 * 4096];
__device__ __align__(16) uint32_t g_wo_hi[4 * 4096];

// ---- mma.sync m16n8k16 f16 -------------------------------------------------
__device__ __forceinline__ void mma16816(float* c, const uint32_t* a,
                                         uint32_t b0, uint32_t b1) {
    asm volatile(
        "mma.sync.aligned.m16n8k16.row.col.f32.f16.f16.f32 "
        "{%0,%1,%2,%3}, {%4,%5,%6,%7}, {%8,%9}, {%0,%1,%2,%3};"
        : "+f"(c[0]), "+f"(c[1]), "+f"(c[2]), "+f"(c[3])
        : "r"(a[0]), "r"(a[1]), "r"(a[2]), "r"(a[3]), "r"(b0), "r"(b1));
}

__device__ __forceinline__ void hilo2(float2 v, uint32_t& hi, uint32_t& lo) {
    __half hx = __float2half_rn(v.x), hy = __float2half_rn(v.y);
    float rx = v.x - __half2float(hx);
    float ry = v.y - __half2float(hy);
    __half2 h = __halves2half2(hx, hy);
    __half2 l = __floats2half2_rn(rx, ry);
    hi = *(uint32_t*)&h;
    lo = *(uint32_t*)&l;
}

__device__ __forceinline__ uint32_t cvt_f16x2(float x, float y) {
    uint32_t r;
    asm("cvt.rn.f16x2.f32 %0, %1, %2;" : "=r"(r) : "f"(y), "f"(x));
    return r;
}
__device__ __forceinline__ uint32_t ex2_f16x2(uint32_t a) {
    uint32_t r;
    asm("ex2.approx.f16x2 %0, %1;" : "=r"(r) : "r"(a));
    return r;
}

__device__ __forceinline__ uint32_t smem_u32(const void* p) {
    uint32_t a;
    asm("{ .reg .u64 t; cvta.to.shared.u64 t, %1; cvt.u32.u64 %0, t; }"
        : "=r"(a) : "l"(p));
    return a;
}
__device__ __forceinline__ void cpa16(uint32_t s, const void* g) {
    asm volatile(
        "{ .reg .u64 gp; cvta.to.global.u64 gp, %1;"
        "  cp.async.cg.shared.global [%0], [gp], 16; }"
        :: "r"(s), "l"(g) : "memory");
}
#define CP_COMMIT() asm volatile("cp.async.commit_group;" ::: "memory")

__device__ __forceinline__ int fpos(int c) {
    int j = c >> 1;
    return (j & 3) * 4 + (j >> 3) * 2 + ((j >> 2) & 1);
}
__device__ __forceinline__ int htperm(int pix) {
    int p = (pix & 63) >> 1;
    int tt = p & 3, jj = p >> 3, half = (p >> 2) & 1;
    int upos = (jj >> 1) * 16 + tt * 4 + (jj & 1) * 2 + half;
    return (pix >> 6) * 64 + upos * 2 + (pix & 1);
}

__device__ __forceinline__ float wsel(
    const float* __restrict__ Wf, const float* __restrict__ Wg,
    const float* __restrict__ Wh, int k, int gn)
{
    if (gn < 32)  return Wf[k * 32 + gn];
    if (gn < 64)  return Wg[k * 32 + gn - 32];
    return Wh[k * 128 + gn - 64];
}
__device__ __forceinline__ float bsel(
    const float* __restrict__ bf, const float* __restrict__ bg,
    const float* __restrict__ bh, int gn)
{
    if (gn < 32)  return bf[gn];
    if (gn < 64)  return bg[gn - 32];
    return bh[gn - 64];
}

// ===========================================================================
// Kernel 0: prep_w — convert weights once into fragment-major fp16 streams.
// items [0, 12288): proj W (hi+lo, 2 words each);
// items [12288, 20480): Wo (hi, 2 words each). Launch with 80*256 = 20480.
// ===========================================================================
__global__ __launch_bounds__(256) void prep_w(
    const float* __restrict__ Wf, const float* __restrict__ Wg,
    const float* __restrict__ Wh, const float* __restrict__ Wo)
{
    int idx = blockIdx.x * 256 + threadIdx.x;
    if (idx < 12288) {
        int ln = idx & 31, kb = (idx >> 5) & 7, nb = (idx >> 8) & 7;
        int ph = (idx >> 11) & 1, y = idx >> 12;      // y in {0,1,2}
        int gn = y * 64 + nb * 8 + (ln >> 2);
        int k = (ph * 8 + kb) * 16 + 2 * (ln & 3);
        float w0 = wsel(Wf, Wg, Wh, k,     gn);
        float w1 = wsel(Wf, Wg, Wh, k + 1, gn);
        float w2 = wsel(Wf, Wg, Wh, k + 8, gn);
        float w3 = wsel(Wf, Wg, Wh, k + 9, gn);
        uint32_t h0, l0, h1, l1;
        hilo2(make_float2(w0, w1), h0, l0);
        hilo2(make_float2(w2, w3), h1, l1);
        g_wp_hi[idx * 2] = h0; g_wp_hi[idx * 2 + 1] = h1;
        g_wp_lo[idx * 2] = l0; g_wp_lo[idx * 2 + 1] = l1;
    } else {
        int i2 = idx - 12288;                          // i2 in [0, 8192)
        int ln = i2 & 31, kb = (i2 >> 5) & 7, nb = (i2 >> 8) & 7, bn4 = i2 >> 11;
        int gn = bn4 * 64 + nb * 8 + (ln >> 2);
        int k = kb * 16 + 2 * (ln & 3);
        float w0 = Wo[(size_t)(k)     * CH + gn];
        float w1 = Wo[(size_t)(k + 1) * CH + gn];
        float w2 = Wo[(size_t)(k + 8) * CH + gn];
        float w3 = Wo[(size_t)(k + 9) * CH + gn];
        g_wo_hi[i2 * 2]     = cvt_f16x2(w0, w1);
        g_wo_hi[i2 * 2 + 1] = cvt_f16x2(w2, w3);
    }
}

// ===========================================================================
// Kernel 1: proj GEMM, 2-pass; weight staging = identity cp.async copies.
// ===========================================================================
__global__ __launch_bounds__(256) void proj_mma(
    const float* __restrict__ x,
    const float* __restrict__ bf, const float* __restrict__ bg,
    const float* __restrict__ bh)
{
    __shared__ __align__(16) uint32_t sBhi[8 * 8 * 64];
    __shared__ __align__(16) uint32_t sBlo[8 * 8 * 64];

    const int tid = threadIdx.x;
    const int w = tid >> 5, lane = tid & 31;
    const int gq = lane >> 2, t = lane & 3;
    const int bm = blockIdx.x * 128;
    const int bn = blockIdx.y * 64;

    const int m0 = bm + w * 16 + gq;
    const float* xr0 = &x[(size_t)m0 * CH];
    const float* xr1 = xr0 + 8 * CH;
    const uint32_t sBhiA = smem_u32(sBhi);
    const uint32_t sBloA = smem_u32(sBlo);

    float c[8][4];
    #pragma unroll
    for (int nb = 0; nb < 8; nb++)
        #pragma unroll
        for (int j = 0; j < 4; j++) c[nb][j] = 0.0f;

    #pragma unroll
    for (int ph = 0; ph < 2; ph++) {
        __syncthreads();
        {
            const uint32_t* srcHi = &g_wp_hi[(blockIdx.y * 2 + ph) * 4096];
            const uint32_t* srcLo = &g_wp_lo[(blockIdx.y * 2 + ph) * 4096];
            #pragma unroll
            for (int i = 0; i < 4; i++) {
                int tsk = tid + 256 * i;
                cpa16(sBhiA + tsk * 16, srcHi + tsk * 4);
                cpa16(sBloA + tsk * 16, srcLo + tsk * 4);
            }
            CP_COMMIT();
            asm volatile("cp.async.wait_group 0;" ::: "memory");
        }
        __syncthreads();

        float2 n0_ = *(const float2*)&xr0[(ph * 8) * 16 + 2 * t];
        float2 n1_ = *(const float2*)&xr1[(ph * 8) * 16 + 2 * t];
        float2 n2_ = *(const float2*)&xr0[(ph * 8) * 16 + 2 * t + 8];
        float2 n3_ = *(const float2*)&xr1[(ph * 8) * 16 + 2 * t + 8];
        #pragma unroll
        for (int kb = 0; kb < 8; kb++) {
            float2 c0 = n0_, c1 = n1_, c2 = n2_, c3 = n3_;
            if (kb < 7) {
                const int kn = (ph * 8 + kb + 1) * 16;
                n0_ = *(const float2*)&xr0[kn + 2 * t];
                n1_ = *(const float2*)&xr1[kn + 2 * t];
                n2_ = *(const float2*)&xr0[kn + 2 * t + 8];
                n3_ = *(const float2*)&xr1[kn + 2 * t + 8];
            }
            uint32_t Ahi[4], Alo[4];
            hilo2(c0, Ahi[0], Alo[0]);
            hilo2(c1, Ahi[1], Alo[1]);
            hilo2(c2, Ahi[2], Alo[2]);
            hilo2(c3, Ahi[3], Alo[3]);
            #pragma unroll
            for (int nb = 0; nb < 8; nb++) {
                uint2 bh2 = *(const uint2*)&sBhi[((nb * 8 + kb) * 32 + lane) * 2];
                uint2 bl2 = *(const uint2*)&sBlo[((nb * 8 + kb) * 32 + lane) * 2];
                mma16816(c[nb], Ahi, bh2.x, bh2.y);
                mma16816(c[nb], Ahi, bl2.x, bl2.y);
            }
        }
    }

    #pragma unroll
    for (int nb = 0; nb < 8; nb++) {
        int gn0 = bn + nb * 8 + 2 * t;
        float b0 = bsel(bf, bg, bh, gn0);
        float b1 = bsel(bf, bg, bh, gn0 + 1);
        float v00 = c[nb][0] + b0, v01 = c[nb][1] + b1;
        float v10 = c[nb][2] + b0, v11 = c[nb][3] + b1;
        if (gn0 < 32) {            // f stream (fp16 hi)
            int p = fpos(gn0);
            uint32_t h, l;
            hilo2(make_float2(v00, v01), h, l);
            g_f16hi[(size_t)m0 * 16 + p] = h;
            hilo2(make_float2(v10, v11), h, l);
            g_f16hi[(size_t)(m0 + 8) * 16 + p] = h;
        } else if (gn0 < 64) {     // g stream (fp16 hi)
            int p = fpos(gn0 - 32);
            uint32_t h, l;
            hilo2(make_float2(v00, v01), h, l);
            g_g16hi[(size_t)m0 * 16 + p] = h;
            hilo2(make_float2(v10, v11), h, l);
            g_g16hi[(size_t)(m0 + 8) * 16 + p] = h;
        } else {                   // h^T permuted fp16
            int dv0 = gn0 - 64;
            int bb0 = m0 >> 12, pix0 = m0 & 4095;
            int m1r = m0 + 8, bb1 = m1r >> 12, pix1 = m1r & 4095;
            int pi0 = htperm(pix0), pi1 = htperm(pix1);
            size_t r00 = ((size_t)bb0 * DV + dv0) * HW;
            size_t r01 = ((size_t)bb0 * DV + dv0 + 1) * HW;
            size_t r10 = ((size_t)bb1 * DV + dv0) * HW;
            size_t r11 = ((size_t)bb1 * DV + dv0 + 1) * HW;
            g_ht_h[r00 + pi0] = __float2half_rn(v00);
            g_ht_h[r01 + pi0] = __float2half_rn(v01);
            g_ht_h[r10 + pi1] = __float2half_rn(v10);
            g_ht_h[r11 + pi1] = __float2half_rn(v11);
        }
    }
}

// ===========================================================================
// Kernel 2: mma.sync flash attention (unchanged from R12).
// ===========================================================================
#define TILE_SMEM 20480
#define ATTN_SMEM (4 * TILE_SMEM)   // 81920

__global__ void __launch_bounds__(256, 2) attn_kernel()
{
    extern __shared__ __align__(16) char dsm[];

    const int tid = threadIdx.x;
    const int w = tid >> 5, lane = tid & 31;
    const int gq = lane >> 2, t = lane & 3;
    const int b = blockIdx.y, q0 = blockIdx.x * 128;
    const size_t bbase = (size_t)b * HW;
    const int qr = q0 + w * 16;
    const float L2E = 1.4426950408889634f;
    const uint32_t sbase = smem_u32(dsm);
    const uint32_t ONES = 0x3C003C00u;

    uint32_t Ahi[2][4];
    {
        const uint32_t* gh = &g_g16hi[(bbase + qr + gq) * 16];
        uint4 u;
        u = *(const uint4*)&gh[4 * t];
        Ahi[0][0] = u.x; Ahi[0][2] = u.y; Ahi[1][0] = u.z; Ahi[1][2] = u.w;
        u = *(const uint4*)&gh[8 * 16 + 4 * t];
        Ahi[0][1] = u.x; Ahi[0][3] = u.y; Ahi[1][1] = u.z; Ahi[1][3] = u.w;
    }

    auto stage = [&](int k0, int buf) {
        const uint32_t base = sbase + buf * TILE_SMEM;
        {
            int n = tid >> 2, tt = tid & 3;
            const uint32_t* gp = &g_f16hi[(bbase + k0 + n) * 16 + tt * 4];
            uint32_t dst = base + (((n >> 3) * 128) + (n & 7) * 16 + tt * 4) * 4;
            cpa16(dst, gp);
        }
        #pragma unroll
        for (int i = 0; i < 4; i++) {
            int task = tid + 256 * i;
            int d = task >> 3, cc = (task >> 2) & 1, tt = task & 3;
            const uint32_t* gp =
                (const uint32_t*)(g_ht_h + ((size_t)b * DV + d) * HW) +
                (k0 >> 1) + cc * 16 + tt * 4;
            uint32_t dst = base + 4096 +
                (((d >> 3) * 256) + cc * 128 + ((d & 7) * 4 + tt) * 4) * 4;
            cpa16(dst, gp);
        }
        CP_COMMIT();
    };

    float O[16][4];
    #pragma unroll
    for (int i = 0; i < 16; i++)
        #pragma unroll
        for (int j = 0; j < 4; j++) O[i][j] = 0.0f;
    float Lc[4] = {0.0f, 0.0f, 0.0f, 0.0f};
    float m0 = -1e30f, m1 = -1e30f;

    stage(0, 0);
    stage(64, 1);
    stage(128, 2);

    for (int kt = 0; kt < 64; ++kt) {
        if (kt < 62) {
            asm volatile("cp.async.wait_group 2;" ::: "memory");
        } else if (kt == 62) {
            asm volatile("cp.async.wait_group 1;" ::: "memory");
        } else {
            asm volatile("cp.async.wait_group 0;" ::: "memory");
        }
        __syncthreads();
        if (kt + 3 < 64) stage((kt + 3) * 64, (kt + 3) & 3);

        const int buf = kt & 3;
        const uint32_t* fhi = (const uint32_t*)(dsm + buf * TILE_SMEM);
        const uint32_t* ht  = fhi + 1024;

        float S[8][4];
        float mt0 = -1e30f, mt1 = -1e30f;
        #pragma unroll
        for (int nb = 0; nb < 8; nb++) {
            float* c = S[nb];
            c[0] = c[1] = c[2] = c[3] = 0.0f;
            uint4 B4 = *(const uint4*)&fhi[nb * 128 + lane * 4];
            mma16816(c, Ahi[0], B4.x, B4.y);
            mma16816(c, Ahi[1], B4.z, B4.w);
            mt0 = fmaxf(mt0, fmaxf(c[0], c[1]));
            mt1 = fmaxf(mt1, fmaxf(c[2], c[3]));
        }
        mt0 = fmaxf(mt0, __shfl_xor_sync(0xffffffffu, mt0, 1));
        mt0 = fmaxf(mt0, __shfl_xor_sync(0xffffffffu, mt0, 2));
        mt1 = fmaxf(mt1, __shfl_xor_sync(0xffffffffu, mt1, 1));
        mt1 = fmaxf(mt1, __shfl_xor_sync(0xffffffffu, mt1, 2));
        const bool newmax = (mt0 > m0) | (mt1 > m1);
        float mn0 = fmaxf(m0, mt0), mn1 = fmaxf(m1, mt1);
        float corr0 = __expf(m0 - mn0), corr1 = __expf(m1 - mn1);
        m0 = mn0; m1 = mn1;
        const float nm0 = -mn0 * L2E, nm1 = -mn1 * L2E;

        uint32_t Pa[4][4];
        #pragma unroll
        for (int nb = 0; nb < 8; nb++) {
            float t0 = fmaf(S[nb][0], L2E, nm0);
            float t1 = fmaf(S[nb][1], L2E, nm0);
            float t2 = fmaf(S[nb][2], L2E, nm1);
            float t3 = fmaf(S[nb][3], L2E, nm1);
            int j = nb >> 1, hi = (nb & 1) << 1;
            Pa[j][hi + 0] = ex2_f16x2(cvt_f16x2(t0, t1));
            Pa[j][hi + 1] = ex2_f16x2(cvt_f16x2(t2, t3));
        }

        if (newmax) {
            #pragma unroll
            for (int nb = 0; nb < 16; nb++) {
                O[nb][0] *= corr0; O[nb][1] *= corr0;
                O[nb][2] *= corr1; O[nb][3] *= corr1;
            }
            Lc[0] *= corr0; Lc[1] *= corr0;
            Lc[2] *= corr1; Lc[3] *= corr1;
        }
        #pragma unroll
        for (int j = 0; j < 4; j++) mma16816(Lc, Pa[j], ONES, ONES);

        #pragma unroll
        for (int nb = 0; nb < 16; nb++) {
            uint4 H0 = *(const uint4*)&ht[nb * 256 + lane * 4];
            uint4 H1 = *(const uint4*)&ht[nb * 256 + 128 + lane * 4];
            mma16816(O[nb], Pa[0], H0.x, H0.y);
            mma16816(O[nb], Pa[1], H0.z, H0.w);
            mma16816(O[nb], Pa[2], H1.x, H1.y);
            mma16816(O[nb], Pa[3], H1.z, H1.w);
        }
    }

    float rl0 = 1.0f / Lc[0], rl1 = 1.0f / Lc[2];

    float* out0 = &g_o[(bbase + qr + gq) * DV + 2 * t];
    float* out1 = &g_o[(bbase + qr + gq + 8) * DV + 2 * t];
    #pragma unroll
    for (int nb = 0; nb < 16; nb++) {
        *(float2*)&out0[nb * 8] = make_float2(O[nb][0] * rl0, O[nb][1] * rl0);
        *(float2*)&out1[nb * 8] = make_float2(O[nb][2] * rl1, O[nb][3] * rl1);
    }
}

// ===========================================================================
// Kernel 3: out = x + o@Wo + bo; Wo staging = identity cp.async copy.
// ===========================================================================
__global__ __launch_bounds__(256) void out_mma(
    const float* __restrict__ x,
    const float* __restrict__ bo,
    float* __restrict__ out)
{
    __shared__ __align__(16) uint32_t sBhi[8 * 8 * 64];

    const int tid = threadIdx.x;
    const int w = tid >> 5, lane = tid & 31;
    const int gq = lane >> 2, t = lane & 3;
    const int bm = blockIdx.x * 128;
    const int bn = blockIdx.y * 64;
    const uint32_t sBhiA = smem_u32(sBhi);

    {
        const uint32_t* src = &g_wo_hi[blockIdx.y * 4096];
        #pragma unroll
        for (int i = 0; i < 4; i++) {
            int tsk = tid + 256 * i;
            cpa16(sBhiA + tsk * 16, src + tsk * 4);
        }
        CP_COMMIT();
        asm volatile("cp.async.wait_group 0;" ::: "memory");
    }
    __syncthreads();

    const int m0 = bm + w * 16 + gq;
    const float* ar0 = &g_o[(size_t)m0 * DV];
    const float* ar1 = ar0 + 8 * DV;

    float c[8][4];
    #pragma unroll
    for (int nb = 0; nb < 8; nb++)
        #pragma unroll
        for (int j = 0; j < 4; j++) c[nb][j] = 0.0f;

    float2 n0_ = *(const float2*)&ar0[2 * t];
    float2 n1_ = *(const float2*)&ar1[2 * t];
    float2 n2_ = *(const float2*)&ar0[2 * t + 8];
    float2 n3_ = *(const float2*)&ar1[2 * t + 8];
    #pragma unroll
    for (int kb = 0; kb < 8; kb++) {
        float2 c0 = n0_, c1 = n1_, c2 = n2_, c3 = n3_;
        if (kb < 7) {
            const int kn = (kb + 1) * 16;
            n0_ = *(const float2*)&ar0[kn + 2 * t];
            n1_ = *(const float2*)&ar1[kn + 2 * t];
            n2_ = *(const float2*)&ar0[kn + 2 * t + 8];
            n3_ = *(const float2*)&ar1[kn + 2 * t + 8];
        }
        uint32_t Ahi[4];
        Ahi[0] = cvt_f16x2(c0.x, c0.y);
        Ahi[1] = cvt_f16x2(c1.x, c1.y);
        Ahi[2] = cvt_f16x2(c2.x, c2.y);
        Ahi[3] = cvt_f16x2(c3.x, c3.y);
        #pragma unroll
        for (int nb = 0; nb < 8; nb++) {
            uint2 bh2 = *(const uint2*)&sBhi[((nb * 8 + kb) * 32 + lane) * 2];
            mma16816(c[nb], Ahi, bh2.x, bh2.y);
        }
    }

    #pragma unroll
    for (int nb = 0; nb < 8; nb++) {
        int gn0 = bn + nb * 8 + 2 * t;
        float2 bb = *(const float2*)&bo[gn0];
        float2 x0 = *(const float2*)&x[(size_t)m0 * CH + gn0];
        float2 x1 = *(const float2*)&x[(size_t)(m0 + 8) * CH + gn0];
        *(float2*)&out[(size_t)m0 * CH + gn0] =
            make_float2(x0.x + c[nb][0] + bb.x, x0.y + c[nb][1] + bb.y);
        *(float2*)&out[(size_t)(m0 + 8) * CH + gn0] =
            make_float2(x1.x + c[nb][2] + bb.x, x1.y + c[nb][3] + bb.y);
    }
}

// ===========================================================================
extern "C" void kernel_launch(void* const* d_in, const int* in_sizes, int n_in,
                              void* d_out, int out_size)
{
    const float* x  = (const float*)d_in[0];
    const float* Wf = (const float*)d_in[1];
    const float* bf = (const float*)d_in[2];
    const float* Wg = (const float*)d_in[3];
    const float* bg = (const float*)d_in[4];
    const float* Wh = (const float*)d_in[5];
    const float* bh = (const float*)d_in[6];
    const float* Wo = (const float*)d_in[7];
    const float* bo = (const float*)d_in[8];
    float* out = (float*)d_out;

    prep_w<<<80, 256>>>(Wf, Wg, Wh, Wo);
    proj_mma<<<dim3(MTOT / 128, 3), 256>>>(x, bf, bg, bh);

    cudaFuncSetAttribute(attn_kernel, cudaFuncAttributeMaxDynamicSharedMemorySize,
                         ATTN_SMEM);
    attn_kernel<<<dim3(HW / 128, BATCH), 256, ATTN_SMEM>>>();

    out_mma<<<dim3(MTOT / 128, 4), 256>>>(x, bo, out);
}

// round 15
// speedup vs baseline: 48.1668x; 1.0642x over previous
#include <cuda_runtime.h>
#include <cuda_fp16.h>
#include <cstdint>

// ---------------------------------------------------------------------------
// SelfAttention_2826088481408 — GB300 sm_103a (base sm_103 PTX target)
// B=16, hw=4096, C=256, d=32, dv=128
// R15: output GEMM fused into attn epilogue (g_o eliminated); proj at
//      3 CTAs/SM. Weights pre-converted by prep_w (R14).
// ---------------------------------------------------------------------------

#define BATCH 16
#define HW    4096
#define CH    256
#define DK    32
#define DV    128
#define MTOT  (BATCH * HW)

__device__ __align__(16) uint32_t g_f16hi[(size_t)MTOT * 16];
__device__ __align__(16) uint32_t g_g16hi[(size_t)MTOT * 16];
__device__ __align__(16) __half g_ht_h[(size_t)BATCH * DV * HW];

// pre-converted weights, fragment-major:
__device__ __align__(16) uint32_t g_wp_hi[3 * 2 * 4096];
__device__ __align__(16) uint32_t g_wp_lo[3 * 2 * 4096];
__device__ __align__(16) uint32_t g_wo_hi[4 * 4096];

// ---- mma.sync m16n8k16 f16 -------------------------------------------------
__device__ __forceinline__ void mma16816(float* c, const uint32_t* a,
                                         uint32_t b0, uint32_t b1) {
    asm volatile(
        "mma.sync.aligned.m16n8k16.row.col.f32.f16.f16.f32 "
        "{%0,%1,%2,%3}, {%4,%5,%6,%7}, {%8,%9}, {%0,%1,%2,%3};"
        : "+f"(c[0]), "+f"(c[1]), "+f"(c[2]), "+f"(c[3])
        : "r"(a[0]), "r"(a[1]), "r"(a[2]), "r"(a[3]), "r"(b0), "r"(b1));
}

__device__ __forceinline__ void hilo2(float2 v, uint32_t& hi, uint32_t& lo) {
    __half hx = __float2half_rn(v.x), hy = __float2half_rn(v.y);
    float rx = v.x - __half2float(hx);
    float ry = v.y - __half2float(hy);
    __half2 h = __halves2half2(hx, hy);
    __half2 l = __floats2half2_rn(rx, ry);
    hi = *(uint32_t*)&h;
    lo = *(uint32_t*)&l;
}

__device__ __forceinline__ uint32_t cvt_f16x2(float x, float y) {
    uint32_t r;
    asm("cvt.rn.f16x2.f32 %0, %1, %2;" : "=r"(r) : "f"(y), "f"(x));
    return r;
}
__device__ __forceinline__ uint32_t ex2_f16x2(uint32_t a) {
    uint32_t r;
    asm("ex2.approx.f16x2 %0, %1;" : "=r"(r) : "r"(a));
    return r;
}

__device__ __forceinline__ uint32_t smem_u32(const void* p) {
    uint32_t a;
    asm("{ .reg .u64 t; cvta.to.shared.u64 t, %1; cvt.u32.u64 %0, t; }"
        : "=r"(a) : "l"(p));
    return a;
}
__device__ __forceinline__ void cpa16(uint32_t s, const void* g) {
    asm volatile(
        "{ .reg .u64 gp; cvta.to.global.u64 gp, %1;"
        "  cp.async.cg.shared.global [%0], [gp], 16; }"
        :: "r"(s), "l"(g) : "memory");
}
#define CP_COMMIT() asm volatile("cp.async.commit_group;" ::: "memory")

__device__ __forceinline__ int fpos(int c) {
    int j = c >> 1;
    return (j & 3) * 4 + (j >> 3) * 2 + ((j >> 2) & 1);
}
__device__ __forceinline__ int htperm(int pix) {
    int p = (pix & 63) >> 1;
    int tt = p & 3, jj = p >> 3, half = (p >> 2) & 1;
    int upos = (jj >> 1) * 16 + tt * 4 + (jj & 1) * 2 + half;
    return (pix >> 6) * 64 + upos * 2 + (pix & 1);
}

__device__ __forceinline__ float wsel(
    const float* __restrict__ Wf, const float* __restrict__ Wg,
    const float* __restrict__ Wh, int k, int gn)
{
    if (gn < 32)  return Wf[k * 32 + gn];
    if (gn < 64)  return Wg[k * 32 + gn - 32];
    return Wh[k * 128 + gn - 64];
}
__device__ __forceinline__ float bsel(
    const float* __restrict__ bf, const float* __restrict__ bg,
    const float* __restrict__ bh, int gn)
{
    if (gn < 32)  return bf[gn];
    if (gn < 64)  return bg[gn - 32];
    return bh[gn - 64];
}

// ===========================================================================
// Kernel 0: prep_w — weights -> fragment-major fp16 streams. 80*256 threads.
// ===========================================================================
__global__ __launch_bounds__(256) void prep_w(
    const float* __restrict__ Wf, const float* __restrict__ Wg,
    const float* __restrict__ Wh, const float* __restrict__ Wo)
{
    int idx = blockIdx.x * 256 + threadIdx.x;
    if (idx < 12288) {
        int ln = idx & 31, kb = (idx >> 5) & 7, nb = (idx >> 8) & 7;
        int ph = (idx >> 11) & 1, y = idx >> 12;
        int gn = y * 64 + nb * 8 + (ln >> 2);
        int k = (ph * 8 + kb) * 16 + 2 * (ln & 3);
        float w0 = wsel(Wf, Wg, Wh, k,     gn);
        float w1 = wsel(Wf, Wg, Wh, k + 1, gn);
        float w2 = wsel(Wf, Wg, Wh, k + 8, gn);
        float w3 = wsel(Wf, Wg, Wh, k + 9, gn);
        uint32_t h0, l0, h1, l1;
        hilo2(make_float2(w0, w1), h0, l0);
        hilo2(make_float2(w2, w3), h1, l1);
        g_wp_hi[idx * 2] = h0; g_wp_hi[idx * 2 + 1] = h1;
        g_wp_lo[idx * 2] = l0; g_wp_lo[idx * 2 + 1] = l1;
    } else {
        int i2 = idx - 12288;
        int ln = i2 & 31, kb = (i2 >> 5) & 7, nb = (i2 >> 8) & 7, bn4 = i2 >> 11;
        int gn = bn4 * 64 + nb * 8 + (ln >> 2);
        int k = kb * 16 + 2 * (ln & 3);
        float w0 = Wo[(size_t)(k)     * CH + gn];
        float w1 = Wo[(size_t)(k + 1) * CH + gn];
        float w2 = Wo[(size_t)(k + 8) * CH + gn];
        float w3 = Wo[(size_t)(k + 9) * CH + gn];
        g_wo_hi[i2 * 2]     = cvt_f16x2(w0, w1);
        g_wo_hi[i2 * 2 + 1] = cvt_f16x2(w2, w3);
    }
}

// ===========================================================================
// Kernel 1: proj GEMM, 2-pass; identity cp.async weight staging; 3 CTAs/SM.
// ===========================================================================
__global__ void __launch_bounds__(256, 3) proj_mma(
    const float* __restrict__ x,
    const float* __restrict__ bf, const float* __restrict__ bg,
    const float* __restrict__ bh)
{
    __shared__ __align__(16) uint32_t sBhi[8 * 8 * 64];
    __shared__ __align__(16) uint32_t sBlo[8 * 8 * 64];

    const int tid = threadIdx.x;
    const int w = tid >> 5, lane = tid & 31;
    const int gq = lane >> 2, t = lane & 3;
    const int bm = blockIdx.x * 128;
    const int bn = blockIdx.y * 64;

    const int m0 = bm + w * 16 + gq;
    const float* xr0 = &x[(size_t)m0 * CH];
    const float* xr1 = xr0 + 8 * CH;
    const uint32_t sBhiA = smem_u32(sBhi);
    const uint32_t sBloA = smem_u32(sBlo);

    float c[8][4];
    #pragma unroll
    for (int nb = 0; nb < 8; nb++)
        #pragma unroll
        for (int j = 0; j < 4; j++) c[nb][j] = 0.0f;

    #pragma unroll
    for (int ph = 0; ph < 2; ph++) {
        __syncthreads();
        {
            const uint32_t* srcHi = &g_wp_hi[(blockIdx.y * 2 + ph) * 4096];
            const uint32_t* srcLo = &g_wp_lo[(blockIdx.y * 2 + ph) * 4096];
            #pragma unroll
            for (int i = 0; i < 4; i++) {
                int tsk = tid + 256 * i;
                cpa16(sBhiA + tsk * 16, srcHi + tsk * 4);
                cpa16(sBloA + tsk * 16, srcLo + tsk * 4);
            }
            CP_COMMIT();
            asm volatile("cp.async.wait_group 0;" ::: "memory");
        }
        __syncthreads();

        float2 n0_ = *(const float2*)&xr0[(ph * 8) * 16 + 2 * t];
        float2 n1_ = *(const float2*)&xr1[(ph * 8) * 16 + 2 * t];
        float2 n2_ = *(const float2*)&xr0[(ph * 8) * 16 + 2 * t + 8];
        float2 n3_ = *(const float2*)&xr1[(ph * 8) * 16 + 2 * t + 8];
        #pragma unroll
        for (int kb = 0; kb < 8; kb++) {
            float2 c0 = n0_, c1 = n1_, c2 = n2_, c3 = n3_;
            if (kb < 7) {
                const int kn = (ph * 8 + kb + 1) * 16;
                n0_ = *(const float2*)&xr0[kn + 2 * t];
                n1_ = *(const float2*)&xr1[kn + 2 * t];
                n2_ = *(const float2*)&xr0[kn + 2 * t + 8];
                n3_ = *(const float2*)&xr1[kn + 2 * t + 8];
            }
            uint32_t Ahi[4], Alo[4];
            hilo2(c0, Ahi[0], Alo[0]);
            hilo2(c1, Ahi[1], Alo[1]);
            hilo2(c2, Ahi[2], Alo[2]);
            hilo2(c3, Ahi[3], Alo[3]);
            #pragma unroll
            for (int nb = 0; nb < 8; nb++) {
                uint2 bh2 = *(const uint2*)&sBhi[((nb * 8 + kb) * 32 + lane) * 2];
                uint2 bl2 = *(const uint2*)&sBlo[((nb * 8 + kb) * 32 + lane) * 2];
                mma16816(c[nb], Ahi, bh2.x, bh2.y);
                mma16816(c[nb], Ahi, bl2.x, bl2.y);
            }
        }
    }

    #pragma unroll
    for (int nb = 0; nb < 8; nb++) {
        int gn0 = bn + nb * 8 + 2 * t;
        float b0 = bsel(bf, bg, bh, gn0);
        float b1 = bsel(bf, bg, bh, gn0 + 1);
        float v00 = c[nb][0] + b0, v01 = c[nb][1] + b1;
        float v10 = c[nb][2] + b0, v11 = c[nb][3] + b1;
        if (gn0 < 32) {            // f stream (fp16 hi)
            int p = fpos(gn0);
            uint32_t h, l;
            hilo2(make_float2(v00, v01), h, l);
            g_f16hi[(size_t)m0 * 16 + p] = h;
            hilo2(make_float2(v10, v11), h, l);
            g_f16hi[(size_t)(m0 + 8) * 16 + p] = h;
        } else if (gn0 < 64) {     // g stream (fp16 hi)
            int p = fpos(gn0 - 32);
            uint32_t h, l;
            hilo2(make_float2(v00, v01), h, l);
            g_g16hi[(size_t)m0 * 16 + p] = h;
            hilo2(make_float2(v10, v11), h, l);
            g_g16hi[(size_t)(m0 + 8) * 16 + p] = h;
        } else {                   // h^T permuted fp16
            int dv0 = gn0 - 64;
            int bb0 = m0 >> 12, pix0 = m0 & 4095;
            int m1r = m0 + 8, bb1 = m1r >> 12, pix1 = m1r & 4095;
            int pi0 = htperm(pix0), pi1 = htperm(pix1);
            size_t r00 = ((size_t)bb0 * DV + dv0) * HW;
            size_t r01 = ((size_t)bb0 * DV + dv0 + 1) * HW;
            size_t r10 = ((size_t)bb1 * DV + dv0) * HW;
            size_t r11 = ((size_t)bb1 * DV + dv0 + 1) * HW;
            g_ht_h[r00 + pi0] = __float2half_rn(v00);
            g_ht_h[r01 + pi0] = __float2half_rn(v01);
            g_ht_h[r10 + pi1] = __float2half_rn(v10);
            g_ht_h[r11 + pi1] = __float2half_rn(v11);
        }
    }
}

// ===========================================================================
// Kernel 2: flash attention + FUSED output GEMM.
// Main loop unchanged from R12/R14. Epilogue: O -> fp16 A-fragments (in regs),
// loop bn: stage g_wo_hi block into pipeline smem, 64 HMMA/warp,
// out = x + O@Wo + bo written directly.
// ===========================================================================
#define TILE_SMEM 20480
#define ATTN_SMEM (4 * TILE_SMEM)   // 81920

__global__ void __launch_bounds__(256, 2) attn_kernel(
    const float* __restrict__ x,
    const float* __restrict__ bo,
    float* __restrict__ out)
{
    extern __shared__ __align__(16) char dsm[];

    const int tid = threadIdx.x;
    const int w = tid >> 5, lane = tid & 31;
    const int gq = lane >> 2, t = lane & 3;
    const int b = blockIdx.y, q0 = blockIdx.x * 128;
    const size_t bbase = (size_t)b * HW;
    const int qr = q0 + w * 16;
    const float L2E = 1.4426950408889634f;
    const uint32_t sbase = smem_u32(dsm);
    const uint32_t ONES = 0x3C003C00u;

    uint32_t Ahi[2][4];
    {
        const uint32_t* gh = &g_g16hi[(bbase + qr + gq) * 16];
        uint4 u;
        u = *(const uint4*)&gh[4 * t];
        Ahi[0][0] = u.x; Ahi[0][2] = u.y; Ahi[1][0] = u.z; Ahi[1][2] = u.w;
        u = *(const uint4*)&gh[8 * 16 + 4 * t];
        Ahi[0][1] = u.x; Ahi[0][3] = u.y; Ahi[1][1] = u.z; Ahi[1][3] = u.w;
    }

    auto stage = [&](int k0, int buf) {
        const uint32_t base = sbase + buf * TILE_SMEM;
        {
            int n = tid >> 2, tt = tid & 3;
            const uint32_t* gp = &g_f16hi[(bbase + k0 + n) * 16 + tt * 4];
            uint32_t dst = base + (((n >> 3) * 128) + (n & 7) * 16 + tt * 4) * 4;
            cpa16(dst, gp);
        }
        #pragma unroll
        for (int i = 0; i < 4; i++) {
            int task = tid + 256 * i;
            int d = task >> 3, cc = (task >> 2) & 1, tt = task & 3;
            const uint32_t* gp =
                (const uint32_t*)(g_ht_h + ((size_t)b * DV + d) * HW) +
                (k0 >> 1) + cc * 16 + tt * 4;
            uint32_t dst = base + 4096 +
                (((d >> 3) * 256) + cc * 128 + ((d & 7) * 4 + tt) * 4) * 4;
            cpa16(dst, gp);
        }
        CP_COMMIT();
    };

    float O[16][4];
    #pragma unroll
    for (int i = 0; i < 16; i++)
        #pragma unroll
        for (int j = 0; j < 4; j++) O[i][j] = 0.0f;
    float Lc[4] = {0.0f, 0.0f, 0.0f, 0.0f};
    float m0 = -1e30f, m1 = -1e30f;

    stage(0, 0);
    stage(64, 1);
    stage(128, 2);

    for (int kt = 0; kt < 64; ++kt) {
        if (kt < 62) {
            asm volatile("cp.async.wait_group 2;" ::: "memory");
        } else if (kt == 62) {
            asm volatile("cp.async.wait_group 1;" ::: "memory");
        } else {
            asm volatile("cp.async.wait_group 0;" ::: "memory");
        }
        __syncthreads();
        if (kt + 3 < 64) stage((kt + 3) * 64, (kt + 3) & 3);

        const int buf = kt & 3;
        const uint32_t* fhi = (const uint32_t*)(dsm + buf * TILE_SMEM);
        const uint32_t* ht  = fhi + 1024;

        float S[8][4];
        float mt0 = -1e30f, mt1 = -1e30f;
        #pragma unroll
        for (int nb = 0; nb < 8; nb++) {
            float* c = S[nb];
            c[0] = c[1] = c[2] = c[3] = 0.0f;
            uint4 B4 = *(const uint4*)&fhi[nb * 128 + lane * 4];
            mma16816(c, Ahi[0], B4.x, B4.y);
            mma16816(c, Ahi[1], B4.z, B4.w);
            mt0 = fmaxf(mt0, fmaxf(c[0], c[1]));
            mt1 = fmaxf(mt1, fmaxf(c[2], c[3]));
        }
        mt0 = fmaxf(mt0, __shfl_xor_sync(0xffffffffu, mt0, 1));
        mt0 = fmaxf(mt0, __shfl_xor_sync(0xffffffffu, mt0, 2));
        mt1 = fmaxf(mt1, __shfl_xor_sync(0xffffffffu, mt1, 1));
        mt1 = fmaxf(mt1, __shfl_xor_sync(0xffffffffu, mt1, 2));
        const bool newmax = (mt0 > m0) | (mt1 > m1);
        float mn0 = fmaxf(m0, mt0), mn1 = fmaxf(m1, mt1);
        float corr0 = __expf(m0 - mn0), corr1 = __expf(m1 - mn1);
        m0 = mn0; m1 = mn1;
        const float nm0 = -mn0 * L2E, nm1 = -mn1 * L2E;

        uint32_t Pa[4][4];
        #pragma unroll
        for (int nb = 0; nb < 8; nb++) {
            float t0 = fmaf(S[nb][0], L2E, nm0);
            float t1 = fmaf(S[nb][1], L2E, nm0);
            float t2 = fmaf(S[nb][2], L2E, nm1);
            float t3 = fmaf(S[nb][3], L2E, nm1);
            int j = nb >> 1, hi = (nb & 1) << 1;
            Pa[j][hi + 0] = ex2_f16x2(cvt_f16x2(t0, t1));
            Pa[j][hi + 1] = ex2_f16x2(cvt_f16x2(t2, t3));
        }

        if (newmax) {
            #pragma unroll
            for (int nb = 0; nb < 16; nb++) {
                O[nb][0] *= corr0; O[nb][1] *= corr0;
                O[nb][2] *= corr1; O[nb][3] *= corr1;
            }
            Lc[0] *= corr0; Lc[1] *= corr0;
            Lc[2] *= corr1; Lc[3] *= corr1;
        }
        #pragma unroll
        for (int j = 0; j < 4; j++) mma16816(Lc, Pa[j], ONES, ONES);

        #pragma unroll
        for (int nb = 0; nb < 16; nb++) {
            uint4 H0 = *(const uint4*)&ht[nb * 256 + lane * 4];
            uint4 H1 = *(const uint4*)&ht[nb * 256 + 128 + lane * 4];
            mma16816(O[nb], Pa[0], H0.x, H0.y);
            mma16816(O[nb], Pa[1], H0.z, H0.w);
            mma16816(O[nb], Pa[2], H1.x, H1.y);
            mma16816(O[nb], Pa[3], H1.z, H1.w);
        }
    }

    // ---- fused output GEMM: out = x + (O/l) @ Wo + bo ----
    float rl0 = 1.0f / Lc[0], rl1 = 1.0f / Lc[2];

    // O -> fp16 A-fragments (8 k-blocks of 16 dv-channels each)
    uint32_t Af[8][4];
    #pragma unroll
    for (int kb = 0; kb < 8; kb++) {
        Af[kb][0] = cvt_f16x2(O[2 * kb][0] * rl0,     O[2 * kb][1] * rl0);
        Af[kb][1] = cvt_f16x2(O[2 * kb][2] * rl1,     O[2 * kb][3] * rl1);
        Af[kb][2] = cvt_f16x2(O[2 * kb + 1][0] * rl0, O[2 * kb + 1][1] * rl0);
        Af[kb][3] = cvt_f16x2(O[2 * kb + 1][2] * rl1, O[2 * kb + 1][3] * rl1);
    }

    const uint32_t* sW = (const uint32_t*)dsm;
    const size_t row0 = bbase + qr + gq;
    #pragma unroll 1
    for (int bn = 0; bn < 4; ++bn) {
        __syncthreads();   // previous consumers of dsm done
        #pragma unroll
        for (int i = 0; i < 4; i++) {
            int tsk = tid + 256 * i;
            cpa16(sbase + tsk * 16, &g_wo_hi[bn * 4096 + tsk * 4]);
        }
        CP_COMMIT();
        asm volatile("cp.async.wait_group 0;" ::: "memory");
        __syncthreads();

        #pragma unroll
        for (int nb = 0; nb < 8; nb++) {
            float c[4] = {0.f, 0.f, 0.f, 0.f};
            #pragma unroll
            for (int kb = 0; kb < 8; kb++) {
                uint2 bb = *(const uint2*)&sW[((nb * 8 + kb) * 32 + lane) * 2];
                mma16816(c, Af[kb], bb.x, bb.y);
            }
            int gn0 = bn * 64 + nb * 8 + 2 * t;
            float2 bv = *(const float2*)&bo[gn0];
            float2 x0 = *(const float2*)&x[row0 * CH + gn0];
            float2 x1 = *(const float2*)&x[(row0 + 8) * CH + gn0];
            *(float2*)&out[row0 * CH + gn0] =
                make_float2(x0.x + c[0] + bv.x, x0.y + c[1] + bv.y);
            *(float2*)&out[(row0 + 8) * CH + gn0] =
                make_float2(x1.x + c[2] + bv.x, x1.y + c[3] + bv.y);
        }
    }
}

// ===========================================================================
extern "C" void kernel_launch(void* const* d_in, const int* in_sizes, int n_in,
                              void* d_out, int out_size)
{
    const float* x  = (const float*)d_in[0];
    const float* Wf = (const float*)d_in[1];
    const float* bf = (const float*)d_in[2];
    const float* Wg = (const float*)d_in[3];
    const float* bg = (const float*)d_in[4];
    const float* Wh = (const float*)d_in[5];
    const float* bh = (const float*)d_in[6];
    const float* Wo = (const float*)d_in[7];
    const float* bo = (const float*)d_in[8];
    float* out = (float*)d_out;

    prep_w<<<80, 256>>>(Wf, Wg, Wh, Wo);
    proj_mma<<<dim3(MTOT / 128, 3), 256>>>(x, bf, bg, bh);

    cudaFuncSetAttribute(attn_kernel, cudaFuncAttributeMaxDynamicSharedMemorySize,
                         ATTN_SMEM);
    attn_kernel<<<dim3(HW / 128, BATCH), 256, ATTN_SMEM>>>(x, bo, out);
}

// round 16
// speedup vs baseline: 49.3758x; 1.0251x over previous
#include <cuda_runtime.h>
#include <cuda_fp16.h>
#include <cstdint>

// ---------------------------------------------------------------------------
// SelfAttention_2826088481408 — GB300 sm_103a (base sm_103 PTX target)
// B=16, hw=4096, C=256, d=32, dv=128
// R16: single-shot Wo staging in attn epilogue (1 barrier), proj weights
//      staged once in 64KB dynamic smem (no mid barriers), warp-uniform
//      newmax rescale. All changes numerically identity vs R15.
// ---------------------------------------------------------------------------

#define BATCH 16
#define HW    4096
#define CH    256
#define DK    32
#define DV    128
#define MTOT  (BATCH * HW)

__device__ __align__(16) uint32_t g_f16hi[(size_t)MTOT * 16];
__device__ __align__(16) uint32_t g_g16hi[(size_t)MTOT * 16];
__device__ __align__(16) __half g_ht_h[(size_t)BATCH * DV * HW];

// pre-converted weights, fragment-major:
__device__ __align__(16) uint32_t g_wp_hi[3 * 2 * 4096];
__device__ __align__(16) uint32_t g_wp_lo[3 * 2 * 4096];
__device__ __align__(16) uint32_t g_wo_hi[4 * 4096];

// ---- mma.sync m16n8k16 f16 -------------------------------------------------
__device__ __forceinline__ void mma16816(float* c, const uint32_t* a,
                                         uint32_t b0, uint32_t b1) {
    asm volatile(
        "mma.sync.aligned.m16n8k16.row.col.f32.f16.f16.f32 "
        "{%0,%1,%2,%3}, {%4,%5,%6,%7}, {%8,%9}, {%0,%1,%2,%3};"
        : "+f"(c[0]), "+f"(c[1]), "+f"(c[2]), "+f"(c[3])
        : "r"(a[0]), "r"(a[1]), "r"(a[2]), "r"(a[3]), "r"(b0), "r"(b1));
}

__device__ __forceinline__ void hilo2(float2 v, uint32_t& hi, uint32_t& lo) {
    __half hx = __float2half_rn(v.x), hy = __float2half_rn(v.y);
    float rx = v.x - __half2float(hx);
    float ry = v.y - __half2float(hy);
    __half2 h = __halves2half2(hx, hy);
    __half2 l = __floats2half2_rn(rx, ry);
    hi = *(uint32_t*)&h;
    lo = *(uint32_t*)&l;
}

__device__ __forceinline__ uint32_t cvt_f16x2(float x, float y) {
    uint32_t r;
    asm("cvt.rn.f16x2.f32 %0, %1, %2;" : "=r"(r) : "f"(y), "f"(x));
    return r;
}
__device__ __forceinline__ uint32_t ex2_f16x2(uint32_t a) {
    uint32_t r;
    asm("ex2.approx.f16x2 %0, %1;" : "=r"(r) : "r"(a));
    return r;
}

__device__ __forceinline__ uint32_t smem_u32(const void* p) {
    uint32_t a;
    asm("{ .reg .u64 t; cvta.to.shared.u64 t, %1; cvt.u32.u64 %0, t; }"
        : "=r"(a) : "l"(p));
    return a;
}
__device__ __forceinline__ void cpa16(uint32_t s, const void* g) {
    asm volatile(
        "{ .reg .u64 gp; cvta.to.global.u64 gp, %1;"
        "  cp.async.cg.shared.global [%0], [gp], 16; }"
        :: "r"(s), "l"(g) : "memory");
}
#define CP_COMMIT() asm volatile("cp.async.commit_group;" ::: "memory")

__device__ __forceinline__ int fpos(int c) {
    int j = c >> 1;
    return (j & 3) * 4 + (j >> 3) * 2 + ((j >> 2) & 1);
}
__device__ __forceinline__ int htperm(int pix) {
    int p = (pix & 63) >> 1;
    int tt = p & 3, jj = p >> 3, half = (p >> 2) & 1;
    int upos = (jj >> 1) * 16 + tt * 4 + (jj & 1) * 2 + half;
    return (pix >> 6) * 64 + upos * 2 + (pix & 1);
}

__device__ __forceinline__ float wsel(
    const float* __restrict__ Wf, const float* __restrict__ Wg,
    const float* __restrict__ Wh, int k, int gn)
{
    if (gn < 32)  return Wf[k * 32 + gn];
    if (gn < 64)  return Wg[k * 32 + gn - 32];
    return Wh[k * 128 + gn - 64];
}
__device__ __forceinline__ float bsel(
    const float* __restrict__ bf, const float* __restrict__ bg,
    const float* __restrict__ bh, int gn)
{
    if (gn < 32)  return bf[gn];
    if (gn < 64)  return bg[gn - 32];
    return bh[gn - 64];
}

// ===========================================================================
// Kernel 0: prep_w — weights -> fragment-major fp16 streams. 80*256 threads.
// ===========================================================================
__global__ __launch_bounds__(256) void prep_w(
    const float* __restrict__ Wf, const float* __restrict__ Wg,
    const float* __restrict__ Wh, const float* __restrict__ Wo)
{
    int idx = blockIdx.x * 256 + threadIdx.x;
    if (idx < 12288) {
        int ln = idx & 31, kb = (idx >> 5) & 7, nb = (idx >> 8) & 7;
        int ph = (idx >> 11) & 1, y = idx >> 12;
        int gn = y * 64 + nb * 8 + (ln >> 2);
        int k = (ph * 8 + kb) * 16 + 2 * (ln & 3);
        float w0 = wsel(Wf, Wg, Wh, k,     gn);
        float w1 = wsel(Wf, Wg, Wh, k + 1, gn);
        float w2 = wsel(Wf, Wg, Wh, k + 8, gn);
        float w3 = wsel(Wf, Wg, Wh, k + 9, gn);
        uint32_t h0, l0, h1, l1;
        hilo2(make_float2(w0, w1), h0, l0);
        hilo2(make_float2(w2, w3), h1, l1);
        g_wp_hi[idx * 2] = h0; g_wp_hi[idx * 2 + 1] = h1;
        g_wp_lo[idx * 2] = l0; g_wp_lo[idx * 2 + 1] = l1;
    } else {
        int i2 = idx - 12288;
        int ln = i2 & 31, kb = (i2 >> 5) & 7, nb = (i2 >> 8) & 7, bn4 = i2 >> 11;
        int gn = bn4 * 64 + nb * 8 + (ln >> 2);
        int k = kb * 16 + 2 * (ln & 3);
        float w0 = Wo[(size_t)(k)     * CH + gn];
        float w1 = Wo[(size_t)(k + 1) * CH + gn];
        float w2 = Wo[(size_t)(k + 8) * CH + gn];
        float w3 = Wo[(size_t)(k + 9) * CH + gn];
        g_wo_hi[i2 * 2]     = cvt_f16x2(w0, w1);
        g_wo_hi[i2 * 2 + 1] = cvt_f16x2(w2, w3);
    }
}

// ===========================================================================
// Kernel 1: proj GEMM, 2-pass; ALL weights staged once into 64KB dynamic
// smem (no mid-kernel barriers); 3 CTAs/SM.
// psm layout: [ph][hi 4096 words | lo 4096 words]
// ===========================================================================
#define PROJ_SMEM 65536

__global__ void __launch_bounds__(256, 3) proj_mma(
    const float* __restrict__ x,
    const float* __restrict__ bf, const float* __restrict__ bg,
    const float* __restrict__ bh)
{
    extern __shared__ __align__(16) uint32_t psm[];

    const int tid = threadIdx.x;
    const int w = tid >> 5, lane = tid & 31;
    const int gq = lane >> 2, t = lane & 3;
    const int bm = blockIdx.x * 128;
    const int bn = blockIdx.y * 64;

    const int m0 = bm + w * 16 + gq;
    const float* xr0 = &x[(size_t)m0 * CH];
    const float* xr1 = xr0 + 8 * CH;
    const uint32_t psmA = smem_u32(psm);

    // stage both phases' hi+lo weight blocks (identity copies, 64KB total)
    {
        const uint32_t* srcHi = &g_wp_hi[blockIdx.y * 2 * 4096];
        const uint32_t* srcLo = &g_wp_lo[blockIdx.y * 2 * 4096];
        #pragma unroll
        for (int i = 0; i < 8; i++) {       // 2048 hi tasks of 16B
            int tsk = tid + 256 * i;
            int ph = tsk >> 10, r = tsk & 1023;
            cpa16(psmA + (ph * 8192 + r * 4) * 4, srcHi + tsk * 4);
            cpa16(psmA + (ph * 8192 + 4096 + r * 4) * 4, srcLo + tsk * 4);
        }
        CP_COMMIT();
        asm volatile("cp.async.wait_group 0;" ::: "memory");
    }
    __syncthreads();

    float c[8][4];
    #pragma unroll
    for (int nb = 0; nb < 8; nb++)
        #pragma unroll
        for (int j = 0; j < 4; j++) c[nb][j] = 0.0f;

    #pragma unroll
    for (int ph = 0; ph < 2; ph++) {
        const uint32_t* sBhi = &psm[ph * 8192];
        const uint32_t* sBlo = &psm[ph * 8192 + 4096];

        float2 n0_ = *(const float2*)&xr0[(ph * 8) * 16 + 2 * t];
        float2 n1_ = *(const float2*)&xr1[(ph * 8) * 16 + 2 * t];
        float2 n2_ = *(const float2*)&xr0[(ph * 8) * 16 + 2 * t + 8];
        float2 n3_ = *(const float2*)&xr1[(ph * 8) * 16 + 2 * t + 8];
        #pragma unroll
        for (int kb = 0; kb < 8; kb++) {
            float2 c0 = n0_, c1 = n1_, c2 = n2_, c3 = n3_;
            if (kb < 7) {
                const int kn = (ph * 8 + kb + 1) * 16;
                n0_ = *(const float2*)&xr0[kn + 2 * t];
                n1_ = *(const float2*)&xr1[kn + 2 * t];
                n2_ = *(const float2*)&xr0[kn + 2 * t + 8];
                n3_ = *(const float2*)&xr1[kn + 2 * t + 8];
            }
            uint32_t Ahi[4], Alo[4];
            hilo2(c0, Ahi[0], Alo[0]);
            hilo2(c1, Ahi[1], Alo[1]);
            hilo2(c2, Ahi[2], Alo[2]);
            hilo2(c3, Ahi[3], Alo[3]);
            #pragma unroll
            for (int nb = 0; nb < 8; nb++) {
                uint2 bh2 = *(const uint2*)&sBhi[((nb * 8 + kb) * 32 + lane) * 2];
                uint2 bl2 = *(const uint2*)&sBlo[((nb * 8 + kb) * 32 + lane) * 2];
                mma16816(c[nb], Ahi, bh2.x, bh2.y);
                mma16816(c[nb], Ahi, bl2.x, bl2.y);
            }
        }
    }

    #pragma unroll
    for (int nb = 0; nb < 8; nb++) {
        int gn0 = bn + nb * 8 + 2 * t;
        float b0 = bsel(bf, bg, bh, gn0);
        float b1 = bsel(bf, bg, bh, gn0 + 1);
        float v00 = c[nb][0] + b0, v01 = c[nb][1] + b1;
        float v10 = c[nb][2] + b0, v11 = c[nb][3] + b1;
        if (gn0 < 32) {            // f stream (fp16 hi)
            int p = fpos(gn0);
            uint32_t h, l;
            hilo2(make_float2(v00, v01), h, l);
            g_f16hi[(size_t)m0 * 16 + p] = h;
            hilo2(make_float2(v10, v11), h, l);
            g_f16hi[(size_t)(m0 + 8) * 16 + p] = h;
        } else if (gn0 < 64) {     // g stream (fp16 hi)
            int p = fpos(gn0 - 32);
            uint32_t h, l;
            hilo2(make_float2(v00, v01), h, l);
            g_g16hi[(size_t)m0 * 16 + p] = h;
            hilo2(make_float2(v10, v11), h, l);
            g_g16hi[(size_t)(m0 + 8) * 16 + p] = h;
        } else {                   // h^T permuted fp16
            int dv0 = gn0 - 64;
            int bb0 = m0 >> 12, pix0 = m0 & 4095;
            int m1r = m0 + 8, bb1 = m1r >> 12, pix1 = m1r & 4095;
            int pi0 = htperm(pix0), pi1 = htperm(pix1);
            size_t r00 = ((size_t)bb0 * DV + dv0) * HW;
            size_t r01 = ((size_t)bb0 * DV + dv0 + 1) * HW;
            size_t r10 = ((size_t)bb1 * DV + dv0) * HW;
            size_t r11 = ((size_t)bb1 * DV + dv0 + 1) * HW;
            g_ht_h[r00 + pi0] = __float2half_rn(v00);
            g_ht_h[r01 + pi0] = __float2half_rn(v01);
            g_ht_h[r10 + pi1] = __float2half_rn(v10);
            g_ht_h[r11 + pi1] = __float2half_rn(v11);
        }
    }
}

// ===========================================================================
// Kernel 2: flash attention + fused output GEMM.
// Epilogue: ALL of g_wo_hi (64KB) staged once; single barrier; 4 bn passes
// of pure mma + store. Warp-uniform newmax rescale in main loop.
// ===========================================================================
#define TILE_SMEM 20480
#define ATTN_SMEM (4 * TILE_SMEM)   // 81920

__global__ void __launch_bounds__(256, 2) attn_kernel(
    const float* __restrict__ x,
    const float* __restrict__ bo,
    float* __restrict__ out)
{
    extern __shared__ __align__(16) char dsm[];

    const int tid = threadIdx.x;
    const int w = tid >> 5, lane = tid & 31;
    const int gq = lane >> 2, t = lane & 3;
    const int b = blockIdx.y, q0 = blockIdx.x * 128;
    const size_t bbase = (size_t)b * HW;
    const int qr = q0 + w * 16;
    const float L2E = 1.4426950408889634f;
    const uint32_t sbase = smem_u32(dsm);
    const uint32_t ONES = 0x3C003C00u;

    uint32_t Ahi[2][4];
    {
        const uint32_t* gh = &g_g16hi[(bbase + qr + gq) * 16];
        uint4 u;
        u = *(const uint4*)&gh[4 * t];
        Ahi[0][0] = u.x; Ahi[0][2] = u.y; Ahi[1][0] = u.z; Ahi[1][2] = u.w;
        u = *(const uint4*)&gh[8 * 16 + 4 * t];
        Ahi[0][1] = u.x; Ahi[0][3] = u.y; Ahi[1][1] = u.z; Ahi[1][3] = u.w;
    }

    auto stage = [&](int k0, int buf) {
        const uint32_t base = sbase + buf * TILE_SMEM;
        {
            int n = tid >> 2, tt = tid & 3;
            const uint32_t* gp = &g_f16hi[(bbase + k0 + n) * 16 + tt * 4];
            uint32_t dst = base + (((n >> 3) * 128) + (n & 7) * 16 + tt * 4) * 4;
            cpa16(dst, gp);
        }
        #pragma unroll
        for (int i = 0; i < 4; i++) {
            int task = tid + 256 * i;
            int d = task >> 3, cc = (task >> 2) & 1, tt = task & 3;
            const uint32_t* gp =
                (const uint32_t*)(g_ht_h + ((size_t)b * DV + d) * HW) +
                (k0 >> 1) + cc * 16 + tt * 4;
            uint32_t dst = base + 4096 +
                (((d >> 3) * 256) + cc * 128 + ((d & 7) * 4 + tt) * 4) * 4;
            cpa16(dst, gp);
        }
        CP_COMMIT();
    };

    float O[16][4];
    #pragma unroll
    for (int i = 0; i < 16; i++)
        #pragma unroll
        for (int j = 0; j < 4; j++) O[i][j] = 0.0f;
    float Lc[4] = {0.0f, 0.0f, 0.0f, 0.0f};
    float m0 = -1e30f, m1 = -1e30f;

    stage(0, 0);
    stage(64, 1);
    stage(128, 2);

    for (int kt = 0; kt < 64; ++kt) {
        if (kt < 62) {
            asm volatile("cp.async.wait_group 2;" ::: "memory");
        } else if (kt == 62) {
            asm volatile("cp.async.wait_group 1;" ::: "memory");
        } else {
            asm volatile("cp.async.wait_group 0;" ::: "memory");
        }
        __syncthreads();
        if (kt + 3 < 64) stage((kt + 3) * 64, (kt + 3) & 3);

        const int buf = kt & 3;
        const uint32_t* fhi = (const uint32_t*)(dsm + buf * TILE_SMEM);
        const uint32_t* ht  = fhi + 1024;

        float S[8][4];
        float mt0 = -1e30f, mt1 = -1e30f;
        #pragma unroll
        for (int nb = 0; nb < 8; nb++) {
            float* c = S[nb];
            c[0] = c[1] = c[2] = c[3] = 0.0f;
            uint4 B4 = *(const uint4*)&fhi[nb * 128 + lane * 4];
            mma16816(c, Ahi[0], B4.x, B4.y);
            mma16816(c, Ahi[1], B4.z, B4.w);
            mt0 = fmaxf(mt0, fmaxf(c[0], c[1]));
            mt1 = fmaxf(mt1, fmaxf(c[2], c[3]));
        }
        mt0 = fmaxf(mt0, __shfl_xor_sync(0xffffffffu, mt0, 1));
        mt0 = fmaxf(mt0, __shfl_xor_sync(0xffffffffu, mt0, 2));
        mt1 = fmaxf(mt1, __shfl_xor_sync(0xffffffffu, mt1, 1));
        mt1 = fmaxf(mt1, __shfl_xor_sync(0xffffffffu, mt1, 2));
        const bool newmax = (mt0 > m0) | (mt1 > m1);
        float mn0 = fmaxf(m0, mt0), mn1 = fmaxf(m1, mt1);
        float corr0 = __expf(m0 - mn0), corr1 = __expf(m1 - mn1);
        m0 = mn0; m1 = mn1;
        const float nm0 = -mn0 * L2E, nm1 = -mn1 * L2E;

        uint32_t Pa[4][4];
        #pragma unroll
        for (int nb = 0; nb < 8; nb++) {
            float t0 = fmaf(S[nb][0], L2E, nm0);
            float t1 = fmaf(S[nb][1], L2E, nm0);
            float t2 = fmaf(S[nb][2], L2E, nm1);
            float t3 = fmaf(S[nb][3], L2E, nm1);
            int j = nb >> 1, hi = (nb & 1) << 1;
            Pa[j][hi + 0] = ex2_f16x2(cvt_f16x2(t0, t1));
            Pa[j][hi + 1] = ex2_f16x2(cvt_f16x2(t2, t3));
        }

        // warp-uniform rescale: rows with unchanged max multiply by exact 1.0
        if (__ballot_sync(0xffffffffu, newmax)) {
            #pragma unroll
            for (int nb = 0; nb < 16; nb++) {
                O[nb][0] *= corr0; O[nb][1] *= corr0;
                O[nb][2] *= corr1; O[nb][3] *= corr1;
            }
            Lc[0] *= corr0; Lc[1] *= corr0;
            Lc[2] *= corr1; Lc[3] *= corr1;
        }
        #pragma unroll
        for (int j = 0; j < 4; j++) mma16816(Lc, Pa[j], ONES, ONES);

        #pragma unroll
        for (int nb = 0; nb < 16; nb++) {
            uint4 H0 = *(const uint4*)&ht[nb * 256 + lane * 4];
            uint4 H1 = *(const uint4*)&ht[nb * 256 + 128 + lane * 4];
            mma16816(O[nb], Pa[0], H0.x, H0.y);
            mma16816(O[nb], Pa[1], H0.z, H0.w);
            mma16816(O[nb], Pa[2], H1.x, H1.y);
            mma16816(O[nb], Pa[3], H1.z, H1.w);
        }
    }

    // ---- fused output GEMM: out = x + (O/l) @ Wo + bo ----
    float rl0 = 1.0f / Lc[0], rl1 = 1.0f / Lc[2];

    uint32_t Af[8][4];
    #pragma unroll
    for (int kb = 0; kb < 8; kb++) {
        Af[kb][0] = cvt_f16x2(O[2 * kb][0] * rl0,     O[2 * kb][1] * rl0);
        Af[kb][1] = cvt_f16x2(O[2 * kb][2] * rl1,     O[2 * kb][3] * rl1);
        Af[kb][2] = cvt_f16x2(O[2 * kb + 1][0] * rl0, O[2 * kb + 1][1] * rl0);
        Af[kb][3] = cvt_f16x2(O[2 * kb + 1][2] * rl1, O[2 * kb + 1][3] * rl1);
    }

    // stage ALL of Wo (64KB) once, identity copy
    __syncthreads();   // main-loop smem consumers done
    #pragma unroll
    for (int i = 0; i < 16; i++) {
        int tsk = tid + 256 * i;
        cpa16(sbase + tsk * 16, &g_wo_hi[tsk * 4]);
    }
    CP_COMMIT();
    asm volatile("cp.async.wait_group 0;" ::: "memory");
    __syncthreads();

    const uint32_t* sW = (const uint32_t*)dsm;
    const size_t row0 = bbase + qr + gq;
    #pragma unroll 1
    for (int bn = 0; bn < 4; ++bn) {
        const uint32_t* sWb = sW + bn * 4096;
        #pragma unroll
        for (int nb = 0; nb < 8; nb++) {
            float c[4] = {0.f, 0.f, 0.f, 0.f};
            #pragma unroll
            for (int kb = 0; kb < 8; kb++) {
                uint2 bb = *(const uint2*)&sWb[((nb * 8 + kb) * 32 + lane) * 2];
                mma16816(c, Af[kb], bb.x, bb.y);
            }
            int gn0 = bn * 64 + nb * 8 + 2 * t;
            float2 bv = *(const float2*)&bo[gn0];
            float2 x0 = *(const float2*)&x[row0 * CH + gn0];
            float2 x1 = *(const float2*)&x[(row0 + 8) * CH + gn0];
            *(float2*)&out[row0 * CH + gn0] =
                make_float2(x0.x + c[0] + bv.x, x0.y + c[1] + bv.y);
            *(float2*)&out[(row0 + 8) * CH + gn0] =
                make_float2(x1.x + c[2] + bv.x, x1.y + c[3] + bv.y);
        }
    }
}

// ===========================================================================
extern "C" void kernel_launch(void* const* d_in, const int* in_sizes, int n_in,
                              void* d_out, int out_size)
{
    const float* x  = (const float*)d_in[0];
    const float* Wf = (const float*)d_in[1];
    const float* bf = (const float*)d_in[2];
    const float* Wg = (const float*)d_in[3];
    const float* bg = (const float*)d_in[4];
    const float* Wh = (const float*)d_in[5];
    const float* bh = (const float*)d_in[6];
    const float* Wo = (const float*)d_in[7];
    const float* bo = (const float*)d_in[8];
    float* out = (float*)d_out;

    prep_w<<<80, 256>>>(Wf, Wg, Wh, Wo);

    cudaFuncSetAttribute(proj_mma, cudaFuncAttributeMaxDynamicSharedMemorySize,
                         PROJ_SMEM);
    proj_mma<<<dim3(MTOT / 128, 3), 256, PROJ_SMEM>>>(x, bf, bg, bh);

    cudaFuncSetAttribute(attn_kernel, cudaFuncAttributeMaxDynamicSharedMemorySize,
                         ATTN_SMEM);
    attn_kernel<<<dim3(HW / 128, BATCH), 256, ATTN_SMEM>>>(x, bo, out);
}

// round 17
// speedup vs baseline: 49.8955x; 1.0105x over previous
#include <cuda_runtime.h>
#include <cuda_fp16.h>
#include <cstdint>

// ---------------------------------------------------------------------------
// SelfAttention_2826088481408 — GB300 sm_103a (base sm_103 PTX target)
// B=16, hw=4096, C=256, d=32, dv=128
// R17: attn main loop processes 2 key tiles per iteration with ONE barrier
//      and ONE wait_group (was per-tile); Lc ones-mma moved after PV.
//      Numerically identical to R16.
// ---------------------------------------------------------------------------

#define BATCH 16
#define HW    4096
#define CH    256
#define DK    32
#define DV    128
#define MTOT  (BATCH * HW)

__device__ __align__(16) uint32_t g_f16hi[(size_t)MTOT * 16];
__device__ __align__(16) uint32_t g_g16hi[(size_t)MTOT * 16];
__device__ __align__(16) __half g_ht_h[(size_t)BATCH * DV * HW];

__device__ __align__(16) uint32_t g_wp_hi[3 * 2 * 4096];
__device__ __align__(16) uint32_t g_wp_lo[3 * 2 * 4096];
__device__ __align__(16) uint32_t g_wo_hi[4 * 4096];

// ---- mma.sync m16n8k16 f16 -------------------------------------------------
__device__ __forceinline__ void mma16816(float* c, const uint32_t* a,
                                         uint32_t b0, uint32_t b1) {
    asm volatile(
        "mma.sync.aligned.m16n8k16.row.col.f32.f16.f16.f32 "
        "{%0,%1,%2,%3}, {%4,%5,%6,%7}, {%8,%9}, {%0,%1,%2,%3};"
        : "+f"(c[0]), "+f"(c[1]), "+f"(c[2]), "+f"(c[3])
        : "r"(a[0]), "r"(a[1]), "r"(a[2]), "r"(a[3]), "r"(b0), "r"(b1));
}

__device__ __forceinline__ void hilo2(float2 v, uint32_t& hi, uint32_t& lo) {
    __half hx = __float2half_rn(v.x), hy = __float2half_rn(v.y);
    float rx = v.x - __half2float(hx);
    float ry = v.y - __half2float(hy);
    __half2 h = __halves2half2(hx, hy);
    __half2 l = __floats2half2_rn(rx, ry);
    hi = *(uint32_t*)&h;
    lo = *(uint32_t*)&l;
}

__device__ __forceinline__ uint32_t cvt_f16x2(float x, float y) {
    uint32_t r;
    asm("cvt.rn.f16x2.f32 %0, %1, %2;" : "=r"(r) : "f"(y), "f"(x));
    return r;
}
__device__ __forceinline__ uint32_t ex2_f16x2(uint32_t a) {
    uint32_t r;
    asm("ex2.approx.f16x2 %0, %1;" : "=r"(r) : "r"(a));
    return r;
}

__device__ __forceinline__ uint32_t smem_u32(const void* p) {
    uint32_t a;
    asm("{ .reg .u64 t; cvta.to.shared.u64 t, %1; cvt.u32.u64 %0, t; }"
        : "=r"(a) : "l"(p));
    return a;
}
__device__ __forceinline__ void cpa16(uint32_t s, const void* g) {
    asm volatile(
        "{ .reg .u64 gp; cvta.to.global.u64 gp, %1;"
        "  cp.async.cg.shared.global [%0], [gp], 16; }"
        :: "r"(s), "l"(g) : "memory");
}
#define CP_COMMIT() asm volatile("cp.async.commit_group;" ::: "memory")

__device__ __forceinline__ int fpos(int c) {
    int j = c >> 1;
    return (j & 3) * 4 + (j >> 3) * 2 + ((j >> 2) & 1);
}
__device__ __forceinline__ int htperm(int pix) {
    int p = (pix & 63) >> 1;
    int tt = p & 3, jj = p >> 3, half = (p >> 2) & 1;
    int upos = (jj >> 1) * 16 + tt * 4 + (jj & 1) * 2 + half;
    return (pix >> 6) * 64 + upos * 2 + (pix & 1);
}

__device__ __forceinline__ float wsel(
    const float* __restrict__ Wf, const float* __restrict__ Wg,
    const float* __restrict__ Wh, int k, int gn)
{
    if (gn < 32)  return Wf[k * 32 + gn];
    if (gn < 64)  return Wg[k * 32 + gn - 32];
    return Wh[k * 128 + gn - 64];
}
__device__ __forceinline__ float bsel(
    const float* __restrict__ bf, const float* __restrict__ bg,
    const float* __restrict__ bh, int gn)
{
    if (gn < 32)  return bf[gn];
    if (gn < 64)  return bg[gn - 32];
    return bh[gn - 64];
}

// ===========================================================================
// Kernel 0: prep_w — weights -> fragment-major fp16 streams. 80*256 threads.
// ===========================================================================
__global__ __launch_bounds__(256) void prep_w(
    const float* __restrict__ Wf, const float* __restrict__ Wg,
    const float* __restrict__ Wh, const float* __restrict__ Wo)
{
    int idx = blockIdx.x * 256 + threadIdx.x;
    if (idx < 12288) {
        int ln = idx & 31, kb = (idx >> 5) & 7, nb = (idx >> 8) & 7;
        int ph = (idx >> 11) & 1, y = idx >> 12;
        int gn = y * 64 + nb * 8 + (ln >> 2);
        int k = (ph * 8 + kb) * 16 + 2 * (ln & 3);
        float w0 = wsel(Wf, Wg, Wh, k,     gn);
        float w1 = wsel(Wf, Wg, Wh, k + 1, gn);
        float w2 = wsel(Wf, Wg, Wh, k + 8, gn);
        float w3 = wsel(Wf, Wg, Wh, k + 9, gn);
        uint32_t h0, l0, h1, l1;
        hilo2(make_float2(w0, w1), h0, l0);
        hilo2(make_float2(w2, w3), h1, l1);
        g_wp_hi[idx * 2] = h0; g_wp_hi[idx * 2 + 1] = h1;
        g_wp_lo[idx * 2] = l0; g_wp_lo[idx * 2 + 1] = l1;
    } else {
        int i2 = idx - 12288;
        int ln = i2 & 31, kb = (i2 >> 5) & 7, nb = (i2 >> 8) & 7, bn4 = i2 >> 11;
        int gn = bn4 * 64 + nb * 8 + (ln >> 2);
        int k = kb * 16 + 2 * (ln & 3);
        float w0 = Wo[(size_t)(k)     * CH + gn];
        float w1 = Wo[(size_t)(k + 1) * CH + gn];
        float w2 = Wo[(size_t)(k + 8) * CH + gn];
        float w3 = Wo[(size_t)(k + 9) * CH + gn];
        g_wo_hi[i2 * 2]     = cvt_f16x2(w0, w1);
        g_wo_hi[i2 * 2 + 1] = cvt_f16x2(w2, w3);
    }
}

// ===========================================================================
// Kernel 1: proj GEMM (unchanged from R16).
// ===========================================================================
#define PROJ_SMEM 65536

__global__ void __launch_bounds__(256, 3) proj_mma(
    const float* __restrict__ x,
    const float* __restrict__ bf, const float* __restrict__ bg,
    const float* __restrict__ bh)
{
    extern __shared__ __align__(16) uint32_t psm[];

    const int tid = threadIdx.x;
    const int w = tid >> 5, lane = tid & 31;
    const int gq = lane >> 2, t = lane & 3;
    const int bm = blockIdx.x * 128;
    const int bn = blockIdx.y * 64;

    const int m0 = bm + w * 16 + gq;
    const float* xr0 = &x[(size_t)m0 * CH];
    const float* xr1 = xr0 + 8 * CH;
    const uint32_t psmA = smem_u32(psm);

    {
        const uint32_t* srcHi = &g_wp_hi[blockIdx.y * 2 * 4096];
        const uint32_t* srcLo = &g_wp_lo[blockIdx.y * 2 * 4096];
        #pragma unroll
        for (int i = 0; i < 8; i++) {
            int tsk = tid + 256 * i;
            int ph = tsk >> 10, r = tsk & 1023;
            cpa16(psmA + (ph * 8192 + r * 4) * 4, srcHi + tsk * 4);
            cpa16(psmA + (ph * 8192 + 4096 + r * 4) * 4, srcLo + tsk * 4);
        }
        CP_COMMIT();
        asm volatile("cp.async.wait_group 0;" ::: "memory");
    }
    __syncthreads();

    float c[8][4];
    #pragma unroll
    for (int nb = 0; nb < 8; nb++)
        #pragma unroll
        for (int j = 0; j < 4; j++) c[nb][j] = 0.0f;

    #pragma unroll
    for (int ph = 0; ph < 2; ph++) {
        const uint32_t* sBhi = &psm[ph * 8192];
        const uint32_t* sBlo = &psm[ph * 8192 + 4096];

        float2 n0_ = *(const float2*)&xr0[(ph * 8) * 16 + 2 * t];
        float2 n1_ = *(const float2*)&xr1[(ph * 8) * 16 + 2 * t];
        float2 n2_ = *(const float2*)&xr0[(ph * 8) * 16 + 2 * t + 8];
        float2 n3_ = *(const float2*)&xr1[(ph * 8) * 16 + 2 * t + 8];
        #pragma unroll
        for (int kb = 0; kb < 8; kb++) {
            float2 c0 = n0_, c1 = n1_, c2 = n2_, c3 = n3_;
            if (kb < 7) {
                const int kn = (ph * 8 + kb + 1) * 16;
                n0_ = *(const float2*)&xr0[kn + 2 * t];
                n1_ = *(const float2*)&xr1[kn + 2 * t];
                n2_ = *(const float2*)&xr0[kn + 2 * t + 8];
                n3_ = *(const float2*)&xr1[kn + 2 * t + 8];
            }
            uint32_t Ahi[4], Alo[4];
            hilo2(c0, Ahi[0], Alo[0]);
            hilo2(c1, Ahi[1], Alo[1]);
            hilo2(c2, Ahi[2], Alo[2]);
            hilo2(c3, Ahi[3], Alo[3]);
            #pragma unroll
            for (int nb = 0; nb < 8; nb++) {
                uint2 bh2 = *(const uint2*)&sBhi[((nb * 8 + kb) * 32 + lane) * 2];
                uint2 bl2 = *(const uint2*)&sBlo[((nb * 8 + kb) * 32 + lane) * 2];
                mma16816(c[nb], Ahi, bh2.x, bh2.y);
                mma16816(c[nb], Ahi, bl2.x, bl2.y);
            }
        }
    }

    #pragma unroll
    for (int nb = 0; nb < 8; nb++) {
        int gn0 = bn + nb * 8 + 2 * t;
        float b0 = bsel(bf, bg, bh, gn0);
        float b1 = bsel(bf, bg, bh, gn0 + 1);
        float v00 = c[nb][0] + b0, v01 = c[nb][1] + b1;
        float v10 = c[nb][2] + b0, v11 = c[nb][3] + b1;
        if (gn0 < 32) {
            int p = fpos(gn0);
            uint32_t h, l;
            hilo2(make_float2(v00, v01), h, l);
            g_f16hi[(size_t)m0 * 16 + p] = h;
            hilo2(make_float2(v10, v11), h, l);
            g_f16hi[(size_t)(m0 + 8) * 16 + p] = h;
        } else if (gn0 < 64) {
            int p = fpos(gn0 - 32);
            uint32_t h, l;
            hilo2(make_float2(v00, v01), h, l);
            g_g16hi[(size_t)m0 * 16 + p] = h;
            hilo2(make_float2(v10, v11), h, l);
            g_g16hi[(size_t)(m0 + 8) * 16 + p] = h;
        } else {
            int dv0 = gn0 - 64;
            int bb0 = m0 >> 12, pix0 = m0 & 4095;
            int m1r = m0 + 8, bb1 = m1r >> 12, pix1 = m1r & 4095;
            int pi0 = htperm(pix0), pi1 = htperm(pix1);
            size_t r00 = ((size_t)bb0 * DV + dv0) * HW;
            size_t r01 = ((size_t)bb0 * DV + dv0 + 1) * HW;
            size_t r10 = ((size_t)bb1 * DV + dv0) * HW;
            size_t r11 = ((size_t)bb1 * DV + dv0 + 1) * HW;
            g_ht_h[r00 + pi0] = __float2half_rn(v00);
            g_ht_h[r01 + pi0] = __float2half_rn(v01);
            g_ht_h[r10 + pi1] = __float2half_rn(v10);
            g_ht_h[r11 + pi1] = __float2half_rn(v11);
        }
    }
}

// ===========================================================================
// Kernel 2: flash attention + fused output GEMM.
// Main loop: 2 key tiles per iteration, ONE barrier + ONE wait per iter.
// ===========================================================================
#define TILE_SMEM 20480
#define ATTN_SMEM (4 * TILE_SMEM)   // 81920

__global__ void __launch_bounds__(256, 2) attn_kernel(
    const float* __restrict__ x,
    const float* __restrict__ bo,
    float* __restrict__ out)
{
    extern __shared__ __align__(16) char dsm[];

    const int tid = threadIdx.x;
    const int w = tid >> 5, lane = tid & 31;
    const int gq = lane >> 2, t = lane & 3;
    const int b = blockIdx.y, q0 = blockIdx.x * 128;
    const size_t bbase = (size_t)b * HW;
    const int qr = q0 + w * 16;
    const float L2E = 1.4426950408889634f;
    const uint32_t sbase = smem_u32(dsm);
    const uint32_t ONES = 0x3C003C00u;

    uint32_t Ahi[2][4];
    {
        const uint32_t* gh = &g_g16hi[(bbase + qr + gq) * 16];
        uint4 u;
        u = *(const uint4*)&gh[4 * t];
        Ahi[0][0] = u.x; Ahi[0][2] = u.y; Ahi[1][0] = u.z; Ahi[1][2] = u.w;
        u = *(const uint4*)&gh[8 * 16 + 4 * t];
        Ahi[0][1] = u.x; Ahi[0][3] = u.y; Ahi[1][1] = u.z; Ahi[1][3] = u.w;
    }

    auto stage = [&](int k0, int buf) {
        const uint32_t base = sbase + buf * TILE_SMEM;
        {
            int n = tid >> 2, tt = tid & 3;
            const uint32_t* gp = &g_f16hi[(bbase + k0 + n) * 16 + tt * 4];
            uint32_t dst = base + (((n >> 3) * 128) + (n & 7) * 16 + tt * 4) * 4;
            cpa16(dst, gp);
        }
        #pragma unroll
        for (int i = 0; i < 4; i++) {
            int task = tid + 256 * i;
            int d = task >> 3, cc = (task >> 2) & 1, tt = task & 3;
            const uint32_t* gp =
                (const uint32_t*)(g_ht_h + ((size_t)b * DV + d) * HW) +
                (k0 >> 1) + cc * 16 + tt * 4;
            uint32_t dst = base + 4096 +
                (((d >> 3) * 256) + cc * 128 + ((d & 7) * 4 + tt) * 4) * 4;
            cpa16(dst, gp);
        }
        CP_COMMIT();
    };

    float O[16][4];
    #pragma unroll
    for (int i = 0; i < 16; i++)
        #pragma unroll
        for (int j = 0; j < 4; j++) O[i][j] = 0.0f;
    float Lc[4] = {0.0f, 0.0f, 0.0f, 0.0f};
    float m0 = -1e30f, m1 = -1e30f;

    // per-tile compute (S -> softmax -> rescale -> PV -> Lc)
    auto tile = [&](int buf) {
        const uint32_t* fhi = (const uint32_t*)(dsm + buf * TILE_SMEM);
        const uint32_t* ht  = fhi + 1024;

        float S[8][4];
        float mt0 = -1e30f, mt1 = -1e30f;
        #pragma unroll
        for (int nb = 0; nb < 8; nb++) {
            float* c = S[nb];
            c[0] = c[1] = c[2] = c[3] = 0.0f;
            uint4 B4 = *(const uint4*)&fhi[nb * 128 + lane * 4];
            mma16816(c, Ahi[0], B4.x, B4.y);
            mma16816(c, Ahi[1], B4.z, B4.w);
            mt0 = fmaxf(mt0, fmaxf(c[0], c[1]));
            mt1 = fmaxf(mt1, fmaxf(c[2], c[3]));
        }
        mt0 = fmaxf(mt0, __shfl_xor_sync(0xffffffffu, mt0, 1));
        mt0 = fmaxf(mt0, __shfl_xor_sync(0xffffffffu, mt0, 2));
        mt1 = fmaxf(mt1, __shfl_xor_sync(0xffffffffu, mt1, 1));
        mt1 = fmaxf(mt1, __shfl_xor_sync(0xffffffffu, mt1, 2));
        const bool newmax = (mt0 > m0) | (mt1 > m1);
        float mn0 = fmaxf(m0, mt0), mn1 = fmaxf(m1, mt1);
        float corr0 = __expf(m0 - mn0), corr1 = __expf(m1 - mn1);
        m0 = mn0; m1 = mn1;
        const float nm0 = -mn0 * L2E, nm1 = -mn1 * L2E;

        uint32_t Pa[4][4];
        #pragma unroll
        for (int nb = 0; nb < 8; nb++) {
            float t0 = fmaf(S[nb][0], L2E, nm0);
            float t1 = fmaf(S[nb][1], L2E, nm0);
            float t2 = fmaf(S[nb][2], L2E, nm1);
            float t3 = fmaf(S[nb][3], L2E, nm1);
            int j = nb >> 1, hi = (nb & 1) << 1;
            Pa[j][hi + 0] = ex2_f16x2(cvt_f16x2(t0, t1));
            Pa[j][hi + 1] = ex2_f16x2(cvt_f16x2(t2, t3));
        }

        if (__ballot_sync(0xffffffffu, newmax)) {
            #pragma unroll
            for (int nb = 0; nb < 16; nb++) {
                O[nb][0] *= corr0; O[nb][1] *= corr0;
                O[nb][2] *= corr1; O[nb][3] *= corr1;
            }
            Lc[0] *= corr0; Lc[1] *= corr0;
            Lc[2] *= corr1; Lc[3] *= corr1;
        }

        #pragma unroll
        for (int nb = 0; nb < 16; nb++) {
            uint4 H0 = *(const uint4*)&ht[nb * 256 + lane * 4];
            uint4 H1 = *(const uint4*)&ht[nb * 256 + 128 + lane * 4];
            mma16816(O[nb], Pa[0], H0.x, H0.y);
            mma16816(O[nb], Pa[1], H0.z, H0.w);
            mma16816(O[nb], Pa[2], H1.x, H1.y);
            mma16816(O[nb], Pa[3], H1.z, H1.w);
        }
        #pragma unroll
        for (int j = 0; j < 4; j++) mma16816(Lc, Pa[j], ONES, ONES);
    };

    stage(0, 0);
    stage(64, 1);

    #pragma unroll 1
    for (int it = 0; it < 32; ++it) {
        const int a = 2 * it;
        asm volatile("cp.async.wait_group 0;" ::: "memory");
        __syncthreads();   // tiles a,a+1 visible; buffers (a+2)&3,(a+3)&3 free
        if (it < 31) {
            stage((a + 2) * 64, (a + 2) & 3);
            stage((a + 3) * 64, (a + 3) & 3);
        }
        tile(a & 3);
        tile((a + 1) & 3);
    }

    // ---- fused output GEMM: out = x + (O/l) @ Wo + bo ----
    float rl0 = 1.0f / Lc[0], rl1 = 1.0f / Lc[2];

    uint32_t Af[8][4];
    #pragma unroll
    for (int kb = 0; kb < 8; kb++) {
        Af[kb][0] = cvt_f16x2(O[2 * kb][0] * rl0,     O[2 * kb][1] * rl0);
        Af[kb][1] = cvt_f16x2(O[2 * kb][2] * rl1,     O[2 * kb][3] * rl1);
        Af[kb][2] = cvt_f16x2(O[2 * kb + 1][0] * rl0, O[2 * kb + 1][1] * rl0);
        Af[kb][3] = cvt_f16x2(O[2 * kb + 1][2] * rl1, O[2 * kb + 1][3] * rl1);
    }

    __syncthreads();   // main-loop smem consumers done
    #pragma unroll
    for (int i = 0; i < 16; i++) {
        int tsk = tid + 256 * i;
        cpa16(sbase + tsk * 16, &g_wo_hi[tsk * 4]);
    }
    CP_COMMIT();
    asm volatile("cp.async.wait_group 0;" ::: "memory");
    __syncthreads();

    const uint32_t* sW = (const uint32_t*)dsm;
    const size_t row0 = bbase + qr + gq;
    #pragma unroll 1
    for (int bn = 0; bn < 4; ++bn) {
        const uint32_t* sWb = sW + bn * 4096;
        #pragma unroll
        for (int nb = 0; nb < 8; nb++) {
            float c[4] = {0.f, 0.f, 0.f, 0.f};
            #pragma unroll
            for (int kb = 0; kb < 8; kb++) {
                uint2 bb = *(const uint2*)&sWb[((nb * 8 + kb) * 32 + lane) * 2];
                mma16816(c, Af[kb], bb.x, bb.y);
            }
            int gn0 = bn * 64 + nb * 8 + 2 * t;
            float2 bv = *(const float2*)&bo[gn0];
            float2 x0 = *(const float2*)&x[row0 * CH + gn0];
            float2 x1 = *(const float2*)&x[(row0 + 8) * CH + gn0];
            *(float2*)&out[row0 * CH + gn0] =
                make_float2(x0.x + c[0] + bv.x, x0.y + c[1] + bv.y);
            *(float2*)&out[(row0 + 8) * CH + gn0] =
                make_float2(x1.x + c[2] + bv.x, x1.y + c[3] + bv.y);
        }
    }
}

// ===========================================================================
extern "C" void kernel_launch(void* const* d_in, const int* in_sizes, int n_in,
                              void* d_out, int out_size)
{
    const float* x  = (const float*)d_in[0];
    const float* Wf = (const float*)d_in[1];
    const float* bf = (const float*)d_in[2];
    const float* Wg = (const float*)d_in[3];
    const float* bg = (const float*)d_in[4];
    const float* Wh = (const float*)d_in[5];
    const float* bh = (const float*)d_in[6];
    const float* Wo = (const float*)d_in[7];
    const float* bo = (const float*)d_in[8];
    float* out = (float*)d_out;

    prep_w<<<80, 256>>>(Wf, Wg, Wh, Wo);

    cudaFuncSetAttribute(proj_mma, cudaFuncAttributeMaxDynamicSharedMemorySize,
                         PROJ_SMEM);
    proj_mma<<<dim3(MTOT / 128, 3), 256, PROJ_SMEM>>>(x, bf, bg, bh);

    cudaFuncSetAttribute(attn_kernel, cudaFuncAttributeMaxDynamicSharedMemorySize,
                         ATTN_SMEM);
    attn_kernel<<<dim3(HW / 128, BATCH), 256, ATTN_SMEM>>>(x, bo, out);
}